// round 1
// baseline (speedup 1.0000x reference)
#include <cuda_runtime.h>
#include <math.h>

#define BB 4
#define SS 1024
#define DD 1024
#define HH 16
#define FF 4096
#define DHD 64
#define NG (BB*HH)          // 64 attention groups (flat reshape)
#define MR (BB*SS)          // 4096 rows

// ---------------- scratch (static device globals; no allocation) -------------
__device__ float g_q[MR*DD];
__device__ float g_k[MR*DD];
__device__ float g_v[MR*DD];
__device__ float g_att[MR*DD];
__device__ float g_tmp[MR*DD];     // attO, then ff2 (reused)
__device__ float g_h[MR*DD];
__device__ float g_ff1[(size_t)MR*FF];
__device__ float g_btab[(2*SS-1)*HH];

// ---------------- relative-position bias table ------------------------------
// bias_tab[r][h] with r = (q - k) + (S-1);  bucket depends only on q-k.
__global__ void bias_table_kernel(const float* __restrict__ rel_bias,
                                  float* __restrict__ tab)
{
    int r = blockIdx.x * blockDim.x + threadIdx.x;
    if (r >= 2*SS - 1) return;
    int rel = r - (SS - 1);        // q - k
    int n = -rel;                  // torch source: n = -relative_position
    int ret = (n < 0) ? 16 : 0;
    int na = n < 0 ? -n : n;
    int bucket;
    if (na < 8) {
        bucket = ret + na;
    } else {
        double v = log((double)na / 8.0) / log(16.0) * 8.0;
        int vi = 8 + (int)v;       // truncation toward zero (v >= 0 here)
        if (vi > 15) vi = 15;
        bucket = ret + vi;
    }
    #pragma unroll
    for (int h = 0; h < HH; h++) tab[r*HH + h] = rel_bias[bucket*HH + h];
}

// ---------------- SGEMM: C[M,N] = A[M,K] @ B[K,N] + bias (opt relu) ---------
// 128x128 tile, BK=8, 256 threads, 8x8 per thread.
__global__ __launch_bounds__(256, 2)
void sgemm_kernel(const float* __restrict__ A, const float* __restrict__ Bm,
                  const float* __restrict__ bias, float* __restrict__ C,
                  int M, int N, int K, int relu)
{
    __shared__ float As[8][128];
    __shared__ float Bs[8][128];
    int tid = threadIdx.x;
    int bm = blockIdx.y, bn = blockIdx.x;
    int tr = tid >> 4, tc = tid & 15;

    int arow = tid >> 1, acol = (tid & 1) * 4;     // A tile 128x8
    int brow = tid >> 5, bcol = (tid & 31) * 4;    // B tile 8x128

    const float* Ap = A + (size_t)(bm*128 + arow)*K + acol;
    const float* Bp = Bm + (size_t)brow*N + bn*128 + bcol;

    float acc[8][8];
    #pragma unroll
    for (int i = 0; i < 8; i++)
        #pragma unroll
        for (int j = 0; j < 8; j++) acc[i][j] = 0.f;

    for (int k0 = 0; k0 < K; k0 += 8) {
        float4 av = *(const float4*)(Ap + k0);
        As[acol+0][arow] = av.x; As[acol+1][arow] = av.y;
        As[acol+2][arow] = av.z; As[acol+3][arow] = av.w;
        float4 bv = *(const float4*)(Bp + (size_t)k0 * N);
        *(float4*)&Bs[brow][bcol] = bv;
        __syncthreads();
        #pragma unroll
        for (int kk = 0; kk < 8; kk++) {
            float4 a0 = *(const float4*)&As[kk][tr*8];
            float4 a1 = *(const float4*)&As[kk][tr*8 + 4];
            float4 b0 = *(const float4*)&Bs[kk][tc*8];
            float4 b1 = *(const float4*)&Bs[kk][tc*8 + 4];
            float ra[8] = {a0.x,a0.y,a0.z,a0.w,a1.x,a1.y,a1.z,a1.w};
            float rb[8] = {b0.x,b0.y,b0.z,b0.w,b1.x,b1.y,b1.z,b1.w};
            #pragma unroll
            for (int i = 0; i < 8; i++)
                #pragma unroll
                for (int j = 0; j < 8; j++)
                    acc[i][j] = fmaf(ra[i], rb[j], acc[i][j]);
        }
        __syncthreads();
    }

    int row0 = bm*128 + tr*8, col0 = bn*128 + tc*8;
    #pragma unroll
    for (int i = 0; i < 8; i++) {
        #pragma unroll
        for (int j = 0; j < 8; j++) {
            float v = acc[i][j] + bias[col0 + j];
            if (relu) v = fmaxf(v, 0.f);
            C[(size_t)(row0 + i)*N + col0 + j] = v;
        }
    }
}

// ---------------- fused attention (flash style) -----------------------------
// Operates on q/k/v reinterpreted as [NG][S][DHD] (flat reshape = identity on
// memory). Group g: head = g % H (bias), batch = g / H (padding mask).
// Block: 256 threads = 16x16, each thread owns a 4x4 tile of the 64x64
// (rows x dims) output tile; k-tiles of 64 with online softmax.
#define ATTN_SMEM (4*64*65*4)
__global__ __launch_bounds__(256, 2)
void attn_kernel(const float* __restrict__ Q, const float* __restrict__ Kg,
                 const float* __restrict__ Vg, const int* __restrict__ mask,
                 const float* __restrict__ btab, float* __restrict__ O)
{
    extern __shared__ float sm[];
    float (*Qs)[65] = (float(*)[65])(sm);
    float (*Ks)[65] = (float(*)[65])(sm + 64*65);
    float (*Vs)[65] = (float(*)[65])(sm + 2*64*65);
    float (*Ps)[65] = (float(*)[65])(sm + 3*64*65);

    const int g  = blockIdx.y;
    const int q0 = blockIdx.x * 64;
    const int tid = threadIdx.x;
    const int tr = tid >> 4, tc = tid & 15;
    const int tr4 = tr*4, tc4 = tc*4;
    const int hh = g & (HH-1);
    const int bb = g >> 4;

    const float* Qb = Q  + ((size_t)g*SS + q0)*DHD;
    const float* Kb = Kg + (size_t)g*SS*DHD;
    const float* Vb = Vg + (size_t)g*SS*DHD;

    // load Q tile (64x64)
    for (int it = tid; it < 64*16; it += 256) {
        int r = it >> 4, c = (it & 15) * 4;
        float4 v = *(const float4*)(Qb + (size_t)r*DHD + c);
        Qs[r][c+0] = v.x; Qs[r][c+1] = v.y; Qs[r][c+2] = v.z; Qs[r][c+3] = v.w;
    }

    float m[4], l[4], o[4][4];
    #pragma unroll
    for (int i = 0; i < 4; i++) {
        m[i] = -INFINITY; l[i] = 0.f;
        #pragma unroll
        for (int j = 0; j < 4; j++) o[i][j] = 0.f;
    }

    for (int k0 = 0; k0 < SS; k0 += 64) {
        __syncthreads();   // prior iteration fully consumed K/V/P (and Q load done)
        for (int it = tid; it < 64*16; it += 256) {
            int r = it >> 4, c = (it & 15) * 4;
            float4 kv = *(const float4*)(Kb + (size_t)(k0 + r)*DHD + c);
            Ks[r][c+0] = kv.x; Ks[r][c+1] = kv.y; Ks[r][c+2] = kv.z; Ks[r][c+3] = kv.w;
            float4 vv = *(const float4*)(Vb + (size_t)(k0 + r)*DHD + c);
            Vs[r][c+0] = vv.x; Vs[r][c+1] = vv.y; Vs[r][c+2] = vv.z; Vs[r][c+3] = vv.w;
        }
        __syncthreads();

        // scores: s[i][j] = q(tr4+i) . k(tc4+j) + bias + maskpen
        float s[4][4];
        #pragma unroll
        for (int j = 0; j < 4; j++) {
            int tk = k0 + tc4 + j;
            int mk = mask[bb*SS + tk];
            #pragma unroll
            for (int i = 0; i < 4; i++) {
                int tq = q0 + tr4 + i;
                float bsv = btab[(tq - tk + SS - 1)*HH + hh];
                s[i][j] = mk ? bsv : -1e30f;
            }
        }
        #pragma unroll 8
        for (int e = 0; e < 64; e++) {
            float qa0 = Qs[tr4+0][e], qa1 = Qs[tr4+1][e];
            float qa2 = Qs[tr4+2][e], qa3 = Qs[tr4+3][e];
            float kb0 = Ks[tc4+0][e], kb1 = Ks[tc4+1][e];
            float kb2 = Ks[tc4+2][e], kb3 = Ks[tc4+3][e];
            s[0][0] = fmaf(qa0, kb0, s[0][0]); s[0][1] = fmaf(qa0, kb1, s[0][1]);
            s[0][2] = fmaf(qa0, kb2, s[0][2]); s[0][3] = fmaf(qa0, kb3, s[0][3]);
            s[1][0] = fmaf(qa1, kb0, s[1][0]); s[1][1] = fmaf(qa1, kb1, s[1][1]);
            s[1][2] = fmaf(qa1, kb2, s[1][2]); s[1][3] = fmaf(qa1, kb3, s[1][3]);
            s[2][0] = fmaf(qa2, kb0, s[2][0]); s[2][1] = fmaf(qa2, kb1, s[2][1]);
            s[2][2] = fmaf(qa2, kb2, s[2][2]); s[2][3] = fmaf(qa2, kb3, s[2][3]);
            s[3][0] = fmaf(qa3, kb0, s[3][0]); s[3][1] = fmaf(qa3, kb1, s[3][1]);
            s[3][2] = fmaf(qa3, kb2, s[3][2]); s[3][3] = fmaf(qa3, kb3, s[3][3]);
        }

        // row max across the 16 column-threads (lanes 0-15 / 16-31 in warp)
        float tm[4], mn[4], alpha[4], ps[4];
        #pragma unroll
        for (int i = 0; i < 4; i++) {
            float v = fmaxf(fmaxf(s[i][0], s[i][1]), fmaxf(s[i][2], s[i][3]));
            #pragma unroll
            for (int off = 1; off < 16; off <<= 1)
                v = fmaxf(v, __shfl_xor_sync(0xffffffffu, v, off));
            tm[i] = v;
        }
        #pragma unroll
        for (int i = 0; i < 4; i++) {
            mn[i] = fmaxf(m[i], tm[i]);
            alpha[i] = __expf(m[i] - mn[i]) * 0.f + expf(m[i] - mn[i]); // exact expf
            float acc = 0.f;
            #pragma unroll
            for (int j = 0; j < 4; j++) {
                float p = expf(s[i][j] - mn[i]);
                Ps[tr4+i][tc4+j] = p;
                acc += p;
            }
            ps[i] = acc;
        }
        #pragma unroll
        for (int i = 0; i < 4; i++) {
            float v = ps[i];
            #pragma unroll
            for (int off = 1; off < 16; off <<= 1)
                v += __shfl_xor_sync(0xffffffffu, v, off);
            l[i] = l[i]*alpha[i] + v;
            m[i] = mn[i];
        }
        #pragma unroll
        for (int i = 0; i < 4; i++)
            #pragma unroll
            for (int j = 0; j < 4; j++) o[i][j] *= alpha[i];

        __syncthreads();   // Ps visible

        #pragma unroll 8
        for (int kk = 0; kk < 64; kk++) {
            float p0 = Ps[tr4+0][kk], p1 = Ps[tr4+1][kk];
            float p2 = Ps[tr4+2][kk], p3 = Ps[tr4+3][kk];
            float v0 = Vs[kk][tc4+0], v1 = Vs[kk][tc4+1];
            float v2 = Vs[kk][tc4+2], v3 = Vs[kk][tc4+3];
            o[0][0] = fmaf(p0, v0, o[0][0]); o[0][1] = fmaf(p0, v1, o[0][1]);
            o[0][2] = fmaf(p0, v2, o[0][2]); o[0][3] = fmaf(p0, v3, o[0][3]);
            o[1][0] = fmaf(p1, v0, o[1][0]); o[1][1] = fmaf(p1, v1, o[1][1]);
            o[1][2] = fmaf(p1, v2, o[1][2]); o[1][3] = fmaf(p1, v3, o[1][3]);
            o[2][0] = fmaf(p2, v0, o[2][0]); o[2][1] = fmaf(p2, v1, o[2][1]);
            o[2][2] = fmaf(p2, v2, o[2][2]); o[2][3] = fmaf(p2, v3, o[2][3]);
            o[3][0] = fmaf(p3, v0, o[3][0]); o[3][1] = fmaf(p3, v1, o[3][1]);
            o[3][2] = fmaf(p3, v2, o[3][2]); o[3][3] = fmaf(p3, v3, o[3][3]);
        }
    }

    #pragma unroll
    for (int i = 0; i < 4; i++) {
        float inv = 1.f / l[i];
        float4 ov = make_float4(o[i][0]*inv, o[i][1]*inv, o[i][2]*inv, o[i][3]*inv);
        *(float4*)(O + ((size_t)g*SS + q0 + tr4 + i)*DHD + tc4) = ov;
    }
}

// ---------------- LayerNorm with residual: Out = LN(A + R) ------------------
__global__ __launch_bounds__(256)
void ln_kernel(const float* __restrict__ A, const float* __restrict__ R,
               const float* __restrict__ gamma, const float* __restrict__ beta,
               float* __restrict__ Out)
{
    __shared__ float xs[DD];
    __shared__ float red[8];
    int row = blockIdx.x;
    int tid = threadIdx.x;
    const float* a = A + (size_t)row*DD;
    const float* r = R + (size_t)row*DD;

    float lsum = 0.f;
    for (int i = tid; i < DD; i += 256) {
        float x = a[i] + r[i];
        xs[i] = x;
        lsum += x;
    }
    #pragma unroll
    for (int off = 16; off; off >>= 1) lsum += __shfl_xor_sync(0xffffffffu, lsum, off);
    if ((tid & 31) == 0) red[tid >> 5] = lsum;
    __syncthreads();
    float tot = 0.f;
    #pragma unroll
    for (int w = 0; w < 8; w++) tot += red[w];
    float mu = tot * (1.f / DD);
    __syncthreads();

    float lsq = 0.f;
    for (int i = tid; i < DD; i += 256) {
        float d = xs[i] - mu;
        lsq += d * d;
    }
    #pragma unroll
    for (int off = 16; off; off >>= 1) lsq += __shfl_xor_sync(0xffffffffu, lsq, off);
    if ((tid & 31) == 0) red[tid >> 5] = lsq;
    __syncthreads();
    float vt = 0.f;
    #pragma unroll
    for (int w = 0; w < 8; w++) vt += red[w];
    float var = vt * (1.f / DD);
    float inv = 1.f / sqrtf(var + 1e-5f);

    for (int i = tid; i < DD; i += 256) {
        Out[(size_t)row*DD + i] = gamma[i] * (xs[i] - mu) * inv + beta[i];
    }
}

// ---------------- launch ----------------------------------------------------
extern "C" void kernel_launch(void* const* d_in, const int* in_sizes, int n_in,
                              void* d_out, int out_size)
{
    const float* x    = (const float*)d_in[0];
    const int*   mask = (const int*)  d_in[1];
    const float* Wq = (const float*)d_in[2];  const float* bq = (const float*)d_in[3];
    const float* Wk = (const float*)d_in[4];  const float* bk = (const float*)d_in[5];
    const float* Wv = (const float*)d_in[6];  const float* bv = (const float*)d_in[7];
    const float* Wo = (const float*)d_in[8];  const float* bo = (const float*)d_in[9];
    const float* rel_bias = (const float*)d_in[10];
    const float* ln1g = (const float*)d_in[11]; const float* ln1b = (const float*)d_in[12];
    const float* W1 = (const float*)d_in[13]; const float* b1 = (const float*)d_in[14];
    const float* W2 = (const float*)d_in[15]; const float* b2 = (const float*)d_in[16];
    const float* ln2g = (const float*)d_in[17]; const float* ln2b = (const float*)d_in[18];
    float* out = (float*)d_out;

    float *q, *k, *v, *att, *tmp, *h, *ff1, *btab;
    cudaGetSymbolAddress((void**)&q,    g_q);
    cudaGetSymbolAddress((void**)&k,    g_k);
    cudaGetSymbolAddress((void**)&v,    g_v);
    cudaGetSymbolAddress((void**)&att,  g_att);
    cudaGetSymbolAddress((void**)&tmp,  g_tmp);
    cudaGetSymbolAddress((void**)&h,    g_h);
    cudaGetSymbolAddress((void**)&ff1,  g_ff1);
    cudaGetSymbolAddress((void**)&btab, g_btab);

    cudaFuncSetAttribute(attn_kernel,
                         cudaFuncAttributeMaxDynamicSharedMemorySize, ATTN_SMEM);

    // 1. relative bias table
    bias_table_kernel<<<(2*SS - 1 + 255)/256, 256>>>(rel_bias, btab);

    // 2. Q/K/V projections
    dim3 gproj(DD/128, MR/128);
    sgemm_kernel<<<gproj, 256>>>(x, Wq, bq, q, MR, DD, DD, 0);
    sgemm_kernel<<<gproj, 256>>>(x, Wk, bk, k, MR, DD, DD, 0);
    sgemm_kernel<<<gproj, 256>>>(x, Wv, bv, v, MR, DD, DD, 0);

    // 3. fused attention over the flat-reshaped [64,1024,64] view
    attn_kernel<<<dim3(SS/64, NG), 256, ATTN_SMEM>>>(q, k, v, mask, btab, att);

    // 4. output projection
    sgemm_kernel<<<gproj, 256>>>(att, Wo, bo, tmp, MR, DD, DD, 0);

    // 5. LN1: h = LN(attO + x)
    ln_kernel<<<MR, 256>>>(tmp, x, ln1g, ln1b, h);

    // 6. FFN
    dim3 gff1(FF/128, MR/128);
    sgemm_kernel<<<gff1, 256>>>(h, W1, b1, ff1, MR, FF, DD, 1);
    dim3 gff2(DD/128, MR/128);
    sgemm_kernel<<<gff2, 256>>>(ff1, W2, b2, tmp, MR, DD, FF, 0);

    // 7. LN2: out = LN(ff2 + h)
    ln_kernel<<<MR, 256>>>(tmp, h, ln2g, ln2b, out);
}

// round 3
// speedup vs baseline: 1.9886x; 1.9886x over previous
#include <cuda_runtime.h>
#include <cuda_bf16.h>
#include <math.h>
#include <stdint.h>

#define BB 4
#define SS 1024
#define DD 1024
#define HH 16
#define FF 4096
#define DHD 64
#define NG (BB*HH)
#define MR (BB*SS)

// ---------------- scratch (static device globals; no allocation) -------------
__device__ float g_q[MR*DD];
__device__ float g_k[MR*DD];
__device__ float g_v[MR*DD];
__device__ float g_att[MR*DD];
__device__ float g_tmp[MR*DD];
__device__ float g_h[MR*DD];
__device__ float g_ff1[(size_t)MR*FF];
__device__ float g_btab[(2*SS-1)*HH];

// bf16 hi/lo split buffers (activations)
__device__ __nv_bfloat16 g_xh[MR*DD],  g_xl[MR*DD];
__device__ __nv_bfloat16 g_ath[MR*DD], g_atl[MR*DD];
__device__ __nv_bfloat16 g_hh[MR*DD],  g_hl[MR*DD];
__device__ __nv_bfloat16 g_fh[(size_t)MR*FF], g_fl[(size_t)MR*FF];
// bf16 hi/lo transposed weights [N,K]
__device__ __nv_bfloat16 g_wqh[DD*DD], g_wql[DD*DD];
__device__ __nv_bfloat16 g_wkh[DD*DD], g_wkl[DD*DD];
__device__ __nv_bfloat16 g_wvh[DD*DD], g_wvl[DD*DD];
__device__ __nv_bfloat16 g_woh[DD*DD], g_wol[DD*DD];
__device__ __nv_bfloat16 g_w1h[(size_t)DD*FF], g_w1l[(size_t)DD*FF];
__device__ __nv_bfloat16 g_w2h[(size_t)FF*DD], g_w2l[(size_t)FF*DD];

// ---------------- PTX helpers ------------------------------------------------
#define SWZ(o) ((o) ^ (((o) >> 3) & 0x70))

__device__ __forceinline__ uint32_t s2u(const void* p){
    uint32_t a;
    asm("{ .reg .u64 t; cvta.to.shared.u64 t, %1; cvt.u32.u64 %0, t; }"
        : "=r"(a) : "l"(p));
    return a;
}
__device__ __forceinline__ void cp16(uint32_t d, const void* s){
    asm volatile("cp.async.cg.shared.global [%0], [%1], 16;" :: "r"(d), "l"(s));
}
__device__ __forceinline__ void ldm4(uint32_t* r, uint32_t a){
    asm volatile("ldmatrix.sync.aligned.m8n8.x4.shared.b16 {%0,%1,%2,%3}, [%4];"
        : "=r"(r[0]), "=r"(r[1]), "=r"(r[2]), "=r"(r[3]) : "r"(a));
}
__device__ __forceinline__ void mma16816(float* c, const uint32_t* a,
                                         uint32_t b0, uint32_t b1){
    asm volatile("mma.sync.aligned.m16n8k16.row.col.f32.bf16.bf16.f32 "
        "{%0,%1,%2,%3}, {%4,%5,%6,%7}, {%8,%9}, {%0,%1,%2,%3};"
        : "+f"(c[0]), "+f"(c[1]), "+f"(c[2]), "+f"(c[3])
        : "r"(a[0]), "r"(a[1]), "r"(a[2]), "r"(a[3]), "r"(b0), "r"(b1));
}

// ---------------- relative-position bias table ------------------------------
__global__ void bias_table_kernel(const float* __restrict__ rel_bias,
                                  float* __restrict__ tab)
{
    int r = blockIdx.x * blockDim.x + threadIdx.x;
    if (r >= 2*SS - 1) return;
    int rel = r - (SS - 1);
    int n = -rel;
    int ret = (n < 0) ? 16 : 0;
    int na = n < 0 ? -n : n;
    int bucket;
    if (na < 8) {
        bucket = ret + na;
    } else {
        double v = log((double)na / 8.0) / log(16.0) * 8.0;
        int vi = 8 + (int)v;
        if (vi > 15) vi = 15;
        bucket = ret + vi;
    }
    #pragma unroll
    for (int h = 0; h < HH; h++) tab[r*HH + h] = rel_bias[bucket*HH + h];
}

// ---------------- fp32 -> bf16 hi/lo split ----------------------------------
__global__ __launch_bounds__(256)
void split_kernel(const float4* __restrict__ in, __nv_bfloat16* __restrict__ oh,
                  __nv_bfloat16* __restrict__ ol, int n4)
{
    int i = blockIdx.x * 256 + threadIdx.x;
    if (i >= n4) return;
    float4 v = in[i];
    float vs[4] = {v.x, v.y, v.z, v.w};
    __nv_bfloat16 h4[4], l4[4];
    #pragma unroll
    for (int j = 0; j < 4; j++){
        __nv_bfloat16 h = __float2bfloat16(vs[j]);
        h4[j] = h;
        l4[j] = __float2bfloat16(vs[j] - __bfloat162float(h));
    }
    *(ushort4*)(oh + (size_t)i*4) = *(ushort4*)h4;
    *(ushort4*)(ol + (size_t)i*4) = *(ushort4*)l4;
}

// ---------------- transpose + split: in[K,N] -> out[N,K] hi/lo --------------
__global__ __launch_bounds__(256)
void transpose_split(const float* __restrict__ in, __nv_bfloat16* __restrict__ oh,
                     __nv_bfloat16* __restrict__ ol, int K, int N)
{
    __shared__ float t[32][33];
    int n0 = blockIdx.x*32, k0 = blockIdx.y*32;
    int tx = threadIdx.x, ty = threadIdx.y;
    #pragma unroll
    for (int i = 0; i < 32; i += 8)
        t[ty+i][tx] = in[(size_t)(k0+ty+i)*N + n0+tx];
    __syncthreads();
    #pragma unroll
    for (int i = 0; i < 32; i += 8){
        float v = t[tx][ty+i];
        __nv_bfloat16 h = __float2bfloat16(v);
        __nv_bfloat16 l = __float2bfloat16(v - __bfloat162float(h));
        oh[(size_t)(n0+ty+i)*K + k0+tx] = h;
        ol[(size_t)(n0+ty+i)*K + k0+tx] = l;
    }
}

// ---------------- split-bf16 tensor GEMM via mma.sync ------------------------
// C[M,N] = A[M,K] @ Bt[N,K]^T + bias, 3-way Markidis split, fp32 accum.
// CTA: 128x128 tile, BK=64, 8 warps (warp tile 32x64), cp.async double buffer.
#define GSMEM (2*4*16384)
__global__ __launch_bounds__(256, 1)
void tcgemm(const __nv_bfloat16* __restrict__ Ah, const __nv_bfloat16* __restrict__ Al,
            const __nv_bfloat16* __restrict__ Bh, const __nv_bfloat16* __restrict__ Bl,
            const float* __restrict__ bias, float* __restrict__ C,
            int M, int N, int K, int relu)
{
    extern __shared__ __align__(1024) char smraw[];
    uint32_t sb = s2u(smraw);
    const int tid = threadIdx.x, wid = tid >> 5, lane = tid & 31;
    const int m0 = blockIdx.y*128, n0 = blockIdx.x*128;
    const int wm = (wid >> 1) * 32;      // warp M offset in tile
    const int wn = (wid & 1) * 64;       // warp N offset in tile

    const int KT = K >> 6;
    const __nv_bfloat16* srcs[4] = { Ah + (size_t)m0*K, Al + (size_t)m0*K,
                                     Bh + (size_t)n0*K, Bl + (size_t)n0*K };

    // per-thread cp.async coords: 4 chunks/tile, 16B each
    const int crow[4] = { (tid + 0) >> 3, (tid + 256) >> 3,
                          (tid + 512) >> 3, (tid + 768) >> 3 };
    const int ccol = (tid & 7);

    // prologue: k-tile 0 -> stage 0
    #pragma unroll
    for (int t = 0; t < 4; t++){
        uint32_t tb = sb + t*16384;
        const __nv_bfloat16* s = srcs[t];
        #pragma unroll
        for (int i = 0; i < 4; i++)
            cp16(tb + SWZ(crow[i]*128 + ccol*16), s + (size_t)crow[i]*K + ccol*8);
    }
    asm volatile("cp.async.commit_group;" ::: "memory");

    float acc[2][8][4];
    #pragma unroll
    for (int a = 0; a < 2; a++)
        #pragma unroll
        for (int b = 0; b < 8; b++)
            #pragma unroll
            for (int c = 0; c < 4; c++) acc[a][b][c] = 0.f;

    // ldmatrix lane addressing within a 16-row block
    const int lrow  = (lane & 7) + ((lane >> 3) & 1) * 8;
    const int lkoff = (lane >> 4) * 8;       // k sub-offset 0/8

    for (int kt = 0; kt < KT; kt++){
        asm volatile("cp.async.wait_group 0;" ::: "memory");
        __syncthreads();

        uint32_t bufs = sb + (kt & 1) * 65536;

        if (kt + 1 < KT){
            uint32_t nbb = sb + ((kt + 1) & 1) * 65536;
            int k0 = (kt + 1) << 6;
            #pragma unroll
            for (int t = 0; t < 4; t++){
                uint32_t tb = nbb + t*16384;
                const __nv_bfloat16* s = srcs[t] + k0;
                #pragma unroll
                for (int i = 0; i < 4; i++)
                    cp16(tb + SWZ(crow[i]*128 + ccol*16), s + (size_t)crow[i]*K + ccol*8);
            }
            asm volatile("cp.async.commit_group;" ::: "memory");
        }

        #pragma unroll
        for (int ks = 0; ks < 4; ks++){
            const int kb2 = (ks*16 + lkoff) * 2;   // byte offset along k
            uint32_t ah[2][4], al[2][4], bh[4][4], bl[4][4];
            #pragma unroll
            for (int mb = 0; mb < 2; mb++){
                int r = wm + mb*16 + lrow;
                ldm4(ah[mb], bufs +         SWZ(r*128 + kb2));
                ldm4(al[mb], bufs + 16384 + SWZ(r*128 + kb2));
            }
            #pragma unroll
            for (int nb = 0; nb < 4; nb++){
                int r = wn + nb*16 + lrow;
                ldm4(bh[nb], bufs + 32768 + SWZ(r*128 + kb2));
                ldm4(bl[nb], bufs + 49152 + SWZ(r*128 + kb2));
            }
            #pragma unroll
            for (int mb = 0; mb < 2; mb++){
                #pragma unroll
                for (int nb = 0; nb < 4; nb++){
                    // n-block 2*nb: k-frag {reg0, reg2}; 2*nb+1: {reg1, reg3}
                    mma16816(acc[mb][2*nb+0], ah[mb], bh[nb][0], bh[nb][2]);
                    mma16816(acc[mb][2*nb+0], ah[mb], bl[nb][0], bl[nb][2]);
                    mma16816(acc[mb][2*nb+0], al[mb], bh[nb][0], bh[nb][2]);
                    mma16816(acc[mb][2*nb+1], ah[mb], bh[nb][1], bh[nb][3]);
                    mma16816(acc[mb][2*nb+1], ah[mb], bl[nb][1], bl[nb][3]);
                    mma16816(acc[mb][2*nb+1], al[mb], bh[nb][1], bh[nb][3]);
                }
            }
        }
        __syncthreads();
    }

    // epilogue: acc frag (mb,nf): C[m0+wm+mb*16 + lane/4 (+8)][n0+wn+nf*8 + (lane%4)*2]
    const int erow = lane >> 2, ecol = (lane & 3) * 2;
    #pragma unroll
    for (int mb = 0; mb < 2; mb++){
        #pragma unroll
        for (int nf = 0; nf < 8; nf++){
            int r = m0 + wm + mb*16 + erow;
            int cc = n0 + wn + nf*8 + ecol;
            float b0 = bias[cc], b1 = bias[cc+1];
            float2 v0 = make_float2(acc[mb][nf][0] + b0, acc[mb][nf][1] + b1);
            float2 v1 = make_float2(acc[mb][nf][2] + b0, acc[mb][nf][3] + b1);
            if (relu){
                v0.x = fmaxf(v0.x, 0.f); v0.y = fmaxf(v0.y, 0.f);
                v1.x = fmaxf(v1.x, 0.f); v1.y = fmaxf(v1.y, 0.f);
            }
            *(float2*)(C + (size_t)r*N + cc)     = v0;
            *(float2*)(C + (size_t)(r+8)*N + cc) = v1;
        }
    }
}

// ---------------- fused attention (flash style, fp32) -----------------------
#define ATTN_SMEM (4*64*65*4)
__global__ __launch_bounds__(256, 2)
void attn_kernel(const float* __restrict__ Q, const float* __restrict__ Kg,
                 const float* __restrict__ Vg, const int* __restrict__ mask,
                 const float* __restrict__ btab, float* __restrict__ O)
{
    extern __shared__ float sm[];
    float (*Qs)[65] = (float(*)[65])(sm);
    float (*Ks)[65] = (float(*)[65])(sm + 64*65);
    float (*Vs)[65] = (float(*)[65])(sm + 2*64*65);
    float (*Ps)[65] = (float(*)[65])(sm + 3*64*65);

    const int g  = blockIdx.y;
    const int q0 = blockIdx.x * 64;
    const int tid = threadIdx.x;
    const int tr = tid >> 4, tc = tid & 15;
    const int tr4 = tr*4, tc4 = tc*4;
    const int hh = g & (HH-1);
    const int bb = g >> 4;

    const float* Qb = Q  + ((size_t)g*SS + q0)*DHD;
    const float* Kb = Kg + (size_t)g*SS*DHD;
    const float* Vb = Vg + (size_t)g*SS*DHD;

    for (int it = tid; it < 64*16; it += 256) {
        int r = it >> 4, c = (it & 15) * 4;
        float4 v = *(const float4*)(Qb + (size_t)r*DHD + c);
        Qs[r][c+0] = v.x; Qs[r][c+1] = v.y; Qs[r][c+2] = v.z; Qs[r][c+3] = v.w;
    }

    float m[4], l[4], o[4][4];
    #pragma unroll
    for (int i = 0; i < 4; i++) {
        m[i] = -INFINITY; l[i] = 0.f;
        #pragma unroll
        for (int j = 0; j < 4; j++) o[i][j] = 0.f;
    }

    for (int k0 = 0; k0 < SS; k0 += 64) {
        __syncthreads();
        for (int it = tid; it < 64*16; it += 256) {
            int r = it >> 4, c = (it & 15) * 4;
            float4 kv = *(const float4*)(Kb + (size_t)(k0 + r)*DHD + c);
            Ks[r][c+0] = kv.x; Ks[r][c+1] = kv.y; Ks[r][c+2] = kv.z; Ks[r][c+3] = kv.w;
            float4 vv = *(const float4*)(Vb + (size_t)(k0 + r)*DHD + c);
            Vs[r][c+0] = vv.x; Vs[r][c+1] = vv.y; Vs[r][c+2] = vv.z; Vs[r][c+3] = vv.w;
        }
        __syncthreads();

        float s[4][4];
        #pragma unroll
        for (int j = 0; j < 4; j++) {
            int tk = k0 + tc4 + j;
            int mk = mask[bb*SS + tk];
            #pragma unroll
            for (int i = 0; i < 4; i++) {
                int tq = q0 + tr4 + i;
                float bsv = btab[(tq - tk + SS - 1)*HH + hh];
                s[i][j] = mk ? bsv : -1e30f;
            }
        }
        #pragma unroll 8
        for (int e = 0; e < 64; e++) {
            float qa0 = Qs[tr4+0][e], qa1 = Qs[tr4+1][e];
            float qa2 = Qs[tr4+2][e], qa3 = Qs[tr4+3][e];
            float kb0 = Ks[tc4+0][e], kb1 = Ks[tc4+1][e];
            float kb2 = Ks[tc4+2][e], kb3 = Ks[tc4+3][e];
            s[0][0] = fmaf(qa0, kb0, s[0][0]); s[0][1] = fmaf(qa0, kb1, s[0][1]);
            s[0][2] = fmaf(qa0, kb2, s[0][2]); s[0][3] = fmaf(qa0, kb3, s[0][3]);
            s[1][0] = fmaf(qa1, kb0, s[1][0]); s[1][1] = fmaf(qa1, kb1, s[1][1]);
            s[1][2] = fmaf(qa1, kb2, s[1][2]); s[1][3] = fmaf(qa1, kb3, s[1][3]);
            s[2][0] = fmaf(qa2, kb0, s[2][0]); s[2][1] = fmaf(qa2, kb1, s[2][1]);
            s[2][2] = fmaf(qa2, kb2, s[2][2]); s[2][3] = fmaf(qa2, kb3, s[2][3]);
            s[3][0] = fmaf(qa3, kb0, s[3][0]); s[3][1] = fmaf(qa3, kb1, s[3][1]);
            s[3][2] = fmaf(qa3, kb2, s[3][2]); s[3][3] = fmaf(qa3, kb3, s[3][3]);
        }

        float tm[4], mn[4], alpha[4], ps[4];
        #pragma unroll
        for (int i = 0; i < 4; i++) {
            float v = fmaxf(fmaxf(s[i][0], s[i][1]), fmaxf(s[i][2], s[i][3]));
            #pragma unroll
            for (int off = 1; off < 16; off <<= 1)
                v = fmaxf(v, __shfl_xor_sync(0xffffffffu, v, off));
            tm[i] = v;
        }
        #pragma unroll
        for (int i = 0; i < 4; i++) {
            mn[i] = fmaxf(m[i], tm[i]);
            alpha[i] = expf(m[i] - mn[i]);
            float acc = 0.f;
            #pragma unroll
            for (int j = 0; j < 4; j++) {
                float p = expf(s[i][j] - mn[i]);
                Ps[tr4+i][tc4+j] = p;
                acc += p;
            }
            ps[i] = acc;
        }
        #pragma unroll
        for (int i = 0; i < 4; i++) {
            float v = ps[i];
            #pragma unroll
            for (int off = 1; off < 16; off <<= 1)
                v += __shfl_xor_sync(0xffffffffu, v, off);
            l[i] = l[i]*alpha[i] + v;
            m[i] = mn[i];
        }
        #pragma unroll
        for (int i = 0; i < 4; i++)
            #pragma unroll
            for (int j = 0; j < 4; j++) o[i][j] *= alpha[i];

        __syncthreads();

        #pragma unroll 8
        for (int kk = 0; kk < 64; kk++) {
            float p0 = Ps[tr4+0][kk], p1 = Ps[tr4+1][kk];
            float p2 = Ps[tr4+2][kk], p3 = Ps[tr4+3][kk];
            float v0 = Vs[kk][tc4+0], v1 = Vs[kk][tc4+1];
            float v2 = Vs[kk][tc4+2], v3 = Vs[kk][tc4+3];
            o[0][0] = fmaf(p0, v0, o[0][0]); o[0][1] = fmaf(p0, v1, o[0][1]);
            o[0][2] = fmaf(p0, v2, o[0][2]); o[0][3] = fmaf(p0, v3, o[0][3]);
            o[1][0] = fmaf(p1, v0, o[1][0]); o[1][1] = fmaf(p1, v1, o[1][1]);
            o[1][2] = fmaf(p1, v2, o[1][2]); o[1][3] = fmaf(p1, v3, o[1][3]);
            o[2][0] = fmaf(p2, v0, o[2][0]); o[2][1] = fmaf(p2, v1, o[2][1]);
            o[2][2] = fmaf(p2, v2, o[2][2]); o[2][3] = fmaf(p2, v3, o[2][3]);
            o[3][0] = fmaf(p3, v0, o[3][0]); o[3][1] = fmaf(p3, v1, o[3][1]);
            o[3][2] = fmaf(p3, v2, o[3][2]); o[3][3] = fmaf(p3, v3, o[3][3]);
        }
    }

    #pragma unroll
    for (int i = 0; i < 4; i++) {
        float inv = 1.f / l[i];
        float4 ov = make_float4(o[i][0]*inv, o[i][1]*inv, o[i][2]*inv, o[i][3]*inv);
        *(float4*)(O + ((size_t)g*SS + q0 + tr4 + i)*DHD + tc4) = ov;
    }
}

// ---------------- LayerNorm with residual: Out = LN(A + R) ------------------
__global__ __launch_bounds__(256)
void ln_kernel(const float* __restrict__ A, const float* __restrict__ R,
               const float* __restrict__ gamma, const float* __restrict__ beta,
               float* __restrict__ Out)
{
    __shared__ float xs[DD];
    __shared__ float red[8];
    int row = blockIdx.x;
    int tid = threadIdx.x;
    const float* a = A + (size_t)row*DD;
    const float* r = R + (size_t)row*DD;

    float lsum = 0.f;
    for (int i = tid; i < DD; i += 256) {
        float x = a[i] + r[i];
        xs[i] = x;
        lsum += x;
    }
    #pragma unroll
    for (int off = 16; off; off >>= 1) lsum += __shfl_xor_sync(0xffffffffu, lsum, off);
    if ((tid & 31) == 0) red[tid >> 5] = lsum;
    __syncthreads();
    float tot = 0.f;
    #pragma unroll
    for (int w = 0; w < 8; w++) tot += red[w];
    float mu = tot * (1.f / DD);
    __syncthreads();

    float lsq = 0.f;
    for (int i = tid; i < DD; i += 256) {
        float d = xs[i] - mu;
        lsq += d * d;
    }
    #pragma unroll
    for (int off = 16; off; off >>= 1) lsq += __shfl_xor_sync(0xffffffffu, lsq, off);
    if ((tid & 31) == 0) red[tid >> 5] = lsq;
    __syncthreads();
    float vt = 0.f;
    #pragma unroll
    for (int w = 0; w < 8; w++) vt += red[w];
    float var = vt * (1.f / DD);
    float inv = 1.f / sqrtf(var + 1e-5f);

    for (int i = tid; i < DD; i += 256) {
        Out[(size_t)row*DD + i] = gamma[i] * (xs[i] - mu) * inv + beta[i];
    }
}

// ---------------- launch ----------------------------------------------------
extern "C" void kernel_launch(void* const* d_in, const int* in_sizes, int n_in,
                              void* d_out, int out_size)
{
    const float* x    = (const float*)d_in[0];
    const int*   mask = (const int*)  d_in[1];
    const float* Wq = (const float*)d_in[2];  const float* bq = (const float*)d_in[3];
    const float* Wk = (const float*)d_in[4];  const float* bk = (const float*)d_in[5];
    const float* Wv = (const float*)d_in[6];  const float* bv = (const float*)d_in[7];
    const float* Wo = (const float*)d_in[8];  const float* bo = (const float*)d_in[9];
    const float* rel_bias = (const float*)d_in[10];
    const float* ln1g = (const float*)d_in[11]; const float* ln1b = (const float*)d_in[12];
    const float* W1 = (const float*)d_in[13]; const float* b1 = (const float*)d_in[14];
    const float* W2 = (const float*)d_in[15]; const float* b2 = (const float*)d_in[16];
    const float* ln2g = (const float*)d_in[17]; const float* ln2b = (const float*)d_in[18];
    float* out = (float*)d_out;

    float *q, *k, *v, *att, *tmp, *h, *ff1, *btab;
    cudaGetSymbolAddress((void**)&q,    g_q);
    cudaGetSymbolAddress((void**)&k,    g_k);
    cudaGetSymbolAddress((void**)&v,    g_v);
    cudaGetSymbolAddress((void**)&att,  g_att);
    cudaGetSymbolAddress((void**)&tmp,  g_tmp);
    cudaGetSymbolAddress((void**)&h,    g_h);
    cudaGetSymbolAddress((void**)&ff1,  g_ff1);
    cudaGetSymbolAddress((void**)&btab, g_btab);

    __nv_bfloat16 *xh,*xl, *ath,*atl, *hh,*hl, *fh,*fl;
    __nv_bfloat16 *wqh,*wql,*wkh,*wkl,*wvh,*wvl,*woh,*wol,*w1h,*w1l,*w2h,*w2l;
    cudaGetSymbolAddress((void**)&xh,  g_xh);  cudaGetSymbolAddress((void**)&xl,  g_xl);
    cudaGetSymbolAddress((void**)&ath, g_ath); cudaGetSymbolAddress((void**)&atl, g_atl);
    cudaGetSymbolAddress((void**)&hh,  g_hh);  cudaGetSymbolAddress((void**)&hl,  g_hl);
    cudaGetSymbolAddress((void**)&fh,  g_fh);  cudaGetSymbolAddress((void**)&fl,  g_fl);
    cudaGetSymbolAddress((void**)&wqh, g_wqh); cudaGetSymbolAddress((void**)&wql, g_wql);
    cudaGetSymbolAddress((void**)&wkh, g_wkh); cudaGetSymbolAddress((void**)&wkl, g_wkl);
    cudaGetSymbolAddress((void**)&wvh, g_wvh); cudaGetSymbolAddress((void**)&wvl, g_wvl);
    cudaGetSymbolAddress((void**)&woh, g_woh); cudaGetSymbolAddress((void**)&wol, g_wol);
    cudaGetSymbolAddress((void**)&w1h, g_w1h); cudaGetSymbolAddress((void**)&w1l, g_w1l);
    cudaGetSymbolAddress((void**)&w2h, g_w2h); cudaGetSymbolAddress((void**)&w2l, g_w2l);

    cudaFuncSetAttribute(attn_kernel,
                         cudaFuncAttributeMaxDynamicSharedMemorySize, ATTN_SMEM);
    cudaFuncSetAttribute(tcgemm,
                         cudaFuncAttributeMaxDynamicSharedMemorySize, GSMEM);

    // 1. relative bias table
    bias_table_kernel<<<(2*SS - 1 + 255)/256, 256>>>(rel_bias, btab);

    // 2. split input, transpose+split weights
    split_kernel<<<(MR*DD/4 + 255)/256, 256>>>((const float4*)x, xh, xl, MR*DD/4);
    dim3 tb(32, 8);
    transpose_split<<<dim3(DD/32, DD/32), tb>>>(Wq, wqh, wql, DD, DD);
    transpose_split<<<dim3(DD/32, DD/32), tb>>>(Wk, wkh, wkl, DD, DD);
    transpose_split<<<dim3(DD/32, DD/32), tb>>>(Wv, wvh, wvl, DD, DD);
    transpose_split<<<dim3(DD/32, DD/32), tb>>>(Wo, woh, wol, DD, DD);
    transpose_split<<<dim3(FF/32, DD/32), tb>>>(W1, w1h, w1l, DD, FF);
    transpose_split<<<dim3(DD/32, FF/32), tb>>>(W2, w2h, w2l, FF, DD);

    // 3. Q/K/V projections (tensor cores)
    dim3 gproj(DD/128, MR/128);
    tcgemm<<<gproj, 256, GSMEM>>>(xh, xl, wqh, wql, bq, q, MR, DD, DD, 0);
    tcgemm<<<gproj, 256, GSMEM>>>(xh, xl, wkh, wkl, bk, k, MR, DD, DD, 0);
    tcgemm<<<gproj, 256, GSMEM>>>(xh, xl, wvh, wvl, bv, v, MR, DD, DD, 0);

    // 4. fused attention (fp32)
    attn_kernel<<<dim3(SS/64, NG), 256, ATTN_SMEM>>>(q, k, v, mask, btab, att);

    // 5. output projection
    split_kernel<<<(MR*DD/4 + 255)/256, 256>>>((const float4*)att, ath, atl, MR*DD/4);
    tcgemm<<<gproj, 256, GSMEM>>>(ath, atl, woh, wol, bo, tmp, MR, DD, DD, 0);

    // 6. LN1
    ln_kernel<<<MR, 256>>>(tmp, x, ln1g, ln1b, h);

    // 7. FFN
    split_kernel<<<(MR*DD/4 + 255)/256, 256>>>((const float4*)h, hh, hl, MR*DD/4);
    dim3 gff1(FF/128, MR/128);
    tcgemm<<<gff1, 256, GSMEM>>>(hh, hl, w1h, w1l, b1, ff1, MR, FF, DD, 1);
    split_kernel<<<((int)((size_t)MR*FF/4) + 255)/256, 256>>>((const float4*)ff1, fh, fl, MR*FF/4);
    dim3 gff2(DD/128, MR/128);
    tcgemm<<<gff2, 256, GSMEM>>>(fh, fl, w2h, w2l, b2, tmp, MR, DD, FF, 0);

    // 8. LN2
    ln_kernel<<<MR, 256>>>(tmp, h, ln2g, ln2b, out);
}

// round 4
// speedup vs baseline: 2.7433x; 1.3795x over previous
#include <cuda_runtime.h>
#include <cuda_bf16.h>
#include <math.h>
#include <stdint.h>

#define BB 4
#define SS 1024
#define DD 1024
#define HH 16
#define FF 4096
#define DHD 64
#define NG (BB*HH)
#define MR (BB*SS)

// ---------------- scratch (static device globals; no allocation) -------------
__device__ float g_tmp[MR*DD];
__device__ float g_h[MR*DD];
__device__ float g_btab[(2*SS-1)*HH];

// bf16 hi/lo activations
__device__ __nv_bfloat16 g_xh[MR*DD],  g_xl[MR*DD];
__device__ __nv_bfloat16 g_qh[MR*DD],  g_ql[MR*DD];
__device__ __nv_bfloat16 g_kbh[MR*DD], g_kbl[MR*DD];
__device__ __nv_bfloat16 g_vbh[MR*DD], g_vbl[MR*DD];
__device__ __nv_bfloat16 g_ath[MR*DD], g_atl[MR*DD];
__device__ __nv_bfloat16 g_hh[MR*DD],  g_hl[MR*DD];
__device__ __nv_bfloat16 g_fh[(size_t)MR*FF], g_fl[(size_t)MR*FF];
// bf16 hi/lo transposed weights [N,K]
__device__ __nv_bfloat16 g_wqh[DD*DD], g_wql[DD*DD];
__device__ __nv_bfloat16 g_wkh[DD*DD], g_wkl[DD*DD];
__device__ __nv_bfloat16 g_wvh[DD*DD], g_wvl[DD*DD];
__device__ __nv_bfloat16 g_woh[DD*DD], g_wol[DD*DD];
__device__ __nv_bfloat16 g_w1h[(size_t)DD*FF], g_w1l[(size_t)DD*FF];
__device__ __nv_bfloat16 g_w2h[(size_t)FF*DD], g_w2l[(size_t)FF*DD];

// ---------------- PTX helpers ------------------------------------------------
#define SWZ(o) ((o) ^ (((o) >> 3) & 0x70))

__device__ __forceinline__ uint32_t s2u(const void* p){
    uint32_t a;
    asm("{ .reg .u64 t; cvta.to.shared.u64 t, %1; cvt.u32.u64 %0, t; }"
        : "=r"(a) : "l"(p));
    return a;
}
__device__ __forceinline__ void cp16(uint32_t d, const void* s){
    asm volatile("cp.async.cg.shared.global [%0], [%1], 16;" :: "r"(d), "l"(s));
}
__device__ __forceinline__ void ldm4(uint32_t* r, uint32_t a){
    asm volatile("ldmatrix.sync.aligned.m8n8.x4.shared.b16 {%0,%1,%2,%3}, [%4];"
        : "=r"(r[0]), "=r"(r[1]), "=r"(r[2]), "=r"(r[3]) : "r"(a));
}
__device__ __forceinline__ void ldm4t(uint32_t* r, uint32_t a){
    asm volatile("ldmatrix.sync.aligned.m8n8.x4.trans.shared.b16 {%0,%1,%2,%3}, [%4];"
        : "=r"(r[0]), "=r"(r[1]), "=r"(r[2]), "=r"(r[3]) : "r"(a));
}
__device__ __forceinline__ void mma16816(float* c, const uint32_t* a,
                                         uint32_t b0, uint32_t b1){
    asm volatile("mma.sync.aligned.m16n8k16.row.col.f32.bf16.bf16.f32 "
        "{%0,%1,%2,%3}, {%4,%5,%6,%7}, {%8,%9}, {%0,%1,%2,%3};"
        : "+f"(c[0]), "+f"(c[1]), "+f"(c[2]), "+f"(c[3])
        : "r"(a[0]), "r"(a[1]), "r"(a[2]), "r"(a[3]), "r"(b0), "r"(b1));
}
__device__ __forceinline__ uint32_t bf2u(__nv_bfloat162 v){
    return *(uint32_t*)&v;
}

// ---------------- relative-position bias table ------------------------------
__global__ void bias_table_kernel(const float* __restrict__ rel_bias,
                                  float* __restrict__ tab)
{
    int r = blockIdx.x * blockDim.x + threadIdx.x;
    if (r >= 2*SS - 1) return;
    int rel = r - (SS - 1);
    int n = -rel;
    int ret = (n < 0) ? 16 : 0;
    int na = n < 0 ? -n : n;
    int bucket;
    if (na < 8) {
        bucket = ret + na;
    } else {
        double v = log((double)na / 8.0) / log(16.0) * 8.0;
        int vi = 8 + (int)v;
        if (vi > 15) vi = 15;
        bucket = ret + vi;
    }
    #pragma unroll
    for (int h = 0; h < HH; h++) tab[r*HH + h] = rel_bias[bucket*HH + h];
}

// ---------------- fp32 -> bf16 hi/lo split ----------------------------------
__global__ __launch_bounds__(256)
void split_kernel(const float4* __restrict__ in, __nv_bfloat16* __restrict__ oh,
                  __nv_bfloat16* __restrict__ ol, int n4)
{
    int i = blockIdx.x * 256 + threadIdx.x;
    if (i >= n4) return;
    float4 v = in[i];
    float vs[4] = {v.x, v.y, v.z, v.w};
    __nv_bfloat16 h4[4], l4[4];
    #pragma unroll
    for (int j = 0; j < 4; j++){
        __nv_bfloat16 h = __float2bfloat16(vs[j]);
        h4[j] = h;
        l4[j] = __float2bfloat16(vs[j] - __bfloat162float(h));
    }
    *(ushort4*)(oh + (size_t)i*4) = *(ushort4*)h4;
    *(ushort4*)(ol + (size_t)i*4) = *(ushort4*)l4;
}

// ---------------- transpose + split: in[K,N] -> out[N,K] hi/lo --------------
__global__ __launch_bounds__(256)
void transpose_split(const float* __restrict__ in, __nv_bfloat16* __restrict__ oh,
                     __nv_bfloat16* __restrict__ ol, int K, int N)
{
    __shared__ float t[32][33];
    int n0 = blockIdx.x*32, k0 = blockIdx.y*32;
    int tx = threadIdx.x, ty = threadIdx.y;
    #pragma unroll
    for (int i = 0; i < 32; i += 8)
        t[ty+i][tx] = in[(size_t)(k0+ty+i)*N + n0+tx];
    __syncthreads();
    #pragma unroll
    for (int i = 0; i < 32; i += 8){
        float v = t[tx][ty+i];
        __nv_bfloat16 h = __float2bfloat16(v);
        __nv_bfloat16 l = __float2bfloat16(v - __bfloat162float(h));
        oh[(size_t)(n0+ty+i)*K + k0+tx] = h;
        ol[(size_t)(n0+ty+i)*K + k0+tx] = l;
    }
}

// ---------------- split-bf16 tensor GEMM via mma.sync ------------------------
// C[M,N] = A[M,K] @ Bt[N,K]^T + bias. Optional fp32 out C and/or bf16 hi/lo out.
#define GSMEM (2*4*16384)
__global__ __launch_bounds__(256, 1)
void tcgemm(const __nv_bfloat16* __restrict__ Ah, const __nv_bfloat16* __restrict__ Al,
            const __nv_bfloat16* __restrict__ Bh, const __nv_bfloat16* __restrict__ Bl,
            const float* __restrict__ bias, float* __restrict__ C,
            __nv_bfloat16* __restrict__ Oh, __nv_bfloat16* __restrict__ Ol,
            int M, int N, int K, int relu)
{
    extern __shared__ __align__(1024) char smraw[];
    uint32_t sb = s2u(smraw);
    const int tid = threadIdx.x, wid = tid >> 5, lane = tid & 31;
    const int m0 = blockIdx.y*128, n0 = blockIdx.x*128;
    const int wm = (wid >> 1) * 32;
    const int wn = (wid & 1) * 64;

    const int KT = K >> 6;
    const __nv_bfloat16* srcs[4] = { Ah + (size_t)m0*K, Al + (size_t)m0*K,
                                     Bh + (size_t)n0*K, Bl + (size_t)n0*K };

    const int crow[4] = { (tid + 0) >> 3, (tid + 256) >> 3,
                          (tid + 512) >> 3, (tid + 768) >> 3 };
    const int ccol = (tid & 7);

    #pragma unroll
    for (int t = 0; t < 4; t++){
        uint32_t tb = sb + t*16384;
        const __nv_bfloat16* s = srcs[t];
        #pragma unroll
        for (int i = 0; i < 4; i++)
            cp16(tb + SWZ(crow[i]*128 + ccol*16), s + (size_t)crow[i]*K + ccol*8);
    }
    asm volatile("cp.async.commit_group;" ::: "memory");

    float acc[2][8][4];
    #pragma unroll
    for (int a = 0; a < 2; a++)
        #pragma unroll
        for (int b = 0; b < 8; b++)
            #pragma unroll
            for (int c = 0; c < 4; c++) acc[a][b][c] = 0.f;

    const int lrow  = (lane & 7) + ((lane >> 3) & 1) * 8;
    const int lkoff = (lane >> 4) * 8;

    for (int kt = 0; kt < KT; kt++){
        asm volatile("cp.async.wait_group 0;" ::: "memory");
        __syncthreads();

        uint32_t bufs = sb + (kt & 1) * 65536;

        if (kt + 1 < KT){
            uint32_t nbb = sb + ((kt + 1) & 1) * 65536;
            int k0 = (kt + 1) << 6;
            #pragma unroll
            for (int t = 0; t < 4; t++){
                uint32_t tb = nbb + t*16384;
                const __nv_bfloat16* s = srcs[t] + k0;
                #pragma unroll
                for (int i = 0; i < 4; i++)
                    cp16(tb + SWZ(crow[i]*128 + ccol*16), s + (size_t)crow[i]*K + ccol*8);
            }
            asm volatile("cp.async.commit_group;" ::: "memory");
        }

        #pragma unroll
        for (int ks = 0; ks < 4; ks++){
            const int kb2 = (ks*16 + lkoff) * 2;
            uint32_t ah[2][4], al[2][4], bh[4][4], bl[4][4];
            #pragma unroll
            for (int mb = 0; mb < 2; mb++){
                int r = wm + mb*16 + lrow;
                ldm4(ah[mb], bufs +         SWZ(r*128 + kb2));
                ldm4(al[mb], bufs + 16384 + SWZ(r*128 + kb2));
            }
            #pragma unroll
            for (int nb = 0; nb < 4; nb++){
                int r = wn + nb*16 + lrow;
                ldm4(bh[nb], bufs + 32768 + SWZ(r*128 + kb2));
                ldm4(bl[nb], bufs + 49152 + SWZ(r*128 + kb2));
            }
            #pragma unroll
            for (int mb = 0; mb < 2; mb++){
                #pragma unroll
                for (int nb = 0; nb < 4; nb++){
                    mma16816(acc[mb][2*nb+0], ah[mb], bh[nb][0], bh[nb][2]);
                    mma16816(acc[mb][2*nb+0], ah[mb], bl[nb][0], bl[nb][2]);
                    mma16816(acc[mb][2*nb+0], al[mb], bh[nb][0], bh[nb][2]);
                    mma16816(acc[mb][2*nb+1], ah[mb], bh[nb][1], bh[nb][3]);
                    mma16816(acc[mb][2*nb+1], ah[mb], bl[nb][1], bl[nb][3]);
                    mma16816(acc[mb][2*nb+1], al[mb], bh[nb][1], bh[nb][3]);
                }
            }
        }
        __syncthreads();
    }

    const int erow = lane >> 2, ecol = (lane & 3) * 2;
    #pragma unroll
    for (int mb = 0; mb < 2; mb++){
        #pragma unroll
        for (int nf = 0; nf < 8; nf++){
            int r = m0 + wm + mb*16 + erow;
            int cc = n0 + wn + nf*8 + ecol;
            float b0 = bias[cc], b1 = bias[cc+1];
            float2 v0 = make_float2(acc[mb][nf][0] + b0, acc[mb][nf][1] + b1);
            float2 v1 = make_float2(acc[mb][nf][2] + b0, acc[mb][nf][3] + b1);
            if (relu){
                v0.x = fmaxf(v0.x, 0.f); v0.y = fmaxf(v0.y, 0.f);
                v1.x = fmaxf(v1.x, 0.f); v1.y = fmaxf(v1.y, 0.f);
            }
            if (C){
                *(float2*)(C + (size_t)r*N + cc)     = v0;
                *(float2*)(C + (size_t)(r+8)*N + cc) = v1;
            }
            if (Oh){
                __nv_bfloat162 h0 = __floats2bfloat162_rn(v0.x, v0.y);
                __nv_bfloat162 l0 = __floats2bfloat162_rn(
                    v0.x - __bfloat162float(h0.x), v0.y - __bfloat162float(h0.y));
                __nv_bfloat162 h1 = __floats2bfloat162_rn(v1.x, v1.y);
                __nv_bfloat162 l1 = __floats2bfloat162_rn(
                    v1.x - __bfloat162float(h1.x), v1.y - __bfloat162float(h1.y));
                *(__nv_bfloat162*)(Oh + (size_t)r*N + cc)     = h0;
                *(__nv_bfloat162*)(Ol + (size_t)r*N + cc)     = l0;
                *(__nv_bfloat162*)(Oh + (size_t)(r+8)*N + cc) = h1;
                *(__nv_bfloat162*)(Ol + (size_t)(r+8)*N + cc) = l1;
            }
        }
    }
}

// ---------------- tensor-core flash attention --------------------------------
// CTA = (q-tile of 128, group). 8 warps x 16 rows. 64-key chunks, split-bf16
// QK^T and P.V with fp32 online softmax. Outputs hi/lo bf16 for the Wo GEMM.
#define AT_SMEM 99328
__global__ __launch_bounds__(256, 1)
void attn_tc(const __nv_bfloat16* __restrict__ Qh_, const __nv_bfloat16* __restrict__ Ql_,
             const __nv_bfloat16* __restrict__ Kh_, const __nv_bfloat16* __restrict__ Kl_,
             const __nv_bfloat16* __restrict__ Vh_, const __nv_bfloat16* __restrict__ Vl_,
             const int* __restrict__ mask, const float* __restrict__ btab,
             __nv_bfloat16* __restrict__ Oh, __nv_bfloat16* __restrict__ Ol)
{
    extern __shared__ __align__(1024) char smraw[];
    uint32_t sb = s2u(smraw);
    const int tid = threadIdx.x, wid = tid >> 5, lane = tid & 31;
    const int g = blockIdx.y, q0 = blockIdx.x * 128;
    const int hh_ = g & (HH-1), bb = g >> 4;
    const int wq = wid * 16;
    const int lr = lane >> 2, lq = lane & 3;
    const int lrow = (lane & 7) + ((lane >> 3) & 1) * 8;
    const int koff = ((lane >> 4) & 1) * 16;           // byte sub-offset

    const uint32_t oQh = 0, oQl = 16384, oKV = 32768;
    float* sbias = (float*)(smraw + 98304);            // 192 floats
    float* spen  = (float*)(smraw + 99072);            // 64 floats

    const size_t gb = (size_t)g * SS * DHD;

    // Q tile (both halves)
    {
        const __nv_bfloat16* qh = Qh_ + gb + (size_t)q0 * DHD;
        const __nv_bfloat16* ql = Ql_ + gb + (size_t)q0 * DHD;
        #pragma unroll
        for (int i = 0; i < 4; i++){
            int c = tid + 256*i, row = c >> 3, col = c & 7;
            cp16(sb + oQh + SWZ(row*128 + col*16), qh + (size_t)row*64 + col*8);
            cp16(sb + oQl + SWZ(row*128 + col*16), ql + (size_t)row*64 + col*8);
        }
    }
    // chunk 0 K/V
    {
        uint32_t kvb = sb + oKV;
        const __nv_bfloat16* srcs[4] = { Kh_ + gb, Kl_ + gb, Vh_ + gb, Vl_ + gb };
        #pragma unroll
        for (int t = 0; t < 4; t++)
            #pragma unroll
            for (int i = 0; i < 2; i++){
                int c = tid + 256*i, row = c >> 3, col = c & 7;
                cp16(kvb + t*8192 + SWZ(row*128 + col*16), srcs[t] + (size_t)row*64 + col*8);
            }
    }
    asm volatile("cp.async.commit_group;" ::: "memory");

    float m0v = -1e30f, m1v = -1e30f, l0 = 0.f, l1 = 0.f;
    float o[8][4];
    #pragma unroll
    for (int i = 0; i < 8; i++)
        #pragma unroll
        for (int j = 0; j < 4; j++) o[i][j] = 0.f;

    for (int ch = 0; ch < 16; ch++){
        const int k0 = ch * 64;
        if (tid < 192){
            int idx = tid + q0 - k0 - 63 + (SS - 1);
            if (idx < 0) idx = 0;
            if (idx > 2*SS - 2) idx = 2*SS - 2;
            sbias[tid] = btab[idx*HH + hh_];
        }
        if (tid < 64) spen[tid] = (mask[bb*SS + k0 + tid] == 0) ? -1e30f : 0.f;

        if (ch + 1 < 16){
            uint32_t kvb = sb + oKV + ((ch+1)&1)*32768;
            const size_t off = gb + (size_t)(k0 + 64)*64;
            const __nv_bfloat16* srcs[4] = { Kh_+off, Kl_+off, Vh_+off, Vl_+off };
            #pragma unroll
            for (int t = 0; t < 4; t++)
                #pragma unroll
                for (int i = 0; i < 2; i++){
                    int c = tid + 256*i, row = c >> 3, col = c & 7;
                    cp16(kvb + t*8192 + SWZ(row*128 + col*16), srcs[t] + (size_t)row*64 + col*8);
                }
            asm volatile("cp.async.commit_group;" ::: "memory");
            asm volatile("cp.async.wait_group 1;" ::: "memory");
        } else {
            asm volatile("cp.async.wait_group 0;" ::: "memory");
        }
        __syncthreads();

        const uint32_t kvb = sb + oKV + (ch&1)*32768;

        // ---- scores S = Qh.Kh + Qh.Kl + Ql.Kh ----
        float s_[8][4];
        #pragma unroll
        for (int i = 0; i < 8; i++)
            #pragma unroll
            for (int j = 0; j < 4; j++) s_[i][j] = 0.f;

        #pragma unroll
        for (int kb = 0; kb < 4; kb++){
            uint32_t qa[4], qb[4];
            ldm4(qa, sb + oQh + SWZ((wq+lrow)*128 + kb*32 + koff));
            ldm4(qb, sb + oQl + SWZ((wq+lrow)*128 + kb*32 + koff));
            #pragma unroll
            for (int j = 0; j < 4; j++){
                uint32_t kh4[4], kl4[4];
                ldm4(kh4, kvb +        SWZ((j*16+lrow)*128 + kb*32 + koff));
                ldm4(kl4, kvb + 8192 + SWZ((j*16+lrow)*128 + kb*32 + koff));
                mma16816(s_[2*j],   qa, kh4[0], kh4[2]);
                mma16816(s_[2*j],   qa, kl4[0], kl4[2]);
                mma16816(s_[2*j],   qb, kh4[0], kh4[2]);
                mma16816(s_[2*j+1], qa, kh4[1], kh4[3]);
                mma16816(s_[2*j+1], qa, kl4[1], kl4[3]);
                mma16816(s_[2*j+1], qb, kh4[1], kh4[3]);
            }
        }

        // ---- bias + mask ----
        const int r0 = wq + lr, r1 = r0 + 8;
        #pragma unroll
        for (int nf = 0; nf < 8; nf++){
            int c0 = nf*8 + lq*2;
            s_[nf][0] += sbias[r0 - c0 + 63]     + spen[c0];
            s_[nf][1] += sbias[r0 - c0 + 62]     + spen[c0+1];
            s_[nf][2] += sbias[r1 - c0 + 63]     + spen[c0];
            s_[nf][3] += sbias[r1 - c0 + 62]     + spen[c0+1];
        }

        // ---- online softmax (rows r0 via regs 0,1; rows r1 via regs 2,3) ----
        float mx0 = -1e30f, mx1 = -1e30f;
        #pragma unroll
        for (int nf = 0; nf < 8; nf++){
            mx0 = fmaxf(mx0, fmaxf(s_[nf][0], s_[nf][1]));
            mx1 = fmaxf(mx1, fmaxf(s_[nf][2], s_[nf][3]));
        }
        #pragma unroll
        for (int off = 1; off < 4; off <<= 1){
            mx0 = fmaxf(mx0, __shfl_xor_sync(0xffffffffu, mx0, off));
            mx1 = fmaxf(mx1, __shfl_xor_sync(0xffffffffu, mx1, off));
        }
        float mn0 = fmaxf(m0v, mx0), mn1 = fmaxf(m1v, mx1);
        float al0 = __expf(m0v - mn0), al1 = __expf(m1v - mn1);
        float sum0 = 0.f, sum1 = 0.f;
        #pragma unroll
        for (int nf = 0; nf < 8; nf++){
            s_[nf][0] = __expf(s_[nf][0] - mn0); sum0 += s_[nf][0];
            s_[nf][1] = __expf(s_[nf][1] - mn0); sum0 += s_[nf][1];
            s_[nf][2] = __expf(s_[nf][2] - mn1); sum1 += s_[nf][2];
            s_[nf][3] = __expf(s_[nf][3] - mn1); sum1 += s_[nf][3];
        }
        #pragma unroll
        for (int off = 1; off < 4; off <<= 1){
            sum0 += __shfl_xor_sync(0xffffffffu, sum0, off);
            sum1 += __shfl_xor_sync(0xffffffffu, sum1, off);
        }
        l0 = l0*al0 + sum0; l1 = l1*al1 + sum1;
        m0v = mn0; m1v = mn1;
        #pragma unroll
        for (int nf = 0; nf < 8; nf++){
            o[nf][0] *= al0; o[nf][1] *= al0;
            o[nf][2] *= al1; o[nf][3] *= al1;
        }

        // ---- O += P.Vh + P.Vl + Plo.Vh (P frags straight from score accs) ----
        #pragma unroll
        for (int kb = 0; kb < 4; kb++){
            uint32_t ah[4], alr[4];
            {
                __nv_bfloat162 t0 = __floats2bfloat162_rn(s_[2*kb][0],   s_[2*kb][1]);
                __nv_bfloat162 t1 = __floats2bfloat162_rn(s_[2*kb][2],   s_[2*kb][3]);
                __nv_bfloat162 t2 = __floats2bfloat162_rn(s_[2*kb+1][0], s_[2*kb+1][1]);
                __nv_bfloat162 t3 = __floats2bfloat162_rn(s_[2*kb+1][2], s_[2*kb+1][3]);
                ah[0] = bf2u(t0); ah[1] = bf2u(t1); ah[2] = bf2u(t2); ah[3] = bf2u(t3);
                alr[0] = bf2u(__floats2bfloat162_rn(
                    s_[2*kb][0]   - __bfloat162float(t0.x), s_[2*kb][1]   - __bfloat162float(t0.y)));
                alr[1] = bf2u(__floats2bfloat162_rn(
                    s_[2*kb][2]   - __bfloat162float(t1.x), s_[2*kb][3]   - __bfloat162float(t1.y)));
                alr[2] = bf2u(__floats2bfloat162_rn(
                    s_[2*kb+1][0] - __bfloat162float(t2.x), s_[2*kb+1][1] - __bfloat162float(t2.y)));
                alr[3] = bf2u(__floats2bfloat162_rn(
                    s_[2*kb+1][2] - __bfloat162float(t3.x), s_[2*kb+1][3] - __bfloat162float(t3.y)));
            }
            #pragma unroll
            for (int j = 0; j < 4; j++){
                uint32_t vh4[4], vl4[4];
                ldm4t(vh4, kvb + 16384 + SWZ((kb*16+lrow)*128 + j*32 + koff));
                ldm4t(vl4, kvb + 24576 + SWZ((kb*16+lrow)*128 + j*32 + koff));
                mma16816(o[2*j],   ah,  vh4[0], vh4[1]);
                mma16816(o[2*j+1], ah,  vh4[2], vh4[3]);
                mma16816(o[2*j],   ah,  vl4[0], vl4[1]);
                mma16816(o[2*j+1], ah,  vl4[2], vl4[3]);
                mma16816(o[2*j],   alr, vh4[0], vh4[1]);
                mma16816(o[2*j+1], alr, vh4[2], vh4[3]);
            }
        }
        __syncthreads();
    }

    // ---- epilogue: normalize, split to hi/lo bf16 ----
    const float inv0 = 1.f / l0, inv1 = 1.f / l1;
    const int tq0 = q0 + wq + lr, tq1 = tq0 + 8;
    const size_t b0 = (size_t)g*65536 + (size_t)tq0*64;
    const size_t b1 = (size_t)g*65536 + (size_t)tq1*64;
    #pragma unroll
    for (int nf = 0; nf < 8; nf++){
        int d0 = nf*8 + lq*2;
        float v0 = o[nf][0]*inv0, v1 = o[nf][1]*inv0;
        float w0 = o[nf][2]*inv1, w1 = o[nf][3]*inv1;
        __nv_bfloat162 hv = __floats2bfloat162_rn(v0, v1);
        __nv_bfloat162 lv = __floats2bfloat162_rn(
            v0 - __bfloat162float(hv.x), v1 - __bfloat162float(hv.y));
        __nv_bfloat162 hw = __floats2bfloat162_rn(w0, w1);
        __nv_bfloat162 lw = __floats2bfloat162_rn(
            w0 - __bfloat162float(hw.x), w1 - __bfloat162float(hw.y));
        *(__nv_bfloat162*)(Oh + b0 + d0) = hv;
        *(__nv_bfloat162*)(Ol + b0 + d0) = lv;
        *(__nv_bfloat162*)(Oh + b1 + d0) = hw;
        *(__nv_bfloat162*)(Ol + b1 + d0) = lw;
    }
}

// ---------------- LayerNorm with residual: Out = LN(A + R) (+opt hi/lo) -----
__global__ __launch_bounds__(256)
void ln_kernel(const float* __restrict__ A, const float* __restrict__ R,
               const float* __restrict__ gamma, const float* __restrict__ beta,
               float* __restrict__ Out,
               __nv_bfloat16* __restrict__ Oh, __nv_bfloat16* __restrict__ Ol)
{
    __shared__ float xs[DD];
    __shared__ float red[8];
    int row = blockIdx.x;
    int tid = threadIdx.x;
    const float* a = A + (size_t)row*DD;
    const float* r = R + (size_t)row*DD;

    float lsum = 0.f;
    for (int i = tid; i < DD; i += 256) {
        float x = a[i] + r[i];
        xs[i] = x;
        lsum += x;
    }
    #pragma unroll
    for (int off = 16; off; off >>= 1) lsum += __shfl_xor_sync(0xffffffffu, lsum, off);
    if ((tid & 31) == 0) red[tid >> 5] = lsum;
    __syncthreads();
    float tot = 0.f;
    #pragma unroll
    for (int w = 0; w < 8; w++) tot += red[w];
    float mu = tot * (1.f / DD);
    __syncthreads();

    float lsq = 0.f;
    for (int i = tid; i < DD; i += 256) {
        float d = xs[i] - mu;
        lsq += d * d;
    }
    #pragma unroll
    for (int off = 16; off; off >>= 1) lsq += __shfl_xor_sync(0xffffffffu, lsq, off);
    if ((tid & 31) == 0) red[tid >> 5] = lsq;
    __syncthreads();
    float vt = 0.f;
    #pragma unroll
    for (int w = 0; w < 8; w++) vt += red[w];
    float var = vt * (1.f / DD);
    float inv = 1.f / sqrtf(var + 1e-5f);

    for (int i = tid; i < DD; i += 256) {
        float v = gamma[i] * (xs[i] - mu) * inv + beta[i];
        Out[(size_t)row*DD + i] = v;
        if (Oh){
            __nv_bfloat16 h = __float2bfloat16(v);
            Oh[(size_t)row*DD + i] = h;
            Ol[(size_t)row*DD + i] = __float2bfloat16(v - __bfloat162float(h));
        }
    }
}

// ---------------- launch ----------------------------------------------------
extern "C" void kernel_launch(void* const* d_in, const int* in_sizes, int n_in,
                              void* d_out, int out_size)
{
    const float* x    = (const float*)d_in[0];
    const int*   mask = (const int*)  d_in[1];
    const float* Wq = (const float*)d_in[2];  const float* bq = (const float*)d_in[3];
    const float* Wk = (const float*)d_in[4];  const float* bk = (const float*)d_in[5];
    const float* Wv = (const float*)d_in[6];  const float* bv = (const float*)d_in[7];
    const float* Wo = (const float*)d_in[8];  const float* bo = (const float*)d_in[9];
    const float* rel_bias = (const float*)d_in[10];
    const float* ln1g = (const float*)d_in[11]; const float* ln1b = (const float*)d_in[12];
    const float* W1 = (const float*)d_in[13]; const float* b1 = (const float*)d_in[14];
    const float* W2 = (const float*)d_in[15]; const float* b2 = (const float*)d_in[16];
    const float* ln2g = (const float*)d_in[17]; const float* ln2b = (const float*)d_in[18];
    float* out = (float*)d_out;

    float *tmp, *h, *btab;
    cudaGetSymbolAddress((void**)&tmp,  g_tmp);
    cudaGetSymbolAddress((void**)&h,    g_h);
    cudaGetSymbolAddress((void**)&btab, g_btab);

    __nv_bfloat16 *xh,*xl, *qh,*ql, *kh,*kl, *vh,*vl, *ath,*atl, *hh,*hl, *fh,*fl;
    __nv_bfloat16 *wqh,*wql,*wkh,*wkl,*wvh,*wvl,*woh,*wol,*w1h,*w1l,*w2h,*w2l;
    cudaGetSymbolAddress((void**)&xh,  g_xh);  cudaGetSymbolAddress((void**)&xl,  g_xl);
    cudaGetSymbolAddress((void**)&qh,  g_qh);  cudaGetSymbolAddress((void**)&ql,  g_ql);
    cudaGetSymbolAddress((void**)&kh,  g_kbh); cudaGetSymbolAddress((void**)&kl,  g_kbl);
    cudaGetSymbolAddress((void**)&vh,  g_vbh); cudaGetSymbolAddress((void**)&vl,  g_vbl);
    cudaGetSymbolAddress((void**)&ath, g_ath); cudaGetSymbolAddress((void**)&atl, g_atl);
    cudaGetSymbolAddress((void**)&hh,  g_hh);  cudaGetSymbolAddress((void**)&hl,  g_hl);
    cudaGetSymbolAddress((void**)&fh,  g_fh);  cudaGetSymbolAddress((void**)&fl,  g_fl);
    cudaGetSymbolAddress((void**)&wqh, g_wqh); cudaGetSymbolAddress((void**)&wql, g_wql);
    cudaGetSymbolAddress((void**)&wkh, g_wkh); cudaGetSymbolAddress((void**)&wkl, g_wkl);
    cudaGetSymbolAddress((void**)&wvh, g_wvh); cudaGetSymbolAddress((void**)&wvl, g_wvl);
    cudaGetSymbolAddress((void**)&woh, g_woh); cudaGetSymbolAddress((void**)&wol, g_wol);
    cudaGetSymbolAddress((void**)&w1h, g_w1h); cudaGetSymbolAddress((void**)&w1l, g_w1l);
    cudaGetSymbolAddress((void**)&w2h, g_w2h); cudaGetSymbolAddress((void**)&w2l, g_w2l);

    cudaFuncSetAttribute(tcgemm,
                         cudaFuncAttributeMaxDynamicSharedMemorySize, GSMEM);
    cudaFuncSetAttribute(attn_tc,
                         cudaFuncAttributeMaxDynamicSharedMemorySize, AT_SMEM);

    // 1. relative bias table + input split + weight transpose/splits
    bias_table_kernel<<<(2*SS - 1 + 255)/256, 256>>>(rel_bias, btab);
    split_kernel<<<(MR*DD/4 + 255)/256, 256>>>((const float4*)x, xh, xl, MR*DD/4);
    dim3 tb(32, 8);
    transpose_split<<<dim3(DD/32, DD/32), tb>>>(Wq, wqh, wql, DD, DD);
    transpose_split<<<dim3(DD/32, DD/32), tb>>>(Wk, wkh, wkl, DD, DD);
    transpose_split<<<dim3(DD/32, DD/32), tb>>>(Wv, wvh, wvl, DD, DD);
    transpose_split<<<dim3(DD/32, DD/32), tb>>>(Wo, woh, wol, DD, DD);
    transpose_split<<<dim3(FF/32, DD/32), tb>>>(W1, w1h, w1l, DD, FF);
    transpose_split<<<dim3(DD/32, FF/32), tb>>>(W2, w2h, w2l, FF, DD);

    // 2. Q/K/V projections -> bf16 hi/lo directly
    dim3 gproj(DD/128, MR/128);
    tcgemm<<<gproj, 256, GSMEM>>>(xh, xl, wqh, wql, bq, nullptr, qh, ql, MR, DD, DD, 0);
    tcgemm<<<gproj, 256, GSMEM>>>(xh, xl, wkh, wkl, bk, nullptr, kh, kl, MR, DD, DD, 0);
    tcgemm<<<gproj, 256, GSMEM>>>(xh, xl, wvh, wvl, bv, nullptr, vh, vl, MR, DD, DD, 0);

    // 3. tensor-core flash attention -> ath/atl
    attn_tc<<<dim3(SS/128, NG), 256, AT_SMEM>>>(qh, ql, kh, kl, vh, vl,
                                                mask, btab, ath, atl);

    // 4. output projection (fp32 out for LN1)
    tcgemm<<<gproj, 256, GSMEM>>>(ath, atl, woh, wol, bo, tmp, nullptr, nullptr,
                                  MR, DD, DD, 0);

    // 5. LN1 -> h fp32 + hh/hl
    ln_kernel<<<MR, 256>>>(tmp, x, ln1g, ln1b, h, hh, hl);

    // 6. FFN: W1+ReLU -> fh/fl directly; W2 -> fp32 tmp
    dim3 gff1(FF/128, MR/128);
    tcgemm<<<gff1, 256, GSMEM>>>(hh, hl, w1h, w1l, b1, nullptr, fh, fl, MR, FF, DD, 1);
    dim3 gff2(DD/128, MR/128);
    tcgemm<<<gff2, 256, GSMEM>>>(fh, fl, w2h, w2l, b2, tmp, nullptr, nullptr,
                                 MR, DD, FF, 0);

    // 7. LN2 -> out
    ln_kernel<<<MR, 256>>>(tmp, h, ln2g, ln2b, out, nullptr, nullptr);
}

// round 5
// speedup vs baseline: 2.7980x; 1.0199x over previous
#include <cuda_runtime.h>
#include <cuda_bf16.h>
#include <math.h>
#include <stdint.h>

#define BB 4
#define SS 1024
#define DD 1024
#define HH 16
#define FF 4096
#define DHD 64
#define NG (BB*HH)
#define MR (BB*SS)

// ---------------- scratch (static device globals; no allocation) -------------
__device__ float g_tmp[MR*DD];
__device__ float g_h[MR*DD];
__device__ float g_btab[(2*SS-1)*HH];

// bf16 hi/lo activations
__device__ __nv_bfloat16 g_xh[MR*DD],  g_xl[MR*DD];
__device__ __nv_bfloat16 g_qh[MR*DD],  g_ql[MR*DD];
__device__ __nv_bfloat16 g_kbh[MR*DD], g_kbl[MR*DD];
__device__ __nv_bfloat16 g_vbh[MR*DD], g_vbl[MR*DD];
__device__ __nv_bfloat16 g_ath[MR*DD], g_atl[MR*DD];
__device__ __nv_bfloat16 g_hh[MR*DD],  g_hl[MR*DD];
__device__ __nv_bfloat16 g_fh[(size_t)MR*FF], g_fl[(size_t)MR*FF];
// bf16 hi/lo transposed weights [N,K]
__device__ __nv_bfloat16 g_wqh[DD*DD], g_wql[DD*DD];
__device__ __nv_bfloat16 g_wkh[DD*DD], g_wkl[DD*DD];
__device__ __nv_bfloat16 g_wvh[DD*DD], g_wvl[DD*DD];
__device__ __nv_bfloat16 g_woh[DD*DD], g_wol[DD*DD];
__device__ __nv_bfloat16 g_w1h[(size_t)DD*FF], g_w1l[(size_t)DD*FF];
__device__ __nv_bfloat16 g_w2h[(size_t)FF*DD], g_w2l[(size_t)FF*DD];

// ---------------- PTX helpers ------------------------------------------------
#define SWZ(o) ((o) ^ (((o) >> 3) & 0x70))

__device__ __forceinline__ uint32_t s2u(const void* p){
    uint32_t a;
    asm("{ .reg .u64 t; cvta.to.shared.u64 t, %1; cvt.u32.u64 %0, t; }"
        : "=r"(a) : "l"(p));
    return a;
}
__device__ __forceinline__ void cp16(uint32_t d, const void* s){
    asm volatile("cp.async.cg.shared.global [%0], [%1], 16;" :: "r"(d), "l"(s));
}
__device__ __forceinline__ void ldm4(uint32_t* r, uint32_t a){
    asm volatile("ldmatrix.sync.aligned.m8n8.x4.shared.b16 {%0,%1,%2,%3}, [%4];"
        : "=r"(r[0]), "=r"(r[1]), "=r"(r[2]), "=r"(r[3]) : "r"(a));
}
__device__ __forceinline__ void ldm4t(uint32_t* r, uint32_t a){
    asm volatile("ldmatrix.sync.aligned.m8n8.x4.trans.shared.b16 {%0,%1,%2,%3}, [%4];"
        : "=r"(r[0]), "=r"(r[1]), "=r"(r[2]), "=r"(r[3]) : "r"(a));
}
__device__ __forceinline__ void mma16816(float* c, const uint32_t* a,
                                         uint32_t b0, uint32_t b1){
    asm volatile("mma.sync.aligned.m16n8k16.row.col.f32.bf16.bf16.f32 "
        "{%0,%1,%2,%3}, {%4,%5,%6,%7}, {%8,%9}, {%0,%1,%2,%3};"
        : "+f"(c[0]), "+f"(c[1]), "+f"(c[2]), "+f"(c[3])
        : "r"(a[0]), "r"(a[1]), "r"(a[2]), "r"(a[3]), "r"(b0), "r"(b1));
}
__device__ __forceinline__ uint32_t bf2u(__nv_bfloat162 v){
    return *(uint32_t*)&v;
}

// ---------------- relative-position bias table ------------------------------
__global__ void bias_table_kernel(const float* __restrict__ rel_bias,
                                  float* __restrict__ tab)
{
    int r = blockIdx.x * blockDim.x + threadIdx.x;
    if (r >= 2*SS - 1) return;
    int rel = r - (SS - 1);
    int n = -rel;
    int ret = (n < 0) ? 16 : 0;
    int na = n < 0 ? -n : n;
    int bucket;
    if (na < 8) {
        bucket = ret + na;
    } else {
        double v = log((double)na / 8.0) / log(16.0) * 8.0;
        int vi = 8 + (int)v;
        if (vi > 15) vi = 15;
        bucket = ret + vi;
    }
    #pragma unroll
    for (int h = 0; h < HH; h++) tab[r*HH + h] = rel_bias[bucket*HH + h];
}

// ---------------- fp32 -> bf16 hi/lo split ----------------------------------
__global__ __launch_bounds__(256)
void split_kernel(const float4* __restrict__ in, __nv_bfloat16* __restrict__ oh,
                  __nv_bfloat16* __restrict__ ol, int n4)
{
    int i = blockIdx.x * 256 + threadIdx.x;
    if (i >= n4) return;
    float4 v = in[i];
    float vs[4] = {v.x, v.y, v.z, v.w};
    __nv_bfloat16 h4[4], l4[4];
    #pragma unroll
    for (int j = 0; j < 4; j++){
        __nv_bfloat16 h = __float2bfloat16(vs[j]);
        h4[j] = h;
        l4[j] = __float2bfloat16(vs[j] - __bfloat162float(h));
    }
    *(ushort4*)(oh + (size_t)i*4) = *(ushort4*)h4;
    *(ushort4*)(ol + (size_t)i*4) = *(ushort4*)l4;
}

// ---------------- transpose + split: in[K,N] -> out[N,K] hi/lo --------------
__global__ __launch_bounds__(256)
void transpose_split(const float* __restrict__ in, __nv_bfloat16* __restrict__ oh,
                     __nv_bfloat16* __restrict__ ol, int K, int N)
{
    __shared__ float t[32][33];
    int n0 = blockIdx.x*32, k0 = blockIdx.y*32;
    int tx = threadIdx.x, ty = threadIdx.y;
    #pragma unroll
    for (int i = 0; i < 32; i += 8)
        t[ty+i][tx] = in[(size_t)(k0+ty+i)*N + n0+tx];
    __syncthreads();
    #pragma unroll
    for (int i = 0; i < 32; i += 8){
        float v = t[tx][ty+i];
        __nv_bfloat16 h = __float2bfloat16(v);
        __nv_bfloat16 l = __float2bfloat16(v - __bfloat162float(h));
        oh[(size_t)(n0+ty+i)*K + k0+tx] = h;
        ol[(size_t)(n0+ty+i)*K + k0+tx] = l;
    }
}

// ---------------- split-bf16 tensor GEMM via mma.sync ------------------------
// C[M,N] = A[M,K] @ Bt[N,K]^T + bias. CTA tile 256x128, warp tile 64x64,
// BK=64, double-buffered cp.async. Optional fp32 and/or bf16 hi/lo outputs.
// smem stage: Ah 32K | Al 32K | Bh 16K | Bl 16K = 96KB; 2 stages = 192KB.
#define GSMEM (2*98304)
__global__ __launch_bounds__(256, 1)
void tcgemm(const __nv_bfloat16* __restrict__ Ah, const __nv_bfloat16* __restrict__ Al,
            const __nv_bfloat16* __restrict__ Bh, const __nv_bfloat16* __restrict__ Bl,
            const float* __restrict__ bias, float* __restrict__ C,
            __nv_bfloat16* __restrict__ Oh, __nv_bfloat16* __restrict__ Ol,
            int M, int N, int K, int relu)
{
    extern __shared__ __align__(1024) char smraw[];
    uint32_t sb = s2u(smraw);
    const int tid = threadIdx.x, wid = tid >> 5, lane = tid & 31;
    const int m0 = blockIdx.y*256, n0 = blockIdx.x*128;
    const int wm = (wid >> 1) * 64;      // 4 warp rows
    const int wn = (wid & 1) * 64;       // 2 warp cols

    const int KT = K >> 6;
    const __nv_bfloat16* pAh = Ah + (size_t)m0*K;
    const __nv_bfloat16* pAl = Al + (size_t)m0*K;
    const __nv_bfloat16* pBh = Bh + (size_t)n0*K;
    const __nv_bfloat16* pBl = Bl + (size_t)n0*K;

    // stage offsets
    const uint32_t oAh = 0, oAl = 32768, oBh = 65536, oBl = 81920;
    const int arow = tid >> 3, acol = tid & 7;   // A: 256 rows x 8 chunks

    // prologue: k-tile 0 -> stage 0
    {
        #pragma unroll
        for (int i = 0; i < 8; i++){
            int r = arow + 32*i;
            cp16(sb + oAh + SWZ(r*128 + acol*16), pAh + (size_t)r*K + acol*8);
            cp16(sb + oAl + SWZ(r*128 + acol*16), pAl + (size_t)r*K + acol*8);
        }
        #pragma unroll
        for (int i = 0; i < 4; i++){
            int r = arow + 32*i;
            cp16(sb + oBh + SWZ(r*128 + acol*16), pBh + (size_t)r*K + acol*8);
            cp16(sb + oBl + SWZ(r*128 + acol*16), pBl + (size_t)r*K + acol*8);
        }
        asm volatile("cp.async.commit_group;" ::: "memory");
    }

    float acc[4][8][4];
    #pragma unroll
    for (int a = 0; a < 4; a++)
        #pragma unroll
        for (int b = 0; b < 8; b++)
            #pragma unroll
            for (int c = 0; c < 4; c++) acc[a][b][c] = 0.f;

    const int lrow = (lane & 7) + ((lane >> 3) & 1) * 8;
    const int koff = ((lane >> 4) & 1) * 16;   // byte sub-offset along k

    for (int kt = 0; kt < KT; kt++){
        asm volatile("cp.async.wait_group 0;" ::: "memory");
        __syncthreads();

        uint32_t bufs = sb + (kt & 1) * 98304;

        if (kt + 1 < KT){
            uint32_t nbb = sb + ((kt + 1) & 1) * 98304;
            int k0 = (kt + 1) << 6;
            #pragma unroll
            for (int i = 0; i < 8; i++){
                int r = arow + 32*i;
                cp16(nbb + oAh + SWZ(r*128 + acol*16), pAh + (size_t)r*K + k0 + acol*8);
                cp16(nbb + oAl + SWZ(r*128 + acol*16), pAl + (size_t)r*K + k0 + acol*8);
            }
            #pragma unroll
            for (int i = 0; i < 4; i++){
                int r = arow + 32*i;
                cp16(nbb + oBh + SWZ(r*128 + acol*16), pBh + (size_t)r*K + k0 + acol*8);
                cp16(nbb + oBl + SWZ(r*128 + acol*16), pBl + (size_t)r*K + k0 + acol*8);
            }
            asm volatile("cp.async.commit_group;" ::: "memory");
        }

        #pragma unroll
        for (int ks = 0; ks < 4; ks++){
            const int kb = ks*32 + koff;
            uint32_t ah[4][4], al[4][4];
            #pragma unroll
            for (int mb = 0; mb < 4; mb++){
                int r = wm + mb*16 + lrow;
                ldm4(ah[mb], bufs + oAh + SWZ(r*128 + kb));
                ldm4(al[mb], bufs + oAl + SWZ(r*128 + kb));
            }
            #pragma unroll
            for (int nb = 0; nb < 4; nb++){
                uint32_t bh4[4], bl4[4];
                int r = wn + nb*16 + lrow;
                ldm4(bh4, bufs + oBh + SWZ(r*128 + kb));
                ldm4(bl4, bufs + oBl + SWZ(r*128 + kb));
                #pragma unroll
                for (int mb = 0; mb < 4; mb++){
                    mma16816(acc[mb][2*nb+0], ah[mb], bh4[0], bh4[2]);
                    mma16816(acc[mb][2*nb+0], ah[mb], bl4[0], bl4[2]);
                    mma16816(acc[mb][2*nb+0], al[mb], bh4[0], bh4[2]);
                    mma16816(acc[mb][2*nb+1], ah[mb], bh4[1], bh4[3]);
                    mma16816(acc[mb][2*nb+1], ah[mb], bl4[1], bl4[3]);
                    mma16816(acc[mb][2*nb+1], al[mb], bh4[1], bh4[3]);
                }
            }
        }
        // NOTE: no bottom __syncthreads needed — next iteration's top
        // wait_group+__syncthreads orders prefetch writes after all reads.
    }

    const int erow = lane >> 2, ecol = (lane & 3) * 2;
    #pragma unroll
    for (int mb = 0; mb < 4; mb++){
        #pragma unroll
        for (int nf = 0; nf < 8; nf++){
            int r = m0 + wm + mb*16 + erow;
            int cc = n0 + wn + nf*8 + ecol;
            float b0 = bias[cc], b1 = bias[cc+1];
            float2 v0 = make_float2(acc[mb][nf][0] + b0, acc[mb][nf][1] + b1);
            float2 v1 = make_float2(acc[mb][nf][2] + b0, acc[mb][nf][3] + b1);
            if (relu){
                v0.x = fmaxf(v0.x, 0.f); v0.y = fmaxf(v0.y, 0.f);
                v1.x = fmaxf(v1.x, 0.f); v1.y = fmaxf(v1.y, 0.f);
            }
            if (C){
                *(float2*)(C + (size_t)r*N + cc)     = v0;
                *(float2*)(C + (size_t)(r+8)*N + cc) = v1;
            }
            if (Oh){
                __nv_bfloat162 h0 = __floats2bfloat162_rn(v0.x, v0.y);
                __nv_bfloat162 l0 = __floats2bfloat162_rn(
                    v0.x - __bfloat162float(h0.x), v0.y - __bfloat162float(h0.y));
                __nv_bfloat162 h1 = __floats2bfloat162_rn(v1.x, v1.y);
                __nv_bfloat162 l1 = __floats2bfloat162_rn(
                    v1.x - __bfloat162float(h1.x), v1.y - __bfloat162float(h1.y));
                *(__nv_bfloat162*)(Oh + (size_t)r*N + cc)     = h0;
                *(__nv_bfloat162*)(Ol + (size_t)r*N + cc)     = l0;
                *(__nv_bfloat162*)(Oh + (size_t)(r+8)*N + cc) = h1;
                *(__nv_bfloat162*)(Ol + (size_t)(r+8)*N + cc) = l1;
            }
        }
    }
}

// ---------------- tensor-core flash attention --------------------------------
#define AT_SMEM 99328
__global__ __launch_bounds__(256, 1)
void attn_tc(const __nv_bfloat16* __restrict__ Qh_, const __nv_bfloat16* __restrict__ Ql_,
             const __nv_bfloat16* __restrict__ Kh_, const __nv_bfloat16* __restrict__ Kl_,
             const __nv_bfloat16* __restrict__ Vh_, const __nv_bfloat16* __restrict__ Vl_,
             const int* __restrict__ mask, const float* __restrict__ btab,
             __nv_bfloat16* __restrict__ Oh, __nv_bfloat16* __restrict__ Ol)
{
    extern __shared__ __align__(1024) char smraw[];
    uint32_t sb = s2u(smraw);
    const int tid = threadIdx.x, wid = tid >> 5, lane = tid & 31;
    const int g = blockIdx.y, q0 = blockIdx.x * 128;
    const int hh_ = g & (HH-1), bb = g >> 4;
    const int wq = wid * 16;
    const int lr = lane >> 2, lq = lane & 3;
    const int lrow = (lane & 7) + ((lane >> 3) & 1) * 8;
    const int koff = ((lane >> 4) & 1) * 16;

    const uint32_t oQh = 0, oQl = 16384, oKV = 32768;
    float* sbias = (float*)(smraw + 98304);
    float* spen  = (float*)(smraw + 99072);

    const size_t gb = (size_t)g * SS * DHD;

    {
        const __nv_bfloat16* qh = Qh_ + gb + (size_t)q0 * DHD;
        const __nv_bfloat16* ql = Ql_ + gb + (size_t)q0 * DHD;
        #pragma unroll
        for (int i = 0; i < 4; i++){
            int c = tid + 256*i, row = c >> 3, col = c & 7;
            cp16(sb + oQh + SWZ(row*128 + col*16), qh + (size_t)row*64 + col*8);
            cp16(sb + oQl + SWZ(row*128 + col*16), ql + (size_t)row*64 + col*8);
        }
    }
    {
        uint32_t kvb = sb + oKV;
        const __nv_bfloat16* srcs[4] = { Kh_ + gb, Kl_ + gb, Vh_ + gb, Vl_ + gb };
        #pragma unroll
        for (int t = 0; t < 4; t++)
            #pragma unroll
            for (int i = 0; i < 2; i++){
                int c = tid + 256*i, row = c >> 3, col = c & 7;
                cp16(kvb + t*8192 + SWZ(row*128 + col*16), srcs[t] + (size_t)row*64 + col*8);
            }
    }
    asm volatile("cp.async.commit_group;" ::: "memory");

    float m0v = -1e30f, m1v = -1e30f, l0 = 0.f, l1 = 0.f;
    float o[8][4];
    #pragma unroll
    for (int i = 0; i < 8; i++)
        #pragma unroll
        for (int j = 0; j < 4; j++) o[i][j] = 0.f;

    for (int ch = 0; ch < 16; ch++){
        const int k0 = ch * 64;
        if (tid < 192){
            int idx = tid + q0 - k0 - 63 + (SS - 1);
            if (idx < 0) idx = 0;
            if (idx > 2*SS - 2) idx = 2*SS - 2;
            sbias[tid] = btab[idx*HH + hh_];
        }
        if (tid < 64) spen[tid] = (mask[bb*SS + k0 + tid] == 0) ? -1e30f : 0.f;

        if (ch + 1 < 16){
            uint32_t kvb = sb + oKV + ((ch+1)&1)*32768;
            const size_t off = gb + (size_t)(k0 + 64)*64;
            const __nv_bfloat16* srcs[4] = { Kh_+off, Kl_+off, Vh_+off, Vl_+off };
            #pragma unroll
            for (int t = 0; t < 4; t++)
                #pragma unroll
                for (int i = 0; i < 2; i++){
                    int c = tid + 256*i, row = c >> 3, col = c & 7;
                    cp16(kvb + t*8192 + SWZ(row*128 + col*16), srcs[t] + (size_t)row*64 + col*8);
                }
            asm volatile("cp.async.commit_group;" ::: "memory");
            asm volatile("cp.async.wait_group 1;" ::: "memory");
        } else {
            asm volatile("cp.async.wait_group 0;" ::: "memory");
        }
        __syncthreads();

        const uint32_t kvb = sb + oKV + (ch&1)*32768;

        float s_[8][4];
        #pragma unroll
        for (int i = 0; i < 8; i++)
            #pragma unroll
            for (int j = 0; j < 4; j++) s_[i][j] = 0.f;

        #pragma unroll
        for (int kb = 0; kb < 4; kb++){
            uint32_t qa[4], qb[4];
            ldm4(qa, sb + oQh + SWZ((wq+lrow)*128 + kb*32 + koff));
            ldm4(qb, sb + oQl + SWZ((wq+lrow)*128 + kb*32 + koff));
            #pragma unroll
            for (int j = 0; j < 4; j++){
                uint32_t kh4[4], kl4[4];
                ldm4(kh4, kvb +        SWZ((j*16+lrow)*128 + kb*32 + koff));
                ldm4(kl4, kvb + 8192 + SWZ((j*16+lrow)*128 + kb*32 + koff));
                mma16816(s_[2*j],   qa, kh4[0], kh4[2]);
                mma16816(s_[2*j],   qa, kl4[0], kl4[2]);
                mma16816(s_[2*j],   qb, kh4[0], kh4[2]);
                mma16816(s_[2*j+1], qa, kh4[1], kh4[3]);
                mma16816(s_[2*j+1], qa, kl4[1], kl4[3]);
                mma16816(s_[2*j+1], qb, kh4[1], kh4[3]);
            }
        }

        const int r0 = wq + lr, r1 = r0 + 8;
        #pragma unroll
        for (int nf = 0; nf < 8; nf++){
            int c0 = nf*8 + lq*2;
            s_[nf][0] += sbias[r0 - c0 + 63]     + spen[c0];
            s_[nf][1] += sbias[r0 - c0 + 62]     + spen[c0+1];
            s_[nf][2] += sbias[r1 - c0 + 63]     + spen[c0];
            s_[nf][3] += sbias[r1 - c0 + 62]     + spen[c0+1];
        }

        float mx0 = -1e30f, mx1 = -1e30f;
        #pragma unroll
        for (int nf = 0; nf < 8; nf++){
            mx0 = fmaxf(mx0, fmaxf(s_[nf][0], s_[nf][1]));
            mx1 = fmaxf(mx1, fmaxf(s_[nf][2], s_[nf][3]));
        }
        #pragma unroll
        for (int off = 1; off < 4; off <<= 1){
            mx0 = fmaxf(mx0, __shfl_xor_sync(0xffffffffu, mx0, off));
            mx1 = fmaxf(mx1, __shfl_xor_sync(0xffffffffu, mx1, off));
        }
        float mn0 = fmaxf(m0v, mx0), mn1 = fmaxf(m1v, mx1);
        float al0 = __expf(m0v - mn0), al1 = __expf(m1v - mn1);
        float sum0 = 0.f, sum1 = 0.f;
        #pragma unroll
        for (int nf = 0; nf < 8; nf++){
            s_[nf][0] = __expf(s_[nf][0] - mn0); sum0 += s_[nf][0];
            s_[nf][1] = __expf(s_[nf][1] - mn0); sum0 += s_[nf][1];
            s_[nf][2] = __expf(s_[nf][2] - mn1); sum1 += s_[nf][2];
            s_[nf][3] = __expf(s_[nf][3] - mn1); sum1 += s_[nf][3];
        }
        #pragma unroll
        for (int off = 1; off < 4; off <<= 1){
            sum0 += __shfl_xor_sync(0xffffffffu, sum0, off);
            sum1 += __shfl_xor_sync(0xffffffffu, sum1, off);
        }
        l0 = l0*al0 + sum0; l1 = l1*al1 + sum1;
        m0v = mn0; m1v = mn1;
        #pragma unroll
        for (int nf = 0; nf < 8; nf++){
            o[nf][0] *= al0; o[nf][1] *= al0;
            o[nf][2] *= al1; o[nf][3] *= al1;
        }

        #pragma unroll
        for (int kb = 0; kb < 4; kb++){
            uint32_t ah[4], alr[4];
            {
                __nv_bfloat162 t0 = __floats2bfloat162_rn(s_[2*kb][0],   s_[2*kb][1]);
                __nv_bfloat162 t1 = __floats2bfloat162_rn(s_[2*kb][2],   s_[2*kb][3]);
                __nv_bfloat162 t2 = __floats2bfloat162_rn(s_[2*kb+1][0], s_[2*kb+1][1]);
                __nv_bfloat162 t3 = __floats2bfloat162_rn(s_[2*kb+1][2], s_[2*kb+1][3]);
                ah[0] = bf2u(t0); ah[1] = bf2u(t1); ah[2] = bf2u(t2); ah[3] = bf2u(t3);
                alr[0] = bf2u(__floats2bfloat162_rn(
                    s_[2*kb][0]   - __bfloat162float(t0.x), s_[2*kb][1]   - __bfloat162float(t0.y)));
                alr[1] = bf2u(__floats2bfloat162_rn(
                    s_[2*kb][2]   - __bfloat162float(t1.x), s_[2*kb][3]   - __bfloat162float(t1.y)));
                alr[2] = bf2u(__floats2bfloat162_rn(
                    s_[2*kb+1][0] - __bfloat162float(t2.x), s_[2*kb+1][1] - __bfloat162float(t2.y)));
                alr[3] = bf2u(__floats2bfloat162_rn(
                    s_[2*kb+1][2] - __bfloat162float(t3.x), s_[2*kb+1][3] - __bfloat162float(t3.y)));
            }
            #pragma unroll
            for (int j = 0; j < 4; j++){
                uint32_t vh4[4], vl4[4];
                ldm4t(vh4, kvb + 16384 + SWZ((kb*16+lrow)*128 + j*32 + koff));
                ldm4t(vl4, kvb + 24576 + SWZ((kb*16+lrow)*128 + j*32 + koff));
                mma16816(o[2*j],   ah,  vh4[0], vh4[1]);
                mma16816(o[2*j+1], ah,  vh4[2], vh4[3]);
                mma16816(o[2*j],   ah,  vl4[0], vl4[1]);
                mma16816(o[2*j+1], ah,  vl4[2], vl4[3]);
                mma16816(o[2*j],   alr, vh4[0], vh4[1]);
                mma16816(o[2*j+1], alr, vh4[2], vh4[3]);
            }
        }
        __syncthreads();
    }

    const float inv0 = 1.f / l0, inv1 = 1.f / l1;
    const int tq0 = q0 + wq + lr, tq1 = tq0 + 8;
    const size_t b0 = (size_t)g*65536 + (size_t)tq0*64;
    const size_t b1 = (size_t)g*65536 + (size_t)tq1*64;
    #pragma unroll
    for (int nf = 0; nf < 8; nf++){
        int d0 = nf*8 + lq*2;
        float v0 = o[nf][0]*inv0, v1 = o[nf][1]*inv0;
        float w0 = o[nf][2]*inv1, w1 = o[nf][3]*inv1;
        __nv_bfloat162 hv = __floats2bfloat162_rn(v0, v1);
        __nv_bfloat162 lv = __floats2bfloat162_rn(
            v0 - __bfloat162float(hv.x), v1 - __bfloat162float(hv.y));
        __nv_bfloat162 hw = __floats2bfloat162_rn(w0, w1);
        __nv_bfloat162 lw = __floats2bfloat162_rn(
            w0 - __bfloat162float(hw.x), w1 - __bfloat162float(hw.y));
        *(__nv_bfloat162*)(Oh + b0 + d0) = hv;
        *(__nv_bfloat162*)(Ol + b0 + d0) = lv;
        *(__nv_bfloat162*)(Oh + b1 + d0) = hw;
        *(__nv_bfloat162*)(Ol + b1 + d0) = lw;
    }
}

// ---------------- LayerNorm with residual: Out = LN(A + R) (+opt hi/lo) -----
__global__ __launch_bounds__(256)
void ln_kernel(const float* __restrict__ A, const float* __restrict__ R,
               const float* __restrict__ gamma, const float* __restrict__ beta,
               float* __restrict__ Out,
               __nv_bfloat16* __restrict__ Oh, __nv_bfloat16* __restrict__ Ol)
{
    __shared__ float xs[DD];
    __shared__ float red[8];
    int row = blockIdx.x;
    int tid = threadIdx.x;
    const float* a = A + (size_t)row*DD;
    const float* r = R + (size_t)row*DD;

    float lsum = 0.f;
    for (int i = tid; i < DD; i += 256) {
        float x = a[i] + r[i];
        xs[i] = x;
        lsum += x;
    }
    #pragma unroll
    for (int off = 16; off; off >>= 1) lsum += __shfl_xor_sync(0xffffffffu, lsum, off);
    if ((tid & 31) == 0) red[tid >> 5] = lsum;
    __syncthreads();
    float tot = 0.f;
    #pragma unroll
    for (int w = 0; w < 8; w++) tot += red[w];
    float mu = tot * (1.f / DD);
    __syncthreads();

    float lsq = 0.f;
    for (int i = tid; i < DD; i += 256) {
        float d = xs[i] - mu;
        lsq += d * d;
    }
    #pragma unroll
    for (int off = 16; off; off >>= 1) lsq += __shfl_xor_sync(0xffffffffu, lsq, off);
    if ((tid & 31) == 0) red[tid >> 5] = lsq;
    __syncthreads();
    float vt = 0.f;
    #pragma unroll
    for (int w = 0; w < 8; w++) vt += red[w];
    float var = vt * (1.f / DD);
    float inv = 1.f / sqrtf(var + 1e-5f);

    for (int i = tid; i < DD; i += 256) {
        float v = gamma[i] * (xs[i] - mu) * inv + beta[i];
        Out[(size_t)row*DD + i] = v;
        if (Oh){
            __nv_bfloat16 h = __float2bfloat16(v);
            Oh[(size_t)row*DD + i] = h;
            Ol[(size_t)row*DD + i] = __float2bfloat16(v - __bfloat162float(h));
        }
    }
}

// ---------------- launch ----------------------------------------------------
extern "C" void kernel_launch(void* const* d_in, const int* in_sizes, int n_in,
                              void* d_out, int out_size)
{
    const float* x    = (const float*)d_in[0];
    const int*   mask = (const int*)  d_in[1];
    const float* Wq = (const float*)d_in[2];  const float* bq = (const float*)d_in[3];
    const float* Wk = (const float*)d_in[4];  const float* bk = (const float*)d_in[5];
    const float* Wv = (const float*)d_in[6];  const float* bv = (const float*)d_in[7];
    const float* Wo = (const float*)d_in[8];  const float* bo = (const float*)d_in[9];
    const float* rel_bias = (const float*)d_in[10];
    const float* ln1g = (const float*)d_in[11]; const float* ln1b = (const float*)d_in[12];
    const float* W1 = (const float*)d_in[13]; const float* b1 = (const float*)d_in[14];
    const float* W2 = (const float*)d_in[15]; const float* b2 = (const float*)d_in[16];
    const float* ln2g = (const float*)d_in[17]; const float* ln2b = (const float*)d_in[18];
    float* out = (float*)d_out;

    float *tmp, *h, *btab;
    cudaGetSymbolAddress((void**)&tmp,  g_tmp);
    cudaGetSymbolAddress((void**)&h,    g_h);
    cudaGetSymbolAddress((void**)&btab, g_btab);

    __nv_bfloat16 *xh,*xl, *qh,*ql, *kh,*kl, *vh,*vl, *ath,*atl, *hh,*hl, *fh,*fl;
    __nv_bfloat16 *wqh,*wql,*wkh,*wkl,*wvh,*wvl,*woh,*wol,*w1h,*w1l,*w2h,*w2l;
    cudaGetSymbolAddress((void**)&xh,  g_xh);  cudaGetSymbolAddress((void**)&xl,  g_xl);
    cudaGetSymbolAddress((void**)&qh,  g_qh);  cudaGetSymbolAddress((void**)&ql,  g_ql);
    cudaGetSymbolAddress((void**)&kh,  g_kbh); cudaGetSymbolAddress((void**)&kl,  g_kbl);
    cudaGetSymbolAddress((void**)&vh,  g_vbh); cudaGetSymbolAddress((void**)&vl,  g_vbl);
    cudaGetSymbolAddress((void**)&ath, g_ath); cudaGetSymbolAddress((void**)&atl, g_atl);
    cudaGetSymbolAddress((void**)&hh,  g_hh);  cudaGetSymbolAddress((void**)&hl,  g_hl);
    cudaGetSymbolAddress((void**)&fh,  g_fh);  cudaGetSymbolAddress((void**)&fl,  g_fl);
    cudaGetSymbolAddress((void**)&wqh, g_wqh); cudaGetSymbolAddress((void**)&wql, g_wql);
    cudaGetSymbolAddress((void**)&wkh, g_wkh); cudaGetSymbolAddress((void**)&wkl, g_wkl);
    cudaGetSymbolAddress((void**)&wvh, g_wvh); cudaGetSymbolAddress((void**)&wvl, g_wvl);
    cudaGetSymbolAddress((void**)&woh, g_woh); cudaGetSymbolAddress((void**)&wol, g_wol);
    cudaGetSymbolAddress((void**)&w1h, g_w1h); cudaGetSymbolAddress((void**)&w1l, g_w1l);
    cudaGetSymbolAddress((void**)&w2h, g_w2h); cudaGetSymbolAddress((void**)&w2l, g_w2l);

    cudaFuncSetAttribute(tcgemm,
                         cudaFuncAttributeMaxDynamicSharedMemorySize, GSMEM);
    cudaFuncSetAttribute(attn_tc,
                         cudaFuncAttributeMaxDynamicSharedMemorySize, AT_SMEM);

    // 1. relative bias table + input split + weight transpose/splits
    bias_table_kernel<<<(2*SS - 1 + 255)/256, 256>>>(rel_bias, btab);
    split_kernel<<<(MR*DD/4 + 255)/256, 256>>>((const float4*)x, xh, xl, MR*DD/4);
    dim3 tb(32, 8);
    transpose_split<<<dim3(DD/32, DD/32), tb>>>(Wq, wqh, wql, DD, DD);
    transpose_split<<<dim3(DD/32, DD/32), tb>>>(Wk, wkh, wkl, DD, DD);
    transpose_split<<<dim3(DD/32, DD/32), tb>>>(Wv, wvh, wvl, DD, DD);
    transpose_split<<<dim3(DD/32, DD/32), tb>>>(Wo, woh, wol, DD, DD);
    transpose_split<<<dim3(FF/32, DD/32), tb>>>(W1, w1h, w1l, DD, FF);
    transpose_split<<<dim3(DD/32, FF/32), tb>>>(W2, w2h, w2l, FF, DD);

    // 2. Q/K/V projections -> bf16 hi/lo directly
    dim3 gproj(DD/128, MR/256);
    tcgemm<<<gproj, 256, GSMEM>>>(xh, xl, wqh, wql, bq, nullptr, qh, ql, MR, DD, DD, 0);
    tcgemm<<<gproj, 256, GSMEM>>>(xh, xl, wkh, wkl, bk, nullptr, kh, kl, MR, DD, DD, 0);
    tcgemm<<<gproj, 256, GSMEM>>>(xh, xl, wvh, wvl, bv, nullptr, vh, vl, MR, DD, DD, 0);

    // 3. tensor-core flash attention -> ath/atl
    attn_tc<<<dim3(SS/128, NG), 256, AT_SMEM>>>(qh, ql, kh, kl, vh, vl,
                                                mask, btab, ath, atl);

    // 4. output projection (fp32 out for LN1)
    tcgemm<<<gproj, 256, GSMEM>>>(ath, atl, woh, wol, bo, tmp, nullptr, nullptr,
                                  MR, DD, DD, 0);

    // 5. LN1 -> h fp32 + hh/hl
    ln_kernel<<<MR, 256>>>(tmp, x, ln1g, ln1b, h, hh, hl);

    // 6. FFN: W1+ReLU -> fh/fl directly; W2 -> fp32 tmp
    dim3 gff1(FF/128, MR/256);
    tcgemm<<<gff1, 256, GSMEM>>>(hh, hl, w1h, w1l, b1, nullptr, fh, fl, MR, FF, DD, 1);
    dim3 gff2(DD/128, MR/256);
    tcgemm<<<gff2, 256, GSMEM>>>(fh, fl, w2h, w2l, b2, tmp, nullptr, nullptr,
                                 MR, DD, FF, 0);

    // 7. LN2 -> out
    ln_kernel<<<MR, 256>>>(tmp, h, ln2g, ln2b, out, nullptr, nullptr);
}

// round 7
// speedup vs baseline: 3.4198x; 1.2222x over previous
#include <cuda_runtime.h>
#include <cuda_bf16.h>
#include <cuda_fp16.h>
#include <math.h>
#include <stdint.h>

#define BB 4
#define SS 1024
#define DD 1024
#define HH 16
#define FF 4096
#define DHD 64
#define NG (BB*HH)
#define MR (BB*SS)

// ---------------- scratch (static device globals; no allocation) -------------
__device__ float g_tmp[MR*DD];
__device__ float g_h[MR*DD];
__device__ float g_btab[(2*SS-1)*HH];

// fp16 hi/lo activations (GEMM operands)
__device__ __half g_xh[MR*DD],  g_xl[MR*DD];
__device__ __half g_ath[MR*DD], g_atl[MR*DD];
__device__ __half g_hh[MR*DD],  g_hl[MR*DD];
__device__ __half g_fh[(size_t)MR*FF], g_fl[(size_t)MR*FF];
// attention operands stay bf16 hi/lo
__device__ __nv_bfloat16 g_qh[MR*DD],  g_ql[MR*DD];
__device__ __nv_bfloat16 g_kbh[MR*DD], g_kbl[MR*DD];
__device__ __nv_bfloat16 g_vbh[MR*DD], g_vbl[MR*DD];
// fp16 transposed weights [N,K]; QKV get hi/lo, Wo/W1/W2 single
__device__ __half g_wqh[DD*DD], g_wql[DD*DD];
__device__ __half g_wkh[DD*DD], g_wkl[DD*DD];
__device__ __half g_wvh[DD*DD], g_wvl[DD*DD];
__device__ __half g_woh[DD*DD];
__device__ __half g_w1h[(size_t)DD*FF];
__device__ __half g_w2h[(size_t)FF*DD];

// ---------------- PTX helpers ------------------------------------------------
#define SWZ(o) ((o) ^ (((o) >> 3) & 0x70))

__device__ __forceinline__ uint32_t s2u(const void* p){
    uint32_t a;
    asm("{ .reg .u64 t; cvta.to.shared.u64 t, %1; cvt.u32.u64 %0, t; }"
        : "=r"(a) : "l"(p));
    return a;
}
__device__ __forceinline__ void cp16(uint32_t d, const void* s){
    asm volatile("cp.async.cg.shared.global [%0], [%1], 16;" :: "r"(d), "l"(s));
}
__device__ __forceinline__ void ldm4(uint32_t* r, uint32_t a){
    asm volatile("ldmatrix.sync.aligned.m8n8.x4.shared.b16 {%0,%1,%2,%3}, [%4];"
        : "=r"(r[0]), "=r"(r[1]), "=r"(r[2]), "=r"(r[3]) : "r"(a));
}
__device__ __forceinline__ void ldm4t(uint32_t* r, uint32_t a){
    asm volatile("ldmatrix.sync.aligned.m8n8.x4.trans.shared.b16 {%0,%1,%2,%3}, [%4];"
        : "=r"(r[0]), "=r"(r[1]), "=r"(r[2]), "=r"(r[3]) : "r"(a));
}
// bf16 mma (attention)
__device__ __forceinline__ void mma_bf(float* c, const uint32_t* a,
                                       uint32_t b0, uint32_t b1){
    asm volatile("mma.sync.aligned.m16n8k16.row.col.f32.bf16.bf16.f32 "
        "{%0,%1,%2,%3}, {%4,%5,%6,%7}, {%8,%9}, {%0,%1,%2,%3};"
        : "+f"(c[0]), "+f"(c[1]), "+f"(c[2]), "+f"(c[3])
        : "r"(a[0]), "r"(a[1]), "r"(a[2]), "r"(a[3]), "r"(b0), "r"(b1));
}
// fp16 mma (GEMMs)
__device__ __forceinline__ void mma_hf(float* c, const uint32_t* a,
                                       uint32_t b0, uint32_t b1){
    asm volatile("mma.sync.aligned.m16n8k16.row.col.f32.f16.f16.f32 "
        "{%0,%1,%2,%3}, {%4,%5,%6,%7}, {%8,%9}, {%0,%1,%2,%3};"
        : "+f"(c[0]), "+f"(c[1]), "+f"(c[2]), "+f"(c[3])
        : "r"(a[0]), "r"(a[1]), "r"(a[2]), "r"(a[3]), "r"(b0), "r"(b1));
}
__device__ __forceinline__ uint32_t bf2u(__nv_bfloat162 v){ return *(uint32_t*)&v; }

__device__ __forceinline__ __half2 split_h2(float a, float b, __half2* lo){
    __half h0 = __float2half_rn(a), h1 = __float2half_rn(b);
    *lo = __halves2half2(__float2half_rn(a - __half2float(h0)),
                         __float2half_rn(b - __half2float(h1)));
    return __halves2half2(h0, h1);
}

// ---------------- relative-position bias table ------------------------------
__global__ void bias_table_kernel(const float* __restrict__ rel_bias,
                                  float* __restrict__ tab)
{
    int r = blockIdx.x * blockDim.x + threadIdx.x;
    if (r >= 2*SS - 1) return;
    int rel = r - (SS - 1);
    int n = -rel;
    int ret = (n < 0) ? 16 : 0;
    int na = n < 0 ? -n : n;
    int bucket;
    if (na < 8) {
        bucket = ret + na;
    } else {
        double v = log((double)na / 8.0) / log(16.0) * 8.0;
        int vi = 8 + (int)v;
        if (vi > 15) vi = 15;
        bucket = ret + vi;
    }
    #pragma unroll
    for (int h = 0; h < HH; h++) tab[r*HH + h] = rel_bias[bucket*HH + h];
}

// ---------------- fp32 -> fp16 hi/lo split -----------------------------------
__global__ __launch_bounds__(256)
void split_kernel(const float4* __restrict__ in, __half* __restrict__ oh,
                  __half* __restrict__ ol, int n4)
{
    int i = blockIdx.x * 256 + threadIdx.x;
    if (i >= n4) return;
    float4 v = in[i];
    __half2 l0, l1;
    __half2 h0 = split_h2(v.x, v.y, &l0);
    __half2 h1 = split_h2(v.z, v.w, &l1);
    __half2* po = (__half2*)(oh + (size_t)i*4);
    __half2* pl = (__half2*)(ol + (size_t)i*4);
    po[0] = h0; po[1] = h1;
    pl[0] = l0; pl[1] = l1;
}

// ---------------- transpose + split: in[K,N] -> out[N,K] fp16 (opt lo) ------
template<int SPLIT>
__global__ __launch_bounds__(256)
void transpose_half(const float* __restrict__ in, __half* __restrict__ oh,
                    __half* __restrict__ ol, int K, int N)
{
    __shared__ float t[32][33];
    int n0 = blockIdx.x*32, k0 = blockIdx.y*32;
    int tx = threadIdx.x, ty = threadIdx.y;
    #pragma unroll
    for (int i = 0; i < 32; i += 8)
        t[ty+i][tx] = in[(size_t)(k0+ty+i)*N + n0+tx];
    __syncthreads();
    #pragma unroll
    for (int i = 0; i < 32; i += 8){
        float v = t[tx][ty+i];
        __half h = __float2half_rn(v);
        oh[(size_t)(n0+ty+i)*K + k0+tx] = h;
        if (SPLIT)
            ol[(size_t)(n0+ty+i)*K + k0+tx] = __float2half_rn(v - __half2float(h));
    }
}

// ---------------- split-fp16 tensor GEMM via mma.sync ------------------------
// C[M,N] = A[M,K] @ Bt[N,K]^T + bias.  TERMS=3: Ah.Bh+Ah.Bl+Al.Bh (QKV).
// TERMS=2: Ah.B+Al.B (B single fp16).  CTA 256x128, warp 64x64, BK=64,
// double-buffered cp.async. Outputs: fp32 C / bf16 hi-lo / fp16 hi-lo.
#define GSM3 (2*98304)
#define GSM2 (2*81920)
template<int TERMS>
__global__ __launch_bounds__(256, 1)
void tcgemm(const __half* __restrict__ Ah, const __half* __restrict__ Al,
            const __half* __restrict__ Bh, const __half* __restrict__ Bl,
            const float* __restrict__ bias, float* __restrict__ C,
            __nv_bfloat16* __restrict__ Obh, __nv_bfloat16* __restrict__ Obl,
            __half* __restrict__ Ohh, __half* __restrict__ Ohl,
            int M, int N, int K, int relu)
{
    extern __shared__ __align__(1024) char smraw[];
    uint32_t sb = s2u(smraw);
    const int tid = threadIdx.x, wid = tid >> 5, lane = tid & 31;
    const int m0 = blockIdx.y*256, n0 = blockIdx.x*128;
    const int wm = (wid >> 1) * 64;
    const int wn = (wid & 1) * 64;
    const uint32_t SSZ = (TERMS == 3) ? 98304u : 81920u;

    const int KT = K >> 6;
    const __half* pAh = Ah + (size_t)m0*K;
    const __half* pAl = Al + (size_t)m0*K;
    const __half* pBh = Bh + (size_t)n0*K;
    const __half* pBl = (TERMS == 3) ? (Bl + (size_t)n0*K) : nullptr;

    const uint32_t oAh = 0, oAl = 32768, oBh = 65536, oBl = 81920;
    const int arow = tid >> 3, acol = tid & 7;

    // prologue
    {
        #pragma unroll
        for (int i = 0; i < 8; i++){
            int r = arow + 32*i;
            cp16(sb + oAh + SWZ(r*128 + acol*16), pAh + (size_t)r*K + acol*8);
            cp16(sb + oAl + SWZ(r*128 + acol*16), pAl + (size_t)r*K + acol*8);
        }
        #pragma unroll
        for (int i = 0; i < 4; i++){
            int r = arow + 32*i;
            cp16(sb + oBh + SWZ(r*128 + acol*16), pBh + (size_t)r*K + acol*8);
            if (TERMS == 3)
                cp16(sb + oBl + SWZ(r*128 + acol*16), pBl + (size_t)r*K + acol*8);
        }
        asm volatile("cp.async.commit_group;" ::: "memory");
    }

    float acc[4][8][4];
    #pragma unroll
    for (int a = 0; a < 4; a++)
        #pragma unroll
        for (int b = 0; b < 8; b++)
            #pragma unroll
            for (int c = 0; c < 4; c++) acc[a][b][c] = 0.f;

    const int lrow = (lane & 7) + ((lane >> 3) & 1) * 8;
    const int koff = ((lane >> 4) & 1) * 16;

    for (int kt = 0; kt < KT; kt++){
        asm volatile("cp.async.wait_group 0;" ::: "memory");
        __syncthreads();

        uint32_t bufs = sb + (kt & 1) * SSZ;

        if (kt + 1 < KT){
            uint32_t nbb = sb + ((kt + 1) & 1) * SSZ;
            int k0 = (kt + 1) << 6;
            #pragma unroll
            for (int i = 0; i < 8; i++){
                int r = arow + 32*i;
                cp16(nbb + oAh + SWZ(r*128 + acol*16), pAh + (size_t)r*K + k0 + acol*8);
                cp16(nbb + oAl + SWZ(r*128 + acol*16), pAl + (size_t)r*K + k0 + acol*8);
            }
            #pragma unroll
            for (int i = 0; i < 4; i++){
                int r = arow + 32*i;
                cp16(nbb + oBh + SWZ(r*128 + acol*16), pBh + (size_t)r*K + k0 + acol*8);
                if (TERMS == 3)
                    cp16(nbb + oBl + SWZ(r*128 + acol*16), pBl + (size_t)r*K + k0 + acol*8);
            }
            asm volatile("cp.async.commit_group;" ::: "memory");
        }

        #pragma unroll
        for (int ks = 0; ks < 4; ks++){
            const int kb = ks*32 + koff;
            uint32_t ah[4][4], al[4][4];
            #pragma unroll
            for (int mb = 0; mb < 4; mb++){
                int r = wm + mb*16 + lrow;
                ldm4(ah[mb], bufs + oAh + SWZ(r*128 + kb));
                ldm4(al[mb], bufs + oAl + SWZ(r*128 + kb));
            }
            #pragma unroll
            for (int nb = 0; nb < 4; nb++){
                uint32_t bh4[4], bl4[4];
                int r = wn + nb*16 + lrow;
                ldm4(bh4, bufs + oBh + SWZ(r*128 + kb));
                if (TERMS == 3)
                    ldm4(bl4, bufs + oBl + SWZ(r*128 + kb));
                #pragma unroll
                for (int mb = 0; mb < 4; mb++){
                    mma_hf(acc[mb][2*nb+0], ah[mb], bh4[0], bh4[2]);
                    mma_hf(acc[mb][2*nb+0], al[mb], bh4[0], bh4[2]);
                    if (TERMS == 3)
                        mma_hf(acc[mb][2*nb+0], ah[mb], bl4[0], bl4[2]);
                    mma_hf(acc[mb][2*nb+1], ah[mb], bh4[1], bh4[3]);
                    mma_hf(acc[mb][2*nb+1], al[mb], bh4[1], bh4[3]);
                    if (TERMS == 3)
                        mma_hf(acc[mb][2*nb+1], ah[mb], bl4[1], bl4[3]);
                }
            }
        }
    }

    const int erow = lane >> 2, ecol = (lane & 3) * 2;
    #pragma unroll
    for (int mb = 0; mb < 4; mb++){
        #pragma unroll
        for (int nf = 0; nf < 8; nf++){
            int r = m0 + wm + mb*16 + erow;
            int cc = n0 + wn + nf*8 + ecol;
            float b0 = bias[cc], b1 = bias[cc+1];
            float2 v0 = make_float2(acc[mb][nf][0] + b0, acc[mb][nf][1] + b1);
            float2 v1 = make_float2(acc[mb][nf][2] + b0, acc[mb][nf][3] + b1);
            if (relu){
                v0.x = fmaxf(v0.x, 0.f); v0.y = fmaxf(v0.y, 0.f);
                v1.x = fmaxf(v1.x, 0.f); v1.y = fmaxf(v1.y, 0.f);
            }
            if (C){
                *(float2*)(C + (size_t)r*N + cc)     = v0;
                *(float2*)(C + (size_t)(r+8)*N + cc) = v1;
            }
            if (Obh){
                __nv_bfloat162 h0 = __floats2bfloat162_rn(v0.x, v0.y);
                __nv_bfloat162 l0 = __floats2bfloat162_rn(
                    v0.x - __bfloat162float(h0.x), v0.y - __bfloat162float(h0.y));
                __nv_bfloat162 h1 = __floats2bfloat162_rn(v1.x, v1.y);
                __nv_bfloat162 l1 = __floats2bfloat162_rn(
                    v1.x - __bfloat162float(h1.x), v1.y - __bfloat162float(h1.y));
                *(__nv_bfloat162*)(Obh + (size_t)r*N + cc)     = h0;
                *(__nv_bfloat162*)(Obl + (size_t)r*N + cc)     = l0;
                *(__nv_bfloat162*)(Obh + (size_t)(r+8)*N + cc) = h1;
                *(__nv_bfloat162*)(Obl + (size_t)(r+8)*N + cc) = l1;
            }
            if (Ohh){
                __half2 l0, l1;
                __half2 h0 = split_h2(v0.x, v0.y, &l0);
                __half2 h1 = split_h2(v1.x, v1.y, &l1);
                *(__half2*)(Ohh + (size_t)r*N + cc)     = h0;
                *(__half2*)(Ohl + (size_t)r*N + cc)     = l0;
                *(__half2*)(Ohh + (size_t)(r+8)*N + cc) = h1;
                *(__half2*)(Ohl + (size_t)(r+8)*N + cc) = l1;
            }
        }
    }
}

// ---------------- tensor-core flash attention (bf16 3-term) ------------------
#define AT_SMEM 99328
__global__ __launch_bounds__(256, 1)
void attn_tc(const __nv_bfloat16* __restrict__ Qh_, const __nv_bfloat16* __restrict__ Ql_,
             const __nv_bfloat16* __restrict__ Kh_, const __nv_bfloat16* __restrict__ Kl_,
             const __nv_bfloat16* __restrict__ Vh_, const __nv_bfloat16* __restrict__ Vl_,
             const int* __restrict__ mask, const float* __restrict__ btab,
             __half* __restrict__ Oh, __half* __restrict__ Ol)
{
    extern __shared__ __align__(1024) char smraw[];
    uint32_t sb = s2u(smraw);
    const int tid = threadIdx.x, wid = tid >> 5, lane = tid & 31;
    const int g = blockIdx.y, q0 = blockIdx.x * 128;
    const int hh_ = g & (HH-1), bb = g >> 4;
    const int wq = wid * 16;
    const int lr = lane >> 2, lq = lane & 3;
    const int lrow = (lane & 7) + ((lane >> 3) & 1) * 8;
    const int koff = ((lane >> 4) & 1) * 16;

    const uint32_t oQh = 0, oQl = 16384, oKV = 32768;
    float* sbias = (float*)(smraw + 98304);
    float* spen  = (float*)(smraw + 99072);

    const size_t gb = (size_t)g * SS * DHD;

    {
        const __nv_bfloat16* qh = Qh_ + gb + (size_t)q0 * DHD;
        const __nv_bfloat16* ql = Ql_ + gb + (size_t)q0 * DHD;
        #pragma unroll
        for (int i = 0; i < 4; i++){
            int c = tid + 256*i, row = c >> 3, col = c & 7;
            cp16(sb + oQh + SWZ(row*128 + col*16), qh + (size_t)row*64 + col*8);
            cp16(sb + oQl + SWZ(row*128 + col*16), ql + (size_t)row*64 + col*8);
        }
    }
    {
        uint32_t kvb = sb + oKV;
        const __nv_bfloat16* srcs[4] = { Kh_ + gb, Kl_ + gb, Vh_ + gb, Vl_ + gb };
        #pragma unroll
        for (int t = 0; t < 4; t++)
            #pragma unroll
            for (int i = 0; i < 2; i++){
                int c = tid + 256*i, row = c >> 3, col = c & 7;
                cp16(kvb + t*8192 + SWZ(row*128 + col*16), srcs[t] + (size_t)row*64 + col*8);
            }
    }
    asm volatile("cp.async.commit_group;" ::: "memory");

    float m0v = -1e30f, m1v = -1e30f, l0 = 0.f, l1 = 0.f;
    float o[8][4];
    #pragma unroll
    for (int i = 0; i < 8; i++)
        #pragma unroll
        for (int j = 0; j < 4; j++) o[i][j] = 0.f;

    for (int ch = 0; ch < 16; ch++){
        const int k0 = ch * 64;
        if (tid < 192){
            int idx = tid + q0 - k0 - 63 + (SS - 1);
            if (idx < 0) idx = 0;
            if (idx > 2*SS - 2) idx = 2*SS - 2;
            sbias[tid] = btab[idx*HH + hh_];
        }
        if (tid < 64) spen[tid] = (mask[bb*SS + k0 + tid] == 0) ? -1e30f : 0.f;

        if (ch + 1 < 16){
            uint32_t kvb = sb + oKV + ((ch+1)&1)*32768;
            const size_t off = gb + (size_t)(k0 + 64)*64;
            const __nv_bfloat16* srcs[4] = { Kh_+off, Kl_+off, Vh_+off, Vl_+off };
            #pragma unroll
            for (int t = 0; t < 4; t++)
                #pragma unroll
                for (int i = 0; i < 2; i++){
                    int c = tid + 256*i, row = c >> 3, col = c & 7;
                    cp16(kvb + t*8192 + SWZ(row*128 + col*16), srcs[t] + (size_t)row*64 + col*8);
                }
            asm volatile("cp.async.commit_group;" ::: "memory");
            asm volatile("cp.async.wait_group 1;" ::: "memory");
        } else {
            asm volatile("cp.async.wait_group 0;" ::: "memory");
        }
        __syncthreads();

        const uint32_t kvb = sb + oKV + (ch&1)*32768;

        float s_[8][4];
        #pragma unroll
        for (int i = 0; i < 8; i++)
            #pragma unroll
            for (int j = 0; j < 4; j++) s_[i][j] = 0.f;

        #pragma unroll
        for (int kb = 0; kb < 4; kb++){
            uint32_t qa[4], qb[4];
            ldm4(qa, sb + oQh + SWZ((wq+lrow)*128 + kb*32 + koff));
            ldm4(qb, sb + oQl + SWZ((wq+lrow)*128 + kb*32 + koff));
            #pragma unroll
            for (int j = 0; j < 4; j++){
                uint32_t kh4[4], kl4[4];
                ldm4(kh4, kvb +        SWZ((j*16+lrow)*128 + kb*32 + koff));
                ldm4(kl4, kvb + 8192 + SWZ((j*16+lrow)*128 + kb*32 + koff));
                mma_bf(s_[2*j],   qa, kh4[0], kh4[2]);
                mma_bf(s_[2*j],   qa, kl4[0], kl4[2]);
                mma_bf(s_[2*j],   qb, kh4[0], kh4[2]);
                mma_bf(s_[2*j+1], qa, kh4[1], kh4[3]);
                mma_bf(s_[2*j+1], qa, kl4[1], kl4[3]);
                mma_bf(s_[2*j+1], qb, kh4[1], kh4[3]);
            }
        }

        const int r0 = wq + lr, r1 = r0 + 8;
        #pragma unroll
        for (int nf = 0; nf < 8; nf++){
            int c0 = nf*8 + lq*2;
            s_[nf][0] += sbias[r0 - c0 + 63]     + spen[c0];
            s_[nf][1] += sbias[r0 - c0 + 62]     + spen[c0+1];
            s_[nf][2] += sbias[r1 - c0 + 63]     + spen[c0];
            s_[nf][3] += sbias[r1 - c0 + 62]     + spen[c0+1];
        }

        float mx0 = -1e30f, mx1 = -1e30f;
        #pragma unroll
        for (int nf = 0; nf < 8; nf++){
            mx0 = fmaxf(mx0, fmaxf(s_[nf][0], s_[nf][1]));
            mx1 = fmaxf(mx1, fmaxf(s_[nf][2], s_[nf][3]));
        }
        #pragma unroll
        for (int off = 1; off < 4; off <<= 1){
            mx0 = fmaxf(mx0, __shfl_xor_sync(0xffffffffu, mx0, off));
            mx1 = fmaxf(mx1, __shfl_xor_sync(0xffffffffu, mx1, off));
        }
        float mn0 = fmaxf(m0v, mx0), mn1 = fmaxf(m1v, mx1);
        float al0 = __expf(m0v - mn0), al1 = __expf(m1v - mn1);
        float sum0 = 0.f, sum1 = 0.f;
        #pragma unroll
        for (int nf = 0; nf < 8; nf++){
            s_[nf][0] = __expf(s_[nf][0] - mn0); sum0 += s_[nf][0];
            s_[nf][1] = __expf(s_[nf][1] - mn0); sum0 += s_[nf][1];
            s_[nf][2] = __expf(s_[nf][2] - mn1); sum1 += s_[nf][2];
            s_[nf][3] = __expf(s_[nf][3] - mn1); sum1 += s_[nf][3];
        }
        #pragma unroll
        for (int off = 1; off < 4; off <<= 1){
            sum0 += __shfl_xor_sync(0xffffffffu, sum0, off);
            sum1 += __shfl_xor_sync(0xffffffffu, sum1, off);
        }
        l0 = l0*al0 + sum0; l1 = l1*al1 + sum1;
        m0v = mn0; m1v = mn1;
        #pragma unroll
        for (int nf = 0; nf < 8; nf++){
            o[nf][0] *= al0; o[nf][1] *= al0;
            o[nf][2] *= al1; o[nf][3] *= al1;
        }

        #pragma unroll
        for (int kb = 0; kb < 4; kb++){
            uint32_t ah[4], alr[4];
            {
                __nv_bfloat162 t0 = __floats2bfloat162_rn(s_[2*kb][0],   s_[2*kb][1]);
                __nv_bfloat162 t1 = __floats2bfloat162_rn(s_[2*kb][2],   s_[2*kb][3]);
                __nv_bfloat162 t2 = __floats2bfloat162_rn(s_[2*kb+1][0], s_[2*kb+1][1]);
                __nv_bfloat162 t3 = __floats2bfloat162_rn(s_[2*kb+1][2], s_[2*kb+1][3]);
                ah[0] = bf2u(t0); ah[1] = bf2u(t1); ah[2] = bf2u(t2); ah[3] = bf2u(t3);
                alr[0] = bf2u(__floats2bfloat162_rn(
                    s_[2*kb][0]   - __bfloat162float(t0.x), s_[2*kb][1]   - __bfloat162float(t0.y)));
                alr[1] = bf2u(__floats2bfloat162_rn(
                    s_[2*kb][2]   - __bfloat162float(t1.x), s_[2*kb][3]   - __bfloat162float(t1.y)));
                alr[2] = bf2u(__floats2bfloat162_rn(
                    s_[2*kb+1][0] - __bfloat162float(t2.x), s_[2*kb+1][1] - __bfloat162float(t2.y)));
                alr[3] = bf2u(__floats2bfloat162_rn(
                    s_[2*kb+1][2] - __bfloat162float(t3.x), s_[2*kb+1][3] - __bfloat162float(t3.y)));
            }
            #pragma unroll
            for (int j = 0; j < 4; j++){
                uint32_t vh4[4], vl4[4];
                ldm4t(vh4, kvb + 16384 + SWZ((kb*16+lrow)*128 + j*32 + koff));
                ldm4t(vl4, kvb + 24576 + SWZ((kb*16+lrow)*128 + j*32 + koff));
                mma_bf(o[2*j],   ah,  vh4[0], vh4[1]);
                mma_bf(o[2*j+1], ah,  vh4[2], vh4[3]);
                mma_bf(o[2*j],   ah,  vl4[0], vl4[1]);
                mma_bf(o[2*j+1], ah,  vl4[2], vl4[3]);
                mma_bf(o[2*j],   alr, vh4[0], vh4[1]);
                mma_bf(o[2*j+1], alr, vh4[2], vh4[3]);
            }
        }
        __syncthreads();
    }

    const float inv0 = 1.f / l0, inv1 = 1.f / l1;
    const int tq0 = q0 + wq + lr, tq1 = tq0 + 8;
    const size_t b0 = (size_t)g*65536 + (size_t)tq0*64;
    const size_t b1 = (size_t)g*65536 + (size_t)tq1*64;
    #pragma unroll
    for (int nf = 0; nf < 8; nf++){
        int d0 = nf*8 + lq*2;
        __half2 lv, lw;
        __half2 hv = split_h2(o[nf][0]*inv0, o[nf][1]*inv0, &lv);
        __half2 hw = split_h2(o[nf][2]*inv1, o[nf][3]*inv1, &lw);
        *(__half2*)(Oh + b0 + d0) = hv;
        *(__half2*)(Ol + b0 + d0) = lv;
        *(__half2*)(Oh + b1 + d0) = hw;
        *(__half2*)(Ol + b1 + d0) = lw;
    }
}

// ---------------- LayerNorm with residual (register-resident) ----------------
__global__ __launch_bounds__(256)
void ln_kernel(const float4* __restrict__ A, const float4* __restrict__ R,
               const float4* __restrict__ gamma, const float4* __restrict__ beta,
               float4* __restrict__ Out,
               __half* __restrict__ Oh, __half* __restrict__ Ol)
{
    __shared__ float red[8];
    const int row = blockIdx.x, tid = threadIdx.x;
    const size_t base = (size_t)row * (DD/4);

    float4 a = A[base + tid], r4 = R[base + tid];
    float x0 = a.x + r4.x, x1 = a.y + r4.y, x2 = a.z + r4.z, x3 = a.w + r4.w;

    float lsum = x0 + x1 + x2 + x3;
    #pragma unroll
    for (int off = 16; off; off >>= 1) lsum += __shfl_xor_sync(0xffffffffu, lsum, off);
    if ((tid & 31) == 0) red[tid >> 5] = lsum;
    __syncthreads();
    float tot = 0.f;
    #pragma unroll
    for (int w = 0; w < 8; w++) tot += red[w];
    float mu = tot * (1.f / DD);
    __syncthreads();

    float d0 = x0-mu, d1 = x1-mu, d2 = x2-mu, d3 = x3-mu;
    float lsq = d0*d0 + d1*d1 + d2*d2 + d3*d3;
    #pragma unroll
    for (int off = 16; off; off >>= 1) lsq += __shfl_xor_sync(0xffffffffu, lsq, off);
    if ((tid & 31) == 0) red[tid >> 5] = lsq;
    __syncthreads();
    float vt = 0.f;
    #pragma unroll
    for (int w = 0; w < 8; w++) vt += red[w];
    float inv = rsqrtf(vt * (1.f / DD) + 1e-5f);

    float4 g = gamma[tid], b = beta[tid];
    float4 v;
    v.x = g.x * d0 * inv + b.x;
    v.y = g.y * d1 * inv + b.y;
    v.z = g.z * d2 * inv + b.z;
    v.w = g.w * d3 * inv + b.w;
    Out[base + tid] = v;
    if (Oh){
        __half2 l0, l1;
        __half2 h0 = split_h2(v.x, v.y, &l0);
        __half2 h1 = split_h2(v.z, v.w, &l1);
        __half2* ph = (__half2*)(Oh + (size_t)row*DD + tid*4);
        __half2* pl = (__half2*)(Ol + (size_t)row*DD + tid*4);
        ph[0] = h0; ph[1] = h1;
        pl[0] = l0; pl[1] = l1;
    }
}

// ---------------- launch ----------------------------------------------------
extern "C" void kernel_launch(void* const* d_in, const int* in_sizes, int n_in,
                              void* d_out, int out_size)
{
    const float* x    = (const float*)d_in[0];
    const int*   mask = (const int*)  d_in[1];
    const float* Wq = (const float*)d_in[2];  const float* bq = (const float*)d_in[3];
    const float* Wk = (const float*)d_in[4];  const float* bk = (const float*)d_in[5];
    const float* Wv = (const float*)d_in[6];  const float* bv = (const float*)d_in[7];
    const float* Wo = (const float*)d_in[8];  const float* bo = (const float*)d_in[9];
    const float* rel_bias = (const float*)d_in[10];
    const float* ln1g = (const float*)d_in[11]; const float* ln1b = (const float*)d_in[12];
    const float* W1 = (const float*)d_in[13]; const float* b1 = (const float*)d_in[14];
    const float* W2 = (const float*)d_in[15]; const float* b2 = (const float*)d_in[16];
    const float* ln2g = (const float*)d_in[17]; const float* ln2b = (const float*)d_in[18];
    float* out = (float*)d_out;

    float *tmp, *h, *btab;
    cudaGetSymbolAddress((void**)&tmp,  g_tmp);
    cudaGetSymbolAddress((void**)&h,    g_h);
    cudaGetSymbolAddress((void**)&btab, g_btab);

    __half *xh,*xl, *ath,*atl, *hh,*hl, *fh,*fl;
    __half *wqh,*wql,*wkh,*wkl,*wvh,*wvl,*woh,*w1h,*w2h;
    __nv_bfloat16 *qh,*ql,*kh,*kl,*vh,*vl;
    cudaGetSymbolAddress((void**)&xh,  g_xh);  cudaGetSymbolAddress((void**)&xl,  g_xl);
    cudaGetSymbolAddress((void**)&ath, g_ath); cudaGetSymbolAddress((void**)&atl, g_atl);
    cudaGetSymbolAddress((void**)&hh,  g_hh);  cudaGetSymbolAddress((void**)&hl,  g_hl);
    cudaGetSymbolAddress((void**)&fh,  g_fh);  cudaGetSymbolAddress((void**)&fl,  g_fl);
    cudaGetSymbolAddress((void**)&qh,  g_qh);  cudaGetSymbolAddress((void**)&ql,  g_ql);
    cudaGetSymbolAddress((void**)&kh,  g_kbh); cudaGetSymbolAddress((void**)&kl,  g_kbl);
    cudaGetSymbolAddress((void**)&vh,  g_vbh); cudaGetSymbolAddress((void**)&vl,  g_vbl);
    cudaGetSymbolAddress((void**)&wqh, g_wqh); cudaGetSymbolAddress((void**)&wql, g_wql);
    cudaGetSymbolAddress((void**)&wkh, g_wkh); cudaGetSymbolAddress((void**)&wkl, g_wkl);
    cudaGetSymbolAddress((void**)&wvh, g_wvh); cudaGetSymbolAddress((void**)&wvl, g_wvl);
    cudaGetSymbolAddress((void**)&woh, g_woh);
    cudaGetSymbolAddress((void**)&w1h, g_w1h);
    cudaGetSymbolAddress((void**)&w2h, g_w2h);

    cudaFuncSetAttribute(tcgemm<3>, cudaFuncAttributeMaxDynamicSharedMemorySize, GSM3);
    cudaFuncSetAttribute(tcgemm<2>, cudaFuncAttributeMaxDynamicSharedMemorySize, GSM2);
    cudaFuncSetAttribute(attn_tc,   cudaFuncAttributeMaxDynamicSharedMemorySize, AT_SMEM);

    // 1. bias table + input split + weight transposes
    bias_table_kernel<<<(2*SS - 1 + 255)/256, 256>>>(rel_bias, btab);
    split_kernel<<<(MR*DD/4 + 255)/256, 256>>>((const float4*)x, xh, xl, MR*DD/4);
    dim3 tb(32, 8);
    transpose_half<1><<<dim3(DD/32, DD/32), tb>>>(Wq, wqh, wql, DD, DD);
    transpose_half<1><<<dim3(DD/32, DD/32), tb>>>(Wk, wkh, wkl, DD, DD);
    transpose_half<1><<<dim3(DD/32, DD/32), tb>>>(Wv, wvh, wvl, DD, DD);
    transpose_half<0><<<dim3(DD/32, DD/32), tb>>>(Wo, woh, nullptr, DD, DD);
    transpose_half<0><<<dim3(FF/32, DD/32), tb>>>(W1, w1h, nullptr, DD, FF);
    transpose_half<0><<<dim3(DD/32, FF/32), tb>>>(W2, w2h, nullptr, FF, DD);

    // 2. Q/K/V projections (fp16 3-term) -> bf16 hi/lo for attention
    dim3 gproj(DD/128, MR/256);
    tcgemm<3><<<gproj, 256, GSM3>>>(xh, xl, wqh, wql, bq, nullptr, qh, ql,
                                    nullptr, nullptr, MR, DD, DD, 0);
    tcgemm<3><<<gproj, 256, GSM3>>>(xh, xl, wkh, wkl, bk, nullptr, kh, kl,
                                    nullptr, nullptr, MR, DD, DD, 0);
    tcgemm<3><<<gproj, 256, GSM3>>>(xh, xl, wvh, wvl, bv, nullptr, vh, vl,
                                    nullptr, nullptr, MR, DD, DD, 0);

    // 3. attention -> fp16 hi/lo
    attn_tc<<<dim3(SS/128, NG), 256, AT_SMEM>>>(qh, ql, kh, kl, vh, vl,
                                                mask, btab, ath, atl);

    // 4. Wo projection (fp16 2-term) -> fp32
    tcgemm<2><<<gproj, 256, GSM2>>>(ath, atl, woh, nullptr, bo, tmp,
                                    nullptr, nullptr, nullptr, nullptr, MR, DD, DD, 0);

    // 5. LN1 -> h fp32 + fp16 hi/lo
    ln_kernel<<<MR, 256>>>((const float4*)tmp, (const float4*)x,
                           (const float4*)ln1g, (const float4*)ln1b,
                           (float4*)h, hh, hl);

    // 6. FFN (fp16 2-term)
    dim3 gff1(FF/128, MR/256);
    tcgemm<2><<<gff1, 256, GSM2>>>(hh, hl, w1h, nullptr, b1, nullptr,
                                   nullptr, nullptr, fh, fl, MR, FF, DD, 1);
    dim3 gff2(DD/128, MR/256);
    tcgemm<2><<<gff2, 256, GSM2>>>(fh, fl, w2h, nullptr, b2, tmp,
                                   nullptr, nullptr, nullptr, nullptr, MR, DD, FF, 0);

    // 7. LN2 -> out
    ln_kernel<<<MR, 256>>>((const float4*)tmp, (const float4*)h,
                           (const float4*)ln2g, (const float4*)ln2b,
                           (float4*)out, nullptr, nullptr);
}

// round 8
// speedup vs baseline: 3.6465x; 1.0663x over previous
#include <cuda_runtime.h>
#include <cuda_fp16.h>
#include <math.h>
#include <stdint.h>

#define BB 4
#define SS 1024
#define DD 1024
#define HH 16
#define FF 4096
#define DHD 64
#define NG (BB*HH)
#define MR (BB*SS)

// ---------------- scratch (static device globals; no allocation) -------------
__device__ float g_tmp[MR*DD];
__device__ float g_h[MR*DD];
__device__ float g_btab[(2*SS-1)*HH];

// fp16 activations
__device__ __half g_xh[MR*DD],  g_xl[MR*DD];          // input hi/lo (QKV A)
__device__ __half g_qh[MR*DD],  g_ql[MR*DD];          // Q hi/lo
__device__ __half g_kh[MR*DD],  g_kl[MR*DD];          // K hi/lo
__device__ __half g_v16[MR*DD];                       // V single
__device__ __half g_att16[MR*DD];                     // attention out single
__device__ __half g_h16[MR*DD];                       // LN1 out single
__device__ __half g_f16[(size_t)MR*FF];               // ReLU(ff1) single
// fp16 transposed weights [N,K], all hi/lo
__device__ __half g_wqh[DD*DD], g_wql[DD*DD];
__device__ __half g_wkh[DD*DD], g_wkl[DD*DD];
__device__ __half g_wvh[DD*DD], g_wvl[DD*DD];
__device__ __half g_woh[DD*DD], g_wol[DD*DD];
__device__ __half g_w1h[(size_t)DD*FF], g_w1l[(size_t)DD*FF];
__device__ __half g_w2h[(size_t)FF*DD], g_w2l[(size_t)FF*DD];

// ---------------- PTX helpers ------------------------------------------------
#define SWZ(o) ((o) ^ (((o) >> 3) & 0x70))

__device__ __forceinline__ uint32_t s2u(const void* p){
    uint32_t a;
    asm("{ .reg .u64 t; cvta.to.shared.u64 t, %1; cvt.u32.u64 %0, t; }"
        : "=r"(a) : "l"(p));
    return a;
}
__device__ __forceinline__ void cp16(uint32_t d, const void* s){
    asm volatile("cp.async.cg.shared.global [%0], [%1], 16;" :: "r"(d), "l"(s));
}
__device__ __forceinline__ void ldm4(uint32_t* r, uint32_t a){
    asm volatile("ldmatrix.sync.aligned.m8n8.x4.shared.b16 {%0,%1,%2,%3}, [%4];"
        : "=r"(r[0]), "=r"(r[1]), "=r"(r[2]), "=r"(r[3]) : "r"(a));
}
__device__ __forceinline__ void ldm4t(uint32_t* r, uint32_t a){
    asm volatile("ldmatrix.sync.aligned.m8n8.x4.trans.shared.b16 {%0,%1,%2,%3}, [%4];"
        : "=r"(r[0]), "=r"(r[1]), "=r"(r[2]), "=r"(r[3]) : "r"(a));
}
__device__ __forceinline__ void mma_hf(float* c, const uint32_t* a,
                                       uint32_t b0, uint32_t b1){
    asm volatile("mma.sync.aligned.m16n8k16.row.col.f32.f16.f16.f32 "
        "{%0,%1,%2,%3}, {%4,%5,%6,%7}, {%8,%9}, {%0,%1,%2,%3};"
        : "+f"(c[0]), "+f"(c[1]), "+f"(c[2]), "+f"(c[3])
        : "r"(a[0]), "r"(a[1]), "r"(a[2]), "r"(a[3]), "r"(b0), "r"(b1));
}
__device__ __forceinline__ uint32_t h2u(__half2 v){ return *(uint32_t*)&v; }

__device__ __forceinline__ __half2 split_h2(float a, float b, __half2* lo){
    __half h0 = __float2half_rn(a), h1 = __float2half_rn(b);
    *lo = __halves2half2(__float2half_rn(a - __half2float(h0)),
                         __float2half_rn(b - __half2float(h1)));
    return __halves2half2(h0, h1);
}

// ---------------- relative-position bias table ------------------------------
__global__ void bias_table_kernel(const float* __restrict__ rel_bias,
                                  float* __restrict__ tab)
{
    int r = blockIdx.x * blockDim.x + threadIdx.x;
    if (r >= 2*SS - 1) return;
    int rel = r - (SS - 1);
    int n = -rel;
    int ret = (n < 0) ? 16 : 0;
    int na = n < 0 ? -n : n;
    int bucket;
    if (na < 8) {
        bucket = ret + na;
    } else {
        double v = log((double)na / 8.0) / log(16.0) * 8.0;
        int vi = 8 + (int)v;
        if (vi > 15) vi = 15;
        bucket = ret + vi;
    }
    #pragma unroll
    for (int h = 0; h < HH; h++) tab[r*HH + h] = rel_bias[bucket*HH + h];
}

// ---------------- fp32 -> fp16 hi/lo split -----------------------------------
__global__ __launch_bounds__(256)
void split_kernel(const float4* __restrict__ in, __half* __restrict__ oh,
                  __half* __restrict__ ol, int n4)
{
    int i = blockIdx.x * 256 + threadIdx.x;
    if (i >= n4) return;
    float4 v = in[i];
    __half2 l0, l1;
    __half2 h0 = split_h2(v.x, v.y, &l0);
    __half2 h1 = split_h2(v.z, v.w, &l1);
    __half2* po = (__half2*)(oh + (size_t)i*4);
    __half2* pl = (__half2*)(ol + (size_t)i*4);
    po[0] = h0; po[1] = h1;
    pl[0] = l0; pl[1] = l1;
}

// ---------------- fused transpose+split of all 6 weights ---------------------
struct TransArgs {
    const float* src[6];
    __half* dh[6];
    __half* dl[6];
    int K[6], N[6], base[6];
};
__global__ __launch_bounds__(256)
void transpose_all(TransArgs a)
{
    __shared__ float t[32][33];
    int bt = blockIdx.x;
    int reg = (bt < 1024) ? 0 : (bt < 2048) ? 1 : (bt < 3072) ? 2 :
              (bt < 4096) ? 3 : (bt < 8192) ? 4 : 5;
    int local = bt - a.base[reg];
    int K = a.K[reg], N = a.N[reg];
    int ntiles = N >> 5;
    int n0 = (local % ntiles) * 32, k0 = (local / ntiles) * 32;

    const float* in = a.src[reg];
    __half* oh = a.dh[reg];
    __half* ol = a.dl[reg];

    int tx = threadIdx.x, ty = threadIdx.y;
    #pragma unroll
    for (int i = 0; i < 32; i += 8)
        t[ty+i][tx] = in[(size_t)(k0+ty+i)*N + n0+tx];
    __syncthreads();
    #pragma unroll
    for (int i = 0; i < 32; i += 8){
        float v = t[tx][ty+i];
        __half h = __float2half_rn(v);
        oh[(size_t)(n0+ty+i)*K + k0+tx] = h;
        ol[(size_t)(n0+ty+i)*K + k0+tx] = __float2half_rn(v - __half2float(h));
    }
}

// ---------------- fused QKV GEMM (fp16 3-term) -------------------------------
// A = x hi/lo [M,K]; per-region B hi/lo [1024,K]. Region 0/1 (Q,K): hi/lo out.
// Region 2 (V): single fp16 out. CTA 256x128, BK=64, 2-stage cp.async.
struct QKVArgs {
    const __half* Bh[3]; const __half* Bl[3];
    const float*  bias[3];
    __half* Oh[3]; __half* Ol[3];   // Ol[2] unused
};
#define GSM3 (2*98304)
__global__ __launch_bounds__(256, 1)
void qkv_gemm(const __half* __restrict__ Ah, const __half* __restrict__ Al,
              QKVArgs args, int M, int K)
{
    extern __shared__ __align__(1024) char smraw[];
    uint32_t sb = s2u(smraw);
    const int tid = threadIdx.x, wid = tid >> 5, lane = tid & 31;
    const int reg = blockIdx.x >> 3;
    const int n0 = (blockIdx.x & 7) * 128;
    const int m0 = blockIdx.y * 256;
    const int wm = (wid >> 1) * 64;
    const int wn = (wid & 1) * 64;
    const int N = DD;

    const int KT = K >> 6;
    const __half* pAh = Ah + (size_t)m0*K;
    const __half* pAl = Al + (size_t)m0*K;
    const __half* pBh = args.Bh[reg] + (size_t)n0*K;
    const __half* pBl = args.Bl[reg] + (size_t)n0*K;

    const uint32_t oAh = 0, oAl = 32768, oBh = 65536, oBl = 81920;
    const int arow = tid >> 3, acol = tid & 7;

    {
        #pragma unroll
        for (int i = 0; i < 8; i++){
            int r = arow + 32*i;
            cp16(sb + oAh + SWZ(r*128 + acol*16), pAh + (size_t)r*K + acol*8);
            cp16(sb + oAl + SWZ(r*128 + acol*16), pAl + (size_t)r*K + acol*8);
        }
        #pragma unroll
        for (int i = 0; i < 4; i++){
            int r = arow + 32*i;
            cp16(sb + oBh + SWZ(r*128 + acol*16), pBh + (size_t)r*K + acol*8);
            cp16(sb + oBl + SWZ(r*128 + acol*16), pBl + (size_t)r*K + acol*8);
        }
        asm volatile("cp.async.commit_group;" ::: "memory");
    }

    float acc[4][8][4];
    #pragma unroll
    for (int a = 0; a < 4; a++)
        #pragma unroll
        for (int b = 0; b < 8; b++)
            #pragma unroll
            for (int c = 0; c < 4; c++) acc[a][b][c] = 0.f;

    const int lrow = (lane & 7) + ((lane >> 3) & 1) * 8;
    const int koff = ((lane >> 4) & 1) * 16;

    for (int kt = 0; kt < KT; kt++){
        asm volatile("cp.async.wait_group 0;" ::: "memory");
        __syncthreads();

        uint32_t bufs = sb + (kt & 1) * 98304;

        if (kt + 1 < KT){
            uint32_t nbb = sb + ((kt + 1) & 1) * 98304;
            int k0 = (kt + 1) << 6;
            #pragma unroll
            for (int i = 0; i < 8; i++){
                int r = arow + 32*i;
                cp16(nbb + oAh + SWZ(r*128 + acol*16), pAh + (size_t)r*K + k0 + acol*8);
                cp16(nbb + oAl + SWZ(r*128 + acol*16), pAl + (size_t)r*K + k0 + acol*8);
            }
            #pragma unroll
            for (int i = 0; i < 4; i++){
                int r = arow + 32*i;
                cp16(nbb + oBh + SWZ(r*128 + acol*16), pBh + (size_t)r*K + k0 + acol*8);
                cp16(nbb + oBl + SWZ(r*128 + acol*16), pBl + (size_t)r*K + k0 + acol*8);
            }
            asm volatile("cp.async.commit_group;" ::: "memory");
        }

        #pragma unroll
        for (int ks = 0; ks < 4; ks++){
            const int kb = ks*32 + koff;
            uint32_t ah[4][4], al[4][4];
            #pragma unroll
            for (int mb = 0; mb < 4; mb++){
                int r = wm + mb*16 + lrow;
                ldm4(ah[mb], bufs + oAh + SWZ(r*128 + kb));
                ldm4(al[mb], bufs + oAl + SWZ(r*128 + kb));
            }
            #pragma unroll
            for (int nb = 0; nb < 4; nb++){
                uint32_t bh4[4], bl4[4];
                int r = wn + nb*16 + lrow;
                ldm4(bh4, bufs + oBh + SWZ(r*128 + kb));
                ldm4(bl4, bufs + oBl + SWZ(r*128 + kb));
                #pragma unroll
                for (int mb = 0; mb < 4; mb++){
                    mma_hf(acc[mb][2*nb+0], ah[mb], bh4[0], bh4[2]);
                    mma_hf(acc[mb][2*nb+0], al[mb], bh4[0], bh4[2]);
                    mma_hf(acc[mb][2*nb+0], ah[mb], bl4[0], bl4[2]);
                    mma_hf(acc[mb][2*nb+1], ah[mb], bh4[1], bh4[3]);
                    mma_hf(acc[mb][2*nb+1], al[mb], bh4[1], bh4[3]);
                    mma_hf(acc[mb][2*nb+1], ah[mb], bl4[1], bl4[3]);
                }
            }
        }
    }

    const float* bias = args.bias[reg];
    __half* Oh = args.Oh[reg];
    __half* Ol = args.Ol[reg];
    const int erow = lane >> 2, ecol = (lane & 3) * 2;
    #pragma unroll
    for (int mb = 0; mb < 4; mb++){
        #pragma unroll
        for (int nf = 0; nf < 8; nf++){
            int r = m0 + wm + mb*16 + erow;
            int cc = n0 + wn + nf*8 + ecol;
            float b0 = bias[cc], b1 = bias[cc+1];
            float2 v0 = make_float2(acc[mb][nf][0] + b0, acc[mb][nf][1] + b1);
            float2 v1 = make_float2(acc[mb][nf][2] + b0, acc[mb][nf][3] + b1);
            if (reg < 2){
                __half2 l0, l1;
                __half2 h0 = split_h2(v0.x, v0.y, &l0);
                __half2 h1 = split_h2(v1.x, v1.y, &l1);
                *(__half2*)(Oh + (size_t)r*N + cc)     = h0;
                *(__half2*)(Ol + (size_t)r*N + cc)     = l0;
                *(__half2*)(Oh + (size_t)(r+8)*N + cc) = h1;
                *(__half2*)(Ol + (size_t)(r+8)*N + cc) = l1;
            } else {
                *(__half2*)(Oh + (size_t)r*N + cc) =
                    __halves2half2(__float2half_rn(v0.x), __float2half_rn(v0.y));
                *(__half2*)(Oh + (size_t)(r+8)*N + cc) =
                    __halves2half2(__float2half_rn(v1.x), __float2half_rn(v1.y));
            }
        }
    }
}

// ---------------- 2-term GEMM: A single fp16, B hi/lo ------------------------
// C[M,N] = A[M,K] @ (Bh+Bl)[N,K]^T + bias. Out fp32 and/or fp16 single (+relu).
#define GSM2 (2*65536)
__global__ __launch_bounds__(256, 1)
void tcgemm2(const __half* __restrict__ A,
             const __half* __restrict__ Bh, const __half* __restrict__ Bl,
             const float* __restrict__ bias, float* __restrict__ C,
             __half* __restrict__ O16, int M, int N, int K, int relu)
{
    extern __shared__ __align__(1024) char smraw[];
    uint32_t sb = s2u(smraw);
    const int tid = threadIdx.x, wid = tid >> 5, lane = tid & 31;
    const int m0 = blockIdx.y*256, n0 = blockIdx.x*128;
    const int wm = (wid >> 1) * 64;
    const int wn = (wid & 1) * 64;

    const int KT = K >> 6;
    const __half* pA  = A  + (size_t)m0*K;
    const __half* pBh = Bh + (size_t)n0*K;
    const __half* pBl = Bl + (size_t)n0*K;

    const uint32_t oA = 0, oBh = 32768, oBl = 49152;
    const int arow = tid >> 3, acol = tid & 7;

    {
        #pragma unroll
        for (int i = 0; i < 8; i++){
            int r = arow + 32*i;
            cp16(sb + oA + SWZ(r*128 + acol*16), pA + (size_t)r*K + acol*8);
        }
        #pragma unroll
        for (int i = 0; i < 4; i++){
            int r = arow + 32*i;
            cp16(sb + oBh + SWZ(r*128 + acol*16), pBh + (size_t)r*K + acol*8);
            cp16(sb + oBl + SWZ(r*128 + acol*16), pBl + (size_t)r*K + acol*8);
        }
        asm volatile("cp.async.commit_group;" ::: "memory");
    }

    float acc[4][8][4];
    #pragma unroll
    for (int a = 0; a < 4; a++)
        #pragma unroll
        for (int b = 0; b < 8; b++)
            #pragma unroll
            for (int c = 0; c < 4; c++) acc[a][b][c] = 0.f;

    const int lrow = (lane & 7) + ((lane >> 3) & 1) * 8;
    const int koff = ((lane >> 4) & 1) * 16;

    for (int kt = 0; kt < KT; kt++){
        asm volatile("cp.async.wait_group 0;" ::: "memory");
        __syncthreads();

        uint32_t bufs = sb + (kt & 1) * 65536;

        if (kt + 1 < KT){
            uint32_t nbb = sb + ((kt + 1) & 1) * 65536;
            int k0 = (kt + 1) << 6;
            #pragma unroll
            for (int i = 0; i < 8; i++){
                int r = arow + 32*i;
                cp16(nbb + oA + SWZ(r*128 + acol*16), pA + (size_t)r*K + k0 + acol*8);
            }
            #pragma unroll
            for (int i = 0; i < 4; i++){
                int r = arow + 32*i;
                cp16(nbb + oBh + SWZ(r*128 + acol*16), pBh + (size_t)r*K + k0 + acol*8);
                cp16(nbb + oBl + SWZ(r*128 + acol*16), pBl + (size_t)r*K + k0 + acol*8);
            }
            asm volatile("cp.async.commit_group;" ::: "memory");
        }

        #pragma unroll
        for (int ks = 0; ks < 4; ks++){
            const int kb = ks*32 + koff;
            uint32_t ah[4][4];
            #pragma unroll
            for (int mb = 0; mb < 4; mb++){
                int r = wm + mb*16 + lrow;
                ldm4(ah[mb], bufs + oA + SWZ(r*128 + kb));
            }
            #pragma unroll
            for (int nb = 0; nb < 4; nb++){
                uint32_t bh4[4], bl4[4];
                int r = wn + nb*16 + lrow;
                ldm4(bh4, bufs + oBh + SWZ(r*128 + kb));
                ldm4(bl4, bufs + oBl + SWZ(r*128 + kb));
                #pragma unroll
                for (int mb = 0; mb < 4; mb++){
                    mma_hf(acc[mb][2*nb+0], ah[mb], bh4[0], bh4[2]);
                    mma_hf(acc[mb][2*nb+0], ah[mb], bl4[0], bl4[2]);
                    mma_hf(acc[mb][2*nb+1], ah[mb], bh4[1], bh4[3]);
                    mma_hf(acc[mb][2*nb+1], ah[mb], bl4[1], bl4[3]);
                }
            }
        }
    }

    const int erow = lane >> 2, ecol = (lane & 3) * 2;
    #pragma unroll
    for (int mb = 0; mb < 4; mb++){
        #pragma unroll
        for (int nf = 0; nf < 8; nf++){
            int r = m0 + wm + mb*16 + erow;
            int cc = n0 + wn + nf*8 + ecol;
            float b0 = bias[cc], b1 = bias[cc+1];
            float2 v0 = make_float2(acc[mb][nf][0] + b0, acc[mb][nf][1] + b1);
            float2 v1 = make_float2(acc[mb][nf][2] + b0, acc[mb][nf][3] + b1);
            if (relu){
                v0.x = fmaxf(v0.x, 0.f); v0.y = fmaxf(v0.y, 0.f);
                v1.x = fmaxf(v1.x, 0.f); v1.y = fmaxf(v1.y, 0.f);
            }
            if (C){
                *(float2*)(C + (size_t)r*N + cc)     = v0;
                *(float2*)(C + (size_t)(r+8)*N + cc) = v1;
            }
            if (O16){
                *(__half2*)(O16 + (size_t)r*N + cc) =
                    __halves2half2(__float2half_rn(v0.x), __float2half_rn(v0.y));
                *(__half2*)(O16 + (size_t)(r+8)*N + cc) =
                    __halves2half2(__float2half_rn(v1.x), __float2half_rn(v1.y));
            }
        }
    }
}

// ---------------- tensor-core flash attention (fp16) -------------------------
// QK: 3-term (Qh.Kh + Qh.Kl + Ql.Kh).  PV: 2-term (Ph.V + Pl.V, V single).
// smem: Qh 16K | Ql 16K | 2 x (Kh 8K | Kl 8K | V 8K) | bias/pen
#define AT_SMEM 83968
__global__ __launch_bounds__(256, 1)
void attn_tc(const __half* __restrict__ Qh_, const __half* __restrict__ Ql_,
             const __half* __restrict__ Kh_, const __half* __restrict__ Kl_,
             const __half* __restrict__ V_,
             const int* __restrict__ mask, const float* __restrict__ btab,
             __half* __restrict__ O16)
{
    extern __shared__ __align__(1024) char smraw[];
    uint32_t sb = s2u(smraw);
    const int tid = threadIdx.x, wid = tid >> 5, lane = tid & 31;
    const int g = blockIdx.y, q0 = blockIdx.x * 128;
    const int hh_ = g & (HH-1), bb = g >> 4;
    const int wq = wid * 16;
    const int lr = lane >> 2, lq = lane & 3;
    const int lrow = (lane & 7) + ((lane >> 3) & 1) * 8;
    const int koff = ((lane >> 4) & 1) * 16;

    const uint32_t oQh = 0, oQl = 16384, oKV = 32768;   // KV buf stride 24576
    float* sbias = (float*)(smraw + 81920);             // 192 floats
    float* spen  = (float*)(smraw + 82816);             // 64 floats

    const size_t gb = (size_t)g * SS * DHD;

    {
        const __half* qh = Qh_ + gb + (size_t)q0 * DHD;
        const __half* ql = Ql_ + gb + (size_t)q0 * DHD;
        #pragma unroll
        for (int i = 0; i < 4; i++){
            int c = tid + 256*i, row = c >> 3, col = c & 7;
            cp16(sb + oQh + SWZ(row*128 + col*16), qh + (size_t)row*64 + col*8);
            cp16(sb + oQl + SWZ(row*128 + col*16), ql + (size_t)row*64 + col*8);
        }
    }
    {
        uint32_t kvb = sb + oKV;
        const __half* srcs[3] = { Kh_ + gb, Kl_ + gb, V_ + gb };
        #pragma unroll
        for (int t = 0; t < 3; t++)
            #pragma unroll
            for (int i = 0; i < 2; i++){
                int c = tid + 256*i, row = c >> 3, col = c & 7;
                cp16(kvb + t*8192 + SWZ(row*128 + col*16), srcs[t] + (size_t)row*64 + col*8);
            }
    }
    asm volatile("cp.async.commit_group;" ::: "memory");

    float m0v = -1e30f, m1v = -1e30f, l0 = 0.f, l1 = 0.f;
    float o[8][4];
    #pragma unroll
    for (int i = 0; i < 8; i++)
        #pragma unroll
        for (int j = 0; j < 4; j++) o[i][j] = 0.f;

    for (int ch = 0; ch < 16; ch++){
        const int k0 = ch * 64;
        if (tid < 192){
            int idx = tid + q0 - k0 - 63 + (SS - 1);
            if (idx < 0) idx = 0;
            if (idx > 2*SS - 2) idx = 2*SS - 2;
            sbias[tid] = btab[idx*HH + hh_];
        }
        if (tid < 64) spen[tid] = (mask[bb*SS + k0 + tid] == 0) ? -1e30f : 0.f;

        if (ch + 1 < 16){
            uint32_t kvb = sb + oKV + ((ch+1)&1)*24576;
            const size_t off = gb + (size_t)(k0 + 64)*64;
            const __half* srcs[3] = { Kh_+off, Kl_+off, V_+off };
            #pragma unroll
            for (int t = 0; t < 3; t++)
                #pragma unroll
                for (int i = 0; i < 2; i++){
                    int c = tid + 256*i, row = c >> 3, col = c & 7;
                    cp16(kvb + t*8192 + SWZ(row*128 + col*16), srcs[t] + (size_t)row*64 + col*8);
                }
            asm volatile("cp.async.commit_group;" ::: "memory");
            asm volatile("cp.async.wait_group 1;" ::: "memory");
        } else {
            asm volatile("cp.async.wait_group 0;" ::: "memory");
        }
        __syncthreads();

        const uint32_t kvb = sb + oKV + (ch&1)*24576;

        float s_[8][4];
        #pragma unroll
        for (int i = 0; i < 8; i++)
            #pragma unroll
            for (int j = 0; j < 4; j++) s_[i][j] = 0.f;

        #pragma unroll
        for (int kb = 0; kb < 4; kb++){
            uint32_t qa[4], qb[4];
            ldm4(qa, sb + oQh + SWZ((wq+lrow)*128 + kb*32 + koff));
            ldm4(qb, sb + oQl + SWZ((wq+lrow)*128 + kb*32 + koff));
            #pragma unroll
            for (int j = 0; j < 4; j++){
                uint32_t kh4[4], kl4[4];
                ldm4(kh4, kvb +        SWZ((j*16+lrow)*128 + kb*32 + koff));
                ldm4(kl4, kvb + 8192 + SWZ((j*16+lrow)*128 + kb*32 + koff));
                mma_hf(s_[2*j],   qa, kh4[0], kh4[2]);
                mma_hf(s_[2*j],   qa, kl4[0], kl4[2]);
                mma_hf(s_[2*j],   qb, kh4[0], kh4[2]);
                mma_hf(s_[2*j+1], qa, kh4[1], kh4[3]);
                mma_hf(s_[2*j+1], qa, kl4[1], kl4[3]);
                mma_hf(s_[2*j+1], qb, kh4[1], kh4[3]);
            }
        }

        const int r0 = wq + lr, r1 = r0 + 8;
        #pragma unroll
        for (int nf = 0; nf < 8; nf++){
            int c0 = nf*8 + lq*2;
            s_[nf][0] += sbias[r0 - c0 + 63] + spen[c0];
            s_[nf][1] += sbias[r0 - c0 + 62] + spen[c0+1];
            s_[nf][2] += sbias[r1 - c0 + 63] + spen[c0];
            s_[nf][3] += sbias[r1 - c0 + 62] + spen[c0+1];
        }

        float mx0 = -1e30f, mx1 = -1e30f;
        #pragma unroll
        for (int nf = 0; nf < 8; nf++){
            mx0 = fmaxf(mx0, fmaxf(s_[nf][0], s_[nf][1]));
            mx1 = fmaxf(mx1, fmaxf(s_[nf][2], s_[nf][3]));
        }
        #pragma unroll
        for (int off = 1; off < 4; off <<= 1){
            mx0 = fmaxf(mx0, __shfl_xor_sync(0xffffffffu, mx0, off));
            mx1 = fmaxf(mx1, __shfl_xor_sync(0xffffffffu, mx1, off));
        }
        float mn0 = fmaxf(m0v, mx0), mn1 = fmaxf(m1v, mx1);
        float al0 = __expf(m0v - mn0), al1 = __expf(m1v - mn1);
        float sum0 = 0.f, sum1 = 0.f;
        #pragma unroll
        for (int nf = 0; nf < 8; nf++){
            s_[nf][0] = __expf(s_[nf][0] - mn0); sum0 += s_[nf][0];
            s_[nf][1] = __expf(s_[nf][1] - mn0); sum0 += s_[nf][1];
            s_[nf][2] = __expf(s_[nf][2] - mn1); sum1 += s_[nf][2];
            s_[nf][3] = __expf(s_[nf][3] - mn1); sum1 += s_[nf][3];
        }
        #pragma unroll
        for (int off = 1; off < 4; off <<= 1){
            sum0 += __shfl_xor_sync(0xffffffffu, sum0, off);
            sum1 += __shfl_xor_sync(0xffffffffu, sum1, off);
        }
        l0 = l0*al0 + sum0; l1 = l1*al1 + sum1;
        m0v = mn0; m1v = mn1;
        #pragma unroll
        for (int nf = 0; nf < 8; nf++){
            o[nf][0] *= al0; o[nf][1] *= al0;
            o[nf][2] *= al1; o[nf][3] *= al1;
        }

        #pragma unroll
        for (int kb = 0; kb < 4; kb++){
            uint32_t ph[4], pl[4];
            {
                __half2 t0l, t1l, t2l, t3l;
                __half2 t0 = split_h2(s_[2*kb][0],   s_[2*kb][1],   &t0l);
                __half2 t1 = split_h2(s_[2*kb][2],   s_[2*kb][3],   &t1l);
                __half2 t2 = split_h2(s_[2*kb+1][0], s_[2*kb+1][1], &t2l);
                __half2 t3 = split_h2(s_[2*kb+1][2], s_[2*kb+1][3], &t3l);
                ph[0] = h2u(t0);  ph[1] = h2u(t1);  ph[2] = h2u(t2);  ph[3] = h2u(t3);
                pl[0] = h2u(t0l); pl[1] = h2u(t1l); pl[2] = h2u(t2l); pl[3] = h2u(t3l);
            }
            #pragma unroll
            for (int j = 0; j < 4; j++){
                uint32_t vh4[4];
                ldm4t(vh4, kvb + 16384 + SWZ((kb*16+lrow)*128 + j*32 + koff));
                mma_hf(o[2*j],   ph, vh4[0], vh4[1]);
                mma_hf(o[2*j+1], ph, vh4[2], vh4[3]);
                mma_hf(o[2*j],   pl, vh4[0], vh4[1]);
                mma_hf(o[2*j+1], pl, vh4[2], vh4[3]);
            }
        }
        __syncthreads();
    }

    const float inv0 = 1.f / l0, inv1 = 1.f / l1;
    const int tq0 = q0 + wq + lr, tq1 = tq0 + 8;
    const size_t b0 = (size_t)g*65536 + (size_t)tq0*64;
    const size_t b1 = (size_t)g*65536 + (size_t)tq1*64;
    #pragma unroll
    for (int nf = 0; nf < 8; nf++){
        int d0 = nf*8 + lq*2;
        *(__half2*)(O16 + b0 + d0) = __halves2half2(
            __float2half_rn(o[nf][0]*inv0), __float2half_rn(o[nf][1]*inv0));
        *(__half2*)(O16 + b1 + d0) = __halves2half2(
            __float2half_rn(o[nf][2]*inv1), __float2half_rn(o[nf][3]*inv1));
    }
}

// ---------------- LayerNorm with residual (register-resident) ----------------
__global__ __launch_bounds__(256)
void ln_kernel(const float4* __restrict__ A, const float4* __restrict__ R,
               const float4* __restrict__ gamma, const float4* __restrict__ beta,
               float4* __restrict__ Out, __half* __restrict__ O16)
{
    __shared__ float red[8];
    const int row = blockIdx.x, tid = threadIdx.x;
    const size_t base = (size_t)row * (DD/4);

    float4 a = A[base + tid], r4 = R[base + tid];
    float x0 = a.x + r4.x, x1 = a.y + r4.y, x2 = a.z + r4.z, x3 = a.w + r4.w;

    float lsum = x0 + x1 + x2 + x3;
    #pragma unroll
    for (int off = 16; off; off >>= 1) lsum += __shfl_xor_sync(0xffffffffu, lsum, off);
    if ((tid & 31) == 0) red[tid >> 5] = lsum;
    __syncthreads();
    float tot = 0.f;
    #pragma unroll
    for (int w = 0; w < 8; w++) tot += red[w];
    float mu = tot * (1.f / DD);
    __syncthreads();

    float d0 = x0-mu, d1 = x1-mu, d2 = x2-mu, d3 = x3-mu;
    float lsq = d0*d0 + d1*d1 + d2*d2 + d3*d3;
    #pragma unroll
    for (int off = 16; off; off >>= 1) lsq += __shfl_xor_sync(0xffffffffu, lsq, off);
    if ((tid & 31) == 0) red[tid >> 5] = lsq;
    __syncthreads();
    float vt = 0.f;
    #pragma unroll
    for (int w = 0; w < 8; w++) vt += red[w];
    float inv = rsqrtf(vt * (1.f / DD) + 1e-5f);

    float4 g = gamma[tid], b = beta[tid];
    float4 v;
    v.x = g.x * d0 * inv + b.x;
    v.y = g.y * d1 * inv + b.y;
    v.z = g.z * d2 * inv + b.z;
    v.w = g.w * d3 * inv + b.w;
    Out[base + tid] = v;
    if (O16){
        __half2* ph = (__half2*)(O16 + (size_t)row*DD + tid*4);
        ph[0] = __halves2half2(__float2half_rn(v.x), __float2half_rn(v.y));
        ph[1] = __halves2half2(__float2half_rn(v.z), __float2half_rn(v.w));
    }
}

// ---------------- launch ----------------------------------------------------
extern "C" void kernel_launch(void* const* d_in, const int* in_sizes, int n_in,
                              void* d_out, int out_size)
{
    const float* x    = (const float*)d_in[0];
    const int*   mask = (const int*)  d_in[1];
    const float* Wq = (const float*)d_in[2];  const float* bq = (const float*)d_in[3];
    const float* Wk = (const float*)d_in[4];  const float* bk = (const float*)d_in[5];
    const float* Wv = (const float*)d_in[6];  const float* bv = (const float*)d_in[7];
    const float* Wo = (const float*)d_in[8];  const float* bo = (const float*)d_in[9];
    const float* rel_bias = (const float*)d_in[10];
    const float* ln1g = (const float*)d_in[11]; const float* ln1b = (const float*)d_in[12];
    const float* W1 = (const float*)d_in[13]; const float* b1 = (const float*)d_in[14];
    const float* W2 = (const float*)d_in[15]; const float* b2 = (const float*)d_in[16];
    const float* ln2g = (const float*)d_in[17]; const float* ln2b = (const float*)d_in[18];
    float* out = (float*)d_out;

    float *tmp, *h, *btab;
    cudaGetSymbolAddress((void**)&tmp,  g_tmp);
    cudaGetSymbolAddress((void**)&h,    g_h);
    cudaGetSymbolAddress((void**)&btab, g_btab);

    __half *xh,*xl, *qh,*ql, *kh,*kl, *v16, *att16, *h16, *f16;
    __half *wqh,*wql,*wkh,*wkl,*wvh,*wvl,*woh,*wol,*w1h,*w1l,*w2h,*w2l;
    cudaGetSymbolAddress((void**)&xh,   g_xh);   cudaGetSymbolAddress((void**)&xl,   g_xl);
    cudaGetSymbolAddress((void**)&qh,   g_qh);   cudaGetSymbolAddress((void**)&ql,   g_ql);
    cudaGetSymbolAddress((void**)&kh,   g_kh);   cudaGetSymbolAddress((void**)&kl,   g_kl);
    cudaGetSymbolAddress((void**)&v16,  g_v16);
    cudaGetSymbolAddress((void**)&att16,g_att16);
    cudaGetSymbolAddress((void**)&h16,  g_h16);
    cudaGetSymbolAddress((void**)&f16,  g_f16);
    cudaGetSymbolAddress((void**)&wqh,  g_wqh);  cudaGetSymbolAddress((void**)&wql,  g_wql);
    cudaGetSymbolAddress((void**)&wkh,  g_wkh);  cudaGetSymbolAddress((void**)&wkl,  g_wkl);
    cudaGetSymbolAddress((void**)&wvh,  g_wvh);  cudaGetSymbolAddress((void**)&wvl,  g_wvl);
    cudaGetSymbolAddress((void**)&woh,  g_woh);  cudaGetSymbolAddress((void**)&wol,  g_wol);
    cudaGetSymbolAddress((void**)&w1h,  g_w1h);  cudaGetSymbolAddress((void**)&w1l,  g_w1l);
    cudaGetSymbolAddress((void**)&w2h,  g_w2h);  cudaGetSymbolAddress((void**)&w2l,  g_w2l);

    cudaFuncSetAttribute(qkv_gemm, cudaFuncAttributeMaxDynamicSharedMemorySize, GSM3);
    cudaFuncSetAttribute(tcgemm2,  cudaFuncAttributeMaxDynamicSharedMemorySize, GSM2);
    cudaFuncSetAttribute(attn_tc,  cudaFuncAttributeMaxDynamicSharedMemorySize, AT_SMEM);

    // launch 0: bias table
    bias_table_kernel<<<(2*SS - 1 + 255)/256, 256>>>(rel_bias, btab);
    // launch 1: split input
    split_kernel<<<(MR*DD/4 + 255)/256, 256>>>((const float4*)x, xh, xl, MR*DD/4);
    // launch 2: all weight transposes
    {
        TransArgs ta;
        const float* srcs[6] = {Wq, Wk, Wv, Wo, W1, W2};
        __half* dh[6] = {wqh, wkh, wvh, woh, w1h, w2h};
        __half* dl[6] = {wql, wkl, wvl, wol, w1l, w2l};
        int Ks[6] = {DD, DD, DD, DD, DD, FF};
        int Ns[6] = {DD, DD, DD, DD, FF, DD};
        int bases[6] = {0, 1024, 2048, 3072, 4096, 8192};
        for (int i = 0; i < 6; i++){
            ta.src[i] = srcs[i]; ta.dh[i] = dh[i]; ta.dl[i] = dl[i];
            ta.K[i] = Ks[i]; ta.N[i] = Ns[i]; ta.base[i] = bases[i];
        }
        transpose_all<<<12288, dim3(32, 8)>>>(ta);
    }
    // launch 3: fused QKV
    {
        QKVArgs qa;
        qa.Bh[0] = wqh; qa.Bl[0] = wql; qa.bias[0] = bq; qa.Oh[0] = qh;  qa.Ol[0] = ql;
        qa.Bh[1] = wkh; qa.Bl[1] = wkl; qa.bias[1] = bk; qa.Oh[1] = kh;  qa.Ol[1] = kl;
        qa.Bh[2] = wvh; qa.Bl[2] = wvl; qa.bias[2] = bv; qa.Oh[2] = v16; qa.Ol[2] = nullptr;
        qkv_gemm<<<dim3(24, MR/256), 256, GSM3>>>(xh, xl, qa, MR, DD);
    }
    // launch 4: attention
    attn_tc<<<dim3(SS/128, NG), 256, AT_SMEM>>>(qh, ql, kh, kl, v16,
                                                mask, btab, att16);
    // launch 5: Wo  (ncu profile slot)
    tcgemm2<<<dim3(DD/128, MR/256), 256, GSM2>>>(att16, woh, wol, bo, tmp,
                                                 nullptr, MR, DD, DD, 0);
    // launch 6: LN1
    ln_kernel<<<MR, 256>>>((const float4*)tmp, (const float4*)x,
                           (const float4*)ln1g, (const float4*)ln1b,
                           (float4*)h, h16);
    // launch 7: W1 + ReLU
    tcgemm2<<<dim3(FF/128, MR/256), 256, GSM2>>>(h16, w1h, w1l, b1, nullptr,
                                                 f16, MR, FF, DD, 1);
    // launch 8: W2
    tcgemm2<<<dim3(DD/128, MR/256), 256, GSM2>>>(f16, w2h, w2l, b2, tmp,
                                                 nullptr, MR, DD, FF, 0);
    // launch 9: LN2
    ln_kernel<<<MR, 256>>>((const float4*)tmp, (const float4*)h,
                           (const float4*)ln2g, (const float4*)ln2b,
                           (float4*)out, nullptr);
}

// round 9
// speedup vs baseline: 3.6938x; 1.0130x over previous
#include <cuda_runtime.h>
#include <cuda_fp16.h>
#include <math.h>
#include <stdint.h>

#define BB 4
#define SS 1024
#define DD 1024
#define HH 16
#define FF 4096
#define DHD 64
#define NG (BB*HH)
#define MR (BB*SS)

// ---------------- scratch (static device globals; no allocation) -------------
__device__ float g_tmp[MR*DD];
__device__ float g_h[MR*DD];
__device__ float g_btab[(2*SS-1)*HH];

__device__ __half g_xh[MR*DD],  g_xl[MR*DD];
__device__ __half g_qh[MR*DD],  g_ql[MR*DD];
__device__ __half g_kh[MR*DD],  g_kl[MR*DD];
__device__ __half g_v16[MR*DD];
__device__ __half g_att16[MR*DD];
__device__ __half g_h16[MR*DD];
__device__ __half g_f16[(size_t)MR*FF];
__device__ __half g_wqh[DD*DD], g_wql[DD*DD];
__device__ __half g_wkh[DD*DD], g_wkl[DD*DD];
__device__ __half g_wvh[DD*DD], g_wvl[DD*DD];
__device__ __half g_woh[DD*DD], g_wol[DD*DD];
__device__ __half g_w1h[(size_t)DD*FF], g_w1l[(size_t)DD*FF];
__device__ __half g_w2h[(size_t)FF*DD], g_w2l[(size_t)FF*DD];

// ---------------- PTX helpers ------------------------------------------------
#define SWZ(o) ((o) ^ (((o) >> 3) & 0x70))

__device__ __forceinline__ uint32_t s2u(const void* p){
    uint32_t a;
    asm("{ .reg .u64 t; cvta.to.shared.u64 t, %1; cvt.u32.u64 %0, t; }"
        : "=r"(a) : "l"(p));
    return a;
}
__device__ __forceinline__ void cp16(uint32_t d, const void* s){
    asm volatile("cp.async.cg.shared.global [%0], [%1], 16;" :: "r"(d), "l"(s));
}
__device__ __forceinline__ void ldm4(uint32_t* r, uint32_t a){
    asm volatile("ldmatrix.sync.aligned.m8n8.x4.shared.b16 {%0,%1,%2,%3}, [%4];"
        : "=r"(r[0]), "=r"(r[1]), "=r"(r[2]), "=r"(r[3]) : "r"(a));
}
__device__ __forceinline__ void ldm4t(uint32_t* r, uint32_t a){
    asm volatile("ldmatrix.sync.aligned.m8n8.x4.trans.shared.b16 {%0,%1,%2,%3}, [%4];"
        : "=r"(r[0]), "=r"(r[1]), "=r"(r[2]), "=r"(r[3]) : "r"(a));
}
__device__ __forceinline__ void mma_hf(float* c, const uint32_t* a,
                                       uint32_t b0, uint32_t b1){
    asm volatile("mma.sync.aligned.m16n8k16.row.col.f32.f16.f16.f32 "
        "{%0,%1,%2,%3}, {%4,%5,%6,%7}, {%8,%9}, {%0,%1,%2,%3};"
        : "+f"(c[0]), "+f"(c[1]), "+f"(c[2]), "+f"(c[3])
        : "r"(a[0]), "r"(a[1]), "r"(a[2]), "r"(a[3]), "r"(b0), "r"(b1));
}
__device__ __forceinline__ uint32_t h2u(__half2 v){ return *(uint32_t*)&v; }

__device__ __forceinline__ __half2 split_h2(float a, float b, __half2* lo){
    __half h0 = __float2half_rn(a), h1 = __float2half_rn(b);
    *lo = __halves2half2(__float2half_rn(a - __half2float(h0)),
                         __float2half_rn(b - __half2float(h1)));
    return __halves2half2(h0, h1);
}

// ---------------- relative-position bias table ------------------------------
__global__ void bias_table_kernel(const float* __restrict__ rel_bias,
                                  float* __restrict__ tab)
{
    int r = blockIdx.x * blockDim.x + threadIdx.x;
    if (r >= 2*SS - 1) return;
    int rel = r - (SS - 1);
    int n = -rel;
    int ret = (n < 0) ? 16 : 0;
    int na = n < 0 ? -n : n;
    int bucket;
    if (na < 8) {
        bucket = ret + na;
    } else {
        double v = log((double)na / 8.0) / log(16.0) * 8.0;
        int vi = 8 + (int)v;
        if (vi > 15) vi = 15;
        bucket = ret + vi;
    }
    #pragma unroll
    for (int h = 0; h < HH; h++) tab[r*HH + h] = rel_bias[bucket*HH + h];
}

// ---------------- fp32 -> fp16 hi/lo split -----------------------------------
__global__ __launch_bounds__(256)
void split_kernel(const float4* __restrict__ in, __half* __restrict__ oh,
                  __half* __restrict__ ol, int n4)
{
    int i = blockIdx.x * 256 + threadIdx.x;
    if (i >= n4) return;
    float4 v = in[i];
    __half2 l0, l1;
    __half2 h0 = split_h2(v.x, v.y, &l0);
    __half2 h1 = split_h2(v.z, v.w, &l1);
    __half2* po = (__half2*)(oh + (size_t)i*4);
    __half2* pl = (__half2*)(ol + (size_t)i*4);
    po[0] = h0; po[1] = h1;
    pl[0] = l0; pl[1] = l1;
}

// ---------------- fused transpose+split of all 6 weights ---------------------
struct TransArgs {
    const float* src[6];
    __half* dh[6];
    __half* dl[6];
    int K[6], N[6], base[6];
};
__global__ __launch_bounds__(256)
void transpose_all(TransArgs a)
{
    __shared__ float t[32][33];
    int bt = blockIdx.x;
    int reg = (bt < 1024) ? 0 : (bt < 2048) ? 1 : (bt < 3072) ? 2 :
              (bt < 4096) ? 3 : (bt < 8192) ? 4 : 5;
    int local = bt - a.base[reg];
    int K = a.K[reg], N = a.N[reg];
    int ntiles = N >> 5;
    int n0 = (local % ntiles) * 32, k0 = (local / ntiles) * 32;

    const float* in = a.src[reg];
    __half* oh = a.dh[reg];
    __half* ol = a.dl[reg];

    int tx = threadIdx.x, ty = threadIdx.y;
    #pragma unroll
    for (int i = 0; i < 32; i += 8)
        t[ty+i][tx] = in[(size_t)(k0+ty+i)*N + n0+tx];
    __syncthreads();
    #pragma unroll
    for (int i = 0; i < 32; i += 8){
        float v = t[tx][ty+i];
        __half h = __float2half_rn(v);
        oh[(size_t)(n0+ty+i)*K + k0+tx] = h;
        ol[(size_t)(n0+ty+i)*K + k0+tx] = __float2half_rn(v - __half2float(h));
    }
}

// ---------------- fused QKV GEMM (fp16 3-term) -------------------------------
struct QKVArgs {
    const __half* Bh[3]; const __half* Bl[3];
    const float*  bias[3];
    __half* Oh[3]; __half* Ol[3];
};
#define GSM3 (2*98304)
__global__ __launch_bounds__(256, 1)
void qkv_gemm(const __half* __restrict__ Ah, const __half* __restrict__ Al,
              QKVArgs args, int M, int K)
{
    extern __shared__ __align__(1024) char smraw[];
    uint32_t sb = s2u(smraw);
    const int tid = threadIdx.x, wid = tid >> 5, lane = tid & 31;
    const int reg = blockIdx.x >> 3;
    const int n0 = (blockIdx.x & 7) * 128;
    const int m0 = blockIdx.y * 256;
    const int wm = (wid >> 1) * 64;
    const int wn = (wid & 1) * 64;
    const int N = DD;

    const int KT = K >> 6;
    const __half* pAh = Ah + (size_t)m0*K;
    const __half* pAl = Al + (size_t)m0*K;
    const __half* pBh = args.Bh[reg] + (size_t)n0*K;
    const __half* pBl = args.Bl[reg] + (size_t)n0*K;

    const uint32_t oAh = 0, oAl = 32768, oBh = 65536, oBl = 81920;
    const int arow = tid >> 3, acol = tid & 7;

    {
        #pragma unroll
        for (int i = 0; i < 8; i++){
            int r = arow + 32*i;
            cp16(sb + oAh + SWZ(r*128 + acol*16), pAh + (size_t)r*K + acol*8);
            cp16(sb + oAl + SWZ(r*128 + acol*16), pAl + (size_t)r*K + acol*8);
        }
        #pragma unroll
        for (int i = 0; i < 4; i++){
            int r = arow + 32*i;
            cp16(sb + oBh + SWZ(r*128 + acol*16), pBh + (size_t)r*K + acol*8);
            cp16(sb + oBl + SWZ(r*128 + acol*16), pBl + (size_t)r*K + acol*8);
        }
        asm volatile("cp.async.commit_group;" ::: "memory");
    }

    float acc[4][8][4];
    #pragma unroll
    for (int a = 0; a < 4; a++)
        #pragma unroll
        for (int b = 0; b < 8; b++)
            #pragma unroll
            for (int c = 0; c < 4; c++) acc[a][b][c] = 0.f;

    const int lrow = (lane & 7) + ((lane >> 3) & 1) * 8;
    const int koff = ((lane >> 4) & 1) * 16;

    for (int kt = 0; kt < KT; kt++){
        asm volatile("cp.async.wait_group 0;" ::: "memory");
        __syncthreads();

        uint32_t bufs = sb + (kt & 1) * 98304;

        if (kt + 1 < KT){
            uint32_t nbb = sb + ((kt + 1) & 1) * 98304;
            int k0 = (kt + 1) << 6;
            #pragma unroll
            for (int i = 0; i < 8; i++){
                int r = arow + 32*i;
                cp16(nbb + oAh + SWZ(r*128 + acol*16), pAh + (size_t)r*K + k0 + acol*8);
                cp16(nbb + oAl + SWZ(r*128 + acol*16), pAl + (size_t)r*K + k0 + acol*8);
            }
            #pragma unroll
            for (int i = 0; i < 4; i++){
                int r = arow + 32*i;
                cp16(nbb + oBh + SWZ(r*128 + acol*16), pBh + (size_t)r*K + k0 + acol*8);
                cp16(nbb + oBl + SWZ(r*128 + acol*16), pBl + (size_t)r*K + k0 + acol*8);
            }
            asm volatile("cp.async.commit_group;" ::: "memory");
        }

        #pragma unroll
        for (int ks = 0; ks < 4; ks++){
            const int kb = ks*32 + koff;
            uint32_t ah[4][4], al[4][4];
            #pragma unroll
            for (int mb = 0; mb < 4; mb++){
                int r = wm + mb*16 + lrow;
                ldm4(ah[mb], bufs + oAh + SWZ(r*128 + kb));
                ldm4(al[mb], bufs + oAl + SWZ(r*128 + kb));
            }
            #pragma unroll
            for (int nb = 0; nb < 4; nb++){
                uint32_t bh4[4], bl4[4];
                int r = wn + nb*16 + lrow;
                ldm4(bh4, bufs + oBh + SWZ(r*128 + kb));
                ldm4(bl4, bufs + oBl + SWZ(r*128 + kb));
                // term-grouped issue: same-acc reuse distance = 8
                #pragma unroll
                for (int mb = 0; mb < 4; mb++)
                    mma_hf(acc[mb][2*nb+0], ah[mb], bh4[0], bh4[2]);
                #pragma unroll
                for (int mb = 0; mb < 4; mb++)
                    mma_hf(acc[mb][2*nb+1], ah[mb], bh4[1], bh4[3]);
                #pragma unroll
                for (int mb = 0; mb < 4; mb++)
                    mma_hf(acc[mb][2*nb+0], al[mb], bh4[0], bh4[2]);
                #pragma unroll
                for (int mb = 0; mb < 4; mb++)
                    mma_hf(acc[mb][2*nb+1], al[mb], bh4[1], bh4[3]);
                #pragma unroll
                for (int mb = 0; mb < 4; mb++)
                    mma_hf(acc[mb][2*nb+0], ah[mb], bl4[0], bl4[2]);
                #pragma unroll
                for (int mb = 0; mb < 4; mb++)
                    mma_hf(acc[mb][2*nb+1], ah[mb], bl4[1], bl4[3]);
            }
        }
    }

    const float* bias = args.bias[reg];
    __half* Oh = args.Oh[reg];
    __half* Ol = args.Ol[reg];
    const int erow = lane >> 2, ecol = (lane & 3) * 2;
    #pragma unroll
    for (int mb = 0; mb < 4; mb++){
        #pragma unroll
        for (int nf = 0; nf < 8; nf++){
            int r = m0 + wm + mb*16 + erow;
            int cc = n0 + wn + nf*8 + ecol;
            float b0 = bias[cc], b1 = bias[cc+1];
            float2 v0 = make_float2(acc[mb][nf][0] + b0, acc[mb][nf][1] + b1);
            float2 v1 = make_float2(acc[mb][nf][2] + b0, acc[mb][nf][3] + b1);
            if (reg < 2){
                __half2 l0, l1;
                __half2 h0 = split_h2(v0.x, v0.y, &l0);
                __half2 h1 = split_h2(v1.x, v1.y, &l1);
                *(__half2*)(Oh + (size_t)r*N + cc)     = h0;
                *(__half2*)(Ol + (size_t)r*N + cc)     = l0;
                *(__half2*)(Oh + (size_t)(r+8)*N + cc) = h1;
                *(__half2*)(Ol + (size_t)(r+8)*N + cc) = l1;
            } else {
                *(__half2*)(Oh + (size_t)r*N + cc) =
                    __halves2half2(__float2half_rn(v0.x), __float2half_rn(v0.y));
                *(__half2*)(Oh + (size_t)(r+8)*N + cc) =
                    __halves2half2(__float2half_rn(v1.x), __float2half_rn(v1.y));
            }
        }
    }
}

// ---------------- 2-term GEMM: A single fp16, B hi/lo ------------------------
#define GSM2 (2*65536)
__global__ __launch_bounds__(256, 1)
void tcgemm2(const __half* __restrict__ A,
             const __half* __restrict__ Bh, const __half* __restrict__ Bl,
             const float* __restrict__ bias, float* __restrict__ C,
             __half* __restrict__ O16, int M, int N, int K, int relu)
{
    extern __shared__ __align__(1024) char smraw[];
    uint32_t sb = s2u(smraw);
    const int tid = threadIdx.x, wid = tid >> 5, lane = tid & 31;
    const int m0 = blockIdx.y*256, n0 = blockIdx.x*128;
    const int wm = (wid >> 1) * 64;
    const int wn = (wid & 1) * 64;

    const int KT = K >> 6;
    const __half* pA  = A  + (size_t)m0*K;
    const __half* pBh = Bh + (size_t)n0*K;
    const __half* pBl = Bl + (size_t)n0*K;

    const uint32_t oA = 0, oBh = 32768, oBl = 49152;
    const int arow = tid >> 3, acol = tid & 7;

    {
        #pragma unroll
        for (int i = 0; i < 8; i++){
            int r = arow + 32*i;
            cp16(sb + oA + SWZ(r*128 + acol*16), pA + (size_t)r*K + acol*8);
        }
        #pragma unroll
        for (int i = 0; i < 4; i++){
            int r = arow + 32*i;
            cp16(sb + oBh + SWZ(r*128 + acol*16), pBh + (size_t)r*K + acol*8);
            cp16(sb + oBl + SWZ(r*128 + acol*16), pBl + (size_t)r*K + acol*8);
        }
        asm volatile("cp.async.commit_group;" ::: "memory");
    }

    float acc[4][8][4];
    #pragma unroll
    for (int a = 0; a < 4; a++)
        #pragma unroll
        for (int b = 0; b < 8; b++)
            #pragma unroll
            for (int c = 0; c < 4; c++) acc[a][b][c] = 0.f;

    const int lrow = (lane & 7) + ((lane >> 3) & 1) * 8;
    const int koff = ((lane >> 4) & 1) * 16;

    for (int kt = 0; kt < KT; kt++){
        asm volatile("cp.async.wait_group 0;" ::: "memory");
        __syncthreads();

        uint32_t bufs = sb + (kt & 1) * 65536;

        if (kt + 1 < KT){
            uint32_t nbb = sb + ((kt + 1) & 1) * 65536;
            int k0 = (kt + 1) << 6;
            #pragma unroll
            for (int i = 0; i < 8; i++){
                int r = arow + 32*i;
                cp16(nbb + oA + SWZ(r*128 + acol*16), pA + (size_t)r*K + k0 + acol*8);
            }
            #pragma unroll
            for (int i = 0; i < 4; i++){
                int r = arow + 32*i;
                cp16(nbb + oBh + SWZ(r*128 + acol*16), pBh + (size_t)r*K + k0 + acol*8);
                cp16(nbb + oBl + SWZ(r*128 + acol*16), pBl + (size_t)r*K + k0 + acol*8);
            }
            asm volatile("cp.async.commit_group;" ::: "memory");
        }

        #pragma unroll
        for (int ks = 0; ks < 4; ks++){
            const int kb = ks*32 + koff;
            uint32_t ah[4][4];
            #pragma unroll
            for (int mb = 0; mb < 4; mb++){
                int r = wm + mb*16 + lrow;
                ldm4(ah[mb], bufs + oA + SWZ(r*128 + kb));
            }
            #pragma unroll
            for (int nb = 0; nb < 4; nb++){
                uint32_t bh4[4], bl4[4];
                int r = wn + nb*16 + lrow;
                ldm4(bh4, bufs + oBh + SWZ(r*128 + kb));
                ldm4(bl4, bufs + oBl + SWZ(r*128 + kb));
                // term-grouped issue: same-acc reuse distance = 8
                #pragma unroll
                for (int mb = 0; mb < 4; mb++)
                    mma_hf(acc[mb][2*nb+0], ah[mb], bh4[0], bh4[2]);
                #pragma unroll
                for (int mb = 0; mb < 4; mb++)
                    mma_hf(acc[mb][2*nb+1], ah[mb], bh4[1], bh4[3]);
                #pragma unroll
                for (int mb = 0; mb < 4; mb++)
                    mma_hf(acc[mb][2*nb+0], ah[mb], bl4[0], bl4[2]);
                #pragma unroll
                for (int mb = 0; mb < 4; mb++)
                    mma_hf(acc[mb][2*nb+1], ah[mb], bl4[1], bl4[3]);
            }
        }
    }

    const int erow = lane >> 2, ecol = (lane & 3) * 2;
    #pragma unroll
    for (int mb = 0; mb < 4; mb++){
        #pragma unroll
        for (int nf = 0; nf < 8; nf++){
            int r = m0 + wm + mb*16 + erow;
            int cc = n0 + wn + nf*8 + ecol;
            float b0 = bias[cc], b1 = bias[cc+1];
            float2 v0 = make_float2(acc[mb][nf][0] + b0, acc[mb][nf][1] + b1);
            float2 v1 = make_float2(acc[mb][nf][2] + b0, acc[mb][nf][3] + b1);
            if (relu){
                v0.x = fmaxf(v0.x, 0.f); v0.y = fmaxf(v0.y, 0.f);
                v1.x = fmaxf(v1.x, 0.f); v1.y = fmaxf(v1.y, 0.f);
            }
            if (C){
                *(float2*)(C + (size_t)r*N + cc)     = v0;
                *(float2*)(C + (size_t)(r+8)*N + cc) = v1;
            }
            if (O16){
                *(__half2*)(O16 + (size_t)r*N + cc) =
                    __halves2half2(__float2half_rn(v0.x), __float2half_rn(v0.y));
                *(__half2*)(O16 + (size_t)(r+8)*N + cc) =
                    __halves2half2(__float2half_rn(v1.x), __float2half_rn(v1.y));
            }
        }
    }
}

// ---------------- tensor-core flash attention (fp16) -------------------------
#define AT_SMEM 83968
__global__ __launch_bounds__(256, 1)
void attn_tc(const __half* __restrict__ Qh_, const __half* __restrict__ Ql_,
             const __half* __restrict__ Kh_, const __half* __restrict__ Kl_,
             const __half* __restrict__ V_,
             const int* __restrict__ mask, const float* __restrict__ btab,
             __half* __restrict__ O16)
{
    extern __shared__ __align__(1024) char smraw[];
    uint32_t sb = s2u(smraw);
    const int tid = threadIdx.x, wid = tid >> 5, lane = tid & 31;
    const int g = blockIdx.y, q0 = blockIdx.x * 128;
    const int hh_ = g & (HH-1), bb = g >> 4;
    const int wq = wid * 16;
    const int lr = lane >> 2, lq = lane & 3;
    const int lrow = (lane & 7) + ((lane >> 3) & 1) * 8;
    const int koff = ((lane >> 4) & 1) * 16;

    const uint32_t oQh = 0, oQl = 16384, oKV = 32768;
    float* sbias = (float*)(smraw + 81920);
    float* spen  = (float*)(smraw + 82816);

    const size_t gb = (size_t)g * SS * DHD;

    {
        const __half* qh = Qh_ + gb + (size_t)q0 * DHD;
        const __half* ql = Ql_ + gb + (size_t)q0 * DHD;
        #pragma unroll
        for (int i = 0; i < 4; i++){
            int c = tid + 256*i, row = c >> 3, col = c & 7;
            cp16(sb + oQh + SWZ(row*128 + col*16), qh + (size_t)row*64 + col*8);
            cp16(sb + oQl + SWZ(row*128 + col*16), ql + (size_t)row*64 + col*8);
        }
    }
    {
        uint32_t kvb = sb + oKV;
        const __half* srcs[3] = { Kh_ + gb, Kl_ + gb, V_ + gb };
        #pragma unroll
        for (int t = 0; t < 3; t++)
            #pragma unroll
            for (int i = 0; i < 2; i++){
                int c = tid + 256*i, row = c >> 3, col = c & 7;
                cp16(kvb + t*8192 + SWZ(row*128 + col*16), srcs[t] + (size_t)row*64 + col*8);
            }
    }
    asm volatile("cp.async.commit_group;" ::: "memory");

    float m0v = -1e30f, m1v = -1e30f, l0 = 0.f, l1 = 0.f;
    float o[8][4];
    #pragma unroll
    for (int i = 0; i < 8; i++)
        #pragma unroll
        for (int j = 0; j < 4; j++) o[i][j] = 0.f;

    for (int ch = 0; ch < 16; ch++){
        const int k0 = ch * 64;
        if (tid < 192){
            int idx = tid + q0 - k0 - 63 + (SS - 1);
            if (idx < 0) idx = 0;
            if (idx > 2*SS - 2) idx = 2*SS - 2;
            sbias[tid] = btab[idx*HH + hh_];
        }
        if (tid < 64) spen[tid] = (mask[bb*SS + k0 + tid] == 0) ? -1e30f : 0.f;

        if (ch + 1 < 16){
            uint32_t kvb = sb + oKV + ((ch+1)&1)*24576;
            const size_t off = gb + (size_t)(k0 + 64)*64;
            const __half* srcs[3] = { Kh_+off, Kl_+off, V_+off };
            #pragma unroll
            for (int t = 0; t < 3; t++)
                #pragma unroll
                for (int i = 0; i < 2; i++){
                    int c = tid + 256*i, row = c >> 3, col = c & 7;
                    cp16(kvb + t*8192 + SWZ(row*128 + col*16), srcs[t] + (size_t)row*64 + col*8);
                }
            asm volatile("cp.async.commit_group;" ::: "memory");
            asm volatile("cp.async.wait_group 1;" ::: "memory");
        } else {
            asm volatile("cp.async.wait_group 0;" ::: "memory");
        }
        __syncthreads();

        const uint32_t kvb = sb + oKV + (ch&1)*24576;

        float s_[8][4];
        #pragma unroll
        for (int i = 0; i < 8; i++)
            #pragma unroll
            for (int j = 0; j < 4; j++) s_[i][j] = 0.f;

        #pragma unroll
        for (int kb = 0; kb < 4; kb++){
            uint32_t qa[4], qb[4];
            ldm4(qa, sb + oQh + SWZ((wq+lrow)*128 + kb*32 + koff));
            ldm4(qb, sb + oQl + SWZ((wq+lrow)*128 + kb*32 + koff));
            // paired key blocks: same-acc reuse distance = 4
            #pragma unroll
            for (int jp = 0; jp < 2; jp++){
                int j0 = 2*jp, j1 = 2*jp + 1;
                uint32_t kh0[4], kl0[4], kh1[4], kl1[4];
                ldm4(kh0, kvb +        SWZ((j0*16+lrow)*128 + kb*32 + koff));
                ldm4(kl0, kvb + 8192 + SWZ((j0*16+lrow)*128 + kb*32 + koff));
                ldm4(kh1, kvb +        SWZ((j1*16+lrow)*128 + kb*32 + koff));
                ldm4(kl1, kvb + 8192 + SWZ((j1*16+lrow)*128 + kb*32 + koff));
                mma_hf(s_[2*j0],   qa, kh0[0], kh0[2]);
                mma_hf(s_[2*j1],   qa, kh1[0], kh1[2]);
                mma_hf(s_[2*j0+1], qa, kh0[1], kh0[3]);
                mma_hf(s_[2*j1+1], qa, kh1[1], kh1[3]);
                mma_hf(s_[2*j0],   qb, kh0[0], kh0[2]);
                mma_hf(s_[2*j1],   qb, kh1[0], kh1[2]);
                mma_hf(s_[2*j0+1], qb, kh0[1], kh0[3]);
                mma_hf(s_[2*j1+1], qb, kh1[1], kh1[3]);
                mma_hf(s_[2*j0],   qa, kl0[0], kl0[2]);
                mma_hf(s_[2*j1],   qa, kl1[0], kl1[2]);
                mma_hf(s_[2*j0+1], qa, kl0[1], kl0[3]);
                mma_hf(s_[2*j1+1], qa, kl1[1], kl1[3]);
            }
        }

        const int r0 = wq + lr, r1 = r0 + 8;
        #pragma unroll
        for (int nf = 0; nf < 8; nf++){
            int c0 = nf*8 + lq*2;
            s_[nf][0] += sbias[r0 - c0 + 63] + spen[c0];
            s_[nf][1] += sbias[r0 - c0 + 62] + spen[c0+1];
            s_[nf][2] += sbias[r1 - c0 + 63] + spen[c0];
            s_[nf][3] += sbias[r1 - c0 + 62] + spen[c0+1];
        }

        float mx0 = -1e30f, mx1 = -1e30f;
        #pragma unroll
        for (int nf = 0; nf < 8; nf++){
            mx0 = fmaxf(mx0, fmaxf(s_[nf][0], s_[nf][1]));
            mx1 = fmaxf(mx1, fmaxf(s_[nf][2], s_[nf][3]));
        }
        #pragma unroll
        for (int off = 1; off < 4; off <<= 1){
            mx0 = fmaxf(mx0, __shfl_xor_sync(0xffffffffu, mx0, off));
            mx1 = fmaxf(mx1, __shfl_xor_sync(0xffffffffu, mx1, off));
        }
        float mn0 = fmaxf(m0v, mx0), mn1 = fmaxf(m1v, mx1);
        float al0 = __expf(m0v - mn0), al1 = __expf(m1v - mn1);
        float sum0 = 0.f, sum1 = 0.f;
        #pragma unroll
        for (int nf = 0; nf < 8; nf++){
            s_[nf][0] = __expf(s_[nf][0] - mn0); sum0 += s_[nf][0];
            s_[nf][1] = __expf(s_[nf][1] - mn0); sum0 += s_[nf][1];
            s_[nf][2] = __expf(s_[nf][2] - mn1); sum1 += s_[nf][2];
            s_[nf][3] = __expf(s_[nf][3] - mn1); sum1 += s_[nf][3];
        }
        #pragma unroll
        for (int off = 1; off < 4; off <<= 1){
            sum0 += __shfl_xor_sync(0xffffffffu, sum0, off);
            sum1 += __shfl_xor_sync(0xffffffffu, sum1, off);
        }
        l0 = l0*al0 + sum0; l1 = l1*al1 + sum1;
        m0v = mn0; m1v = mn1;
        #pragma unroll
        for (int nf = 0; nf < 8; nf++){
            o[nf][0] *= al0; o[nf][1] *= al0;
            o[nf][2] *= al1; o[nf][3] *= al1;
        }

        #pragma unroll
        for (int kb = 0; kb < 4; kb++){
            uint32_t ph[4], pl[4];
            {
                __half2 t0l, t1l, t2l, t3l;
                __half2 t0 = split_h2(s_[2*kb][0],   s_[2*kb][1],   &t0l);
                __half2 t1 = split_h2(s_[2*kb][2],   s_[2*kb][3],   &t1l);
                __half2 t2 = split_h2(s_[2*kb+1][0], s_[2*kb+1][1], &t2l);
                __half2 t3 = split_h2(s_[2*kb+1][2], s_[2*kb+1][3], &t3l);
                ph[0] = h2u(t0);  ph[1] = h2u(t1);  ph[2] = h2u(t2);  ph[3] = h2u(t3);
                pl[0] = h2u(t0l); pl[1] = h2u(t1l); pl[2] = h2u(t2l); pl[3] = h2u(t3l);
            }
            // paired dim blocks: same-acc reuse distance = 4
            #pragma unroll
            for (int jp = 0; jp < 2; jp++){
                int j0 = 2*jp, j1 = 2*jp + 1;
                uint32_t v0[4], v1[4];
                ldm4t(v0, kvb + 16384 + SWZ((kb*16+lrow)*128 + j0*32 + koff));
                ldm4t(v1, kvb + 16384 + SWZ((kb*16+lrow)*128 + j1*32 + koff));
                mma_hf(o[2*j0],   ph, v0[0], v0[1]);
                mma_hf(o[2*j1],   ph, v1[0], v1[1]);
                mma_hf(o[2*j0+1], ph, v0[2], v0[3]);
                mma_hf(o[2*j1+1], ph, v1[2], v1[3]);
                mma_hf(o[2*j0],   pl, v0[0], v0[1]);
                mma_hf(o[2*j1],   pl, v1[0], v1[1]);
                mma_hf(o[2*j0+1], pl, v0[2], v0[3]);
                mma_hf(o[2*j1+1], pl, v1[2], v1[3]);
            }
        }
        __syncthreads();
    }

    const float inv0 = 1.f / l0, inv1 = 1.f / l1;
    const int tq0 = q0 + wq + lr, tq1 = tq0 + 8;
    const size_t b0 = (size_t)g*65536 + (size_t)tq0*64;
    const size_t b1 = (size_t)g*65536 + (size_t)tq1*64;
    #pragma unroll
    for (int nf = 0; nf < 8; nf++){
        int d0 = nf*8 + lq*2;
        *(__half2*)(O16 + b0 + d0) = __halves2half2(
            __float2half_rn(o[nf][0]*inv0), __float2half_rn(o[nf][1]*inv0));
        *(__half2*)(O16 + b1 + d0) = __halves2half2(
            __float2half_rn(o[nf][2]*inv1), __float2half_rn(o[nf][3]*inv1));
    }
}

// ---------------- LayerNorm with residual (register-resident) ----------------
__global__ __launch_bounds__(256)
void ln_kernel(const float4* __restrict__ A, const float4* __restrict__ R,
               const float4* __restrict__ gamma, const float4* __restrict__ beta,
               float4* __restrict__ Out, __half* __restrict__ O16)
{
    __shared__ float red[8];
    const int row = blockIdx.x, tid = threadIdx.x;
    const size_t base = (size_t)row * (DD/4);

    float4 a = A[base + tid], r4 = R[base + tid];
    float x0 = a.x + r4.x, x1 = a.y + r4.y, x2 = a.z + r4.z, x3 = a.w + r4.w;

    float lsum = x0 + x1 + x2 + x3;
    #pragma unroll
    for (int off = 16; off; off >>= 1) lsum += __shfl_xor_sync(0xffffffffu, lsum, off);
    if ((tid & 31) == 0) red[tid >> 5] = lsum;
    __syncthreads();
    float tot = 0.f;
    #pragma unroll
    for (int w = 0; w < 8; w++) tot += red[w];
    float mu = tot * (1.f / DD);
    __syncthreads();

    float d0 = x0-mu, d1 = x1-mu, d2 = x2-mu, d3 = x3-mu;
    float lsq = d0*d0 + d1*d1 + d2*d2 + d3*d3;
    #pragma unroll
    for (int off = 16; off; off >>= 1) lsq += __shfl_xor_sync(0xffffffffu, lsq, off);
    if ((tid & 31) == 0) red[tid >> 5] = lsq;
    __syncthreads();
    float vt = 0.f;
    #pragma unroll
    for (int w = 0; w < 8; w++) vt += red[w];
    float inv = rsqrtf(vt * (1.f / DD) + 1e-5f);

    float4 g = gamma[tid], b = beta[tid];
    float4 v;
    v.x = g.x * d0 * inv + b.x;
    v.y = g.y * d1 * inv + b.y;
    v.z = g.z * d2 * inv + b.z;
    v.w = g.w * d3 * inv + b.w;
    Out[base + tid] = v;
    if (O16){
        __half2* ph = (__half2*)(O16 + (size_t)row*DD + tid*4);
        ph[0] = __halves2half2(__float2half_rn(v.x), __float2half_rn(v.y));
        ph[1] = __halves2half2(__float2half_rn(v.z), __float2half_rn(v.w));
    }
}

// ---------------- launch ----------------------------------------------------
extern "C" void kernel_launch(void* const* d_in, const int* in_sizes, int n_in,
                              void* d_out, int out_size)
{
    const float* x    = (const float*)d_in[0];
    const int*   mask = (const int*)  d_in[1];
    const float* Wq = (const float*)d_in[2];  const float* bq = (const float*)d_in[3];
    const float* Wk = (const float*)d_in[4];  const float* bk = (const float*)d_in[5];
    const float* Wv = (const float*)d_in[6];  const float* bv = (const float*)d_in[7];
    const float* Wo = (const float*)d_in[8];  const float* bo = (const float*)d_in[9];
    const float* rel_bias = (const float*)d_in[10];
    const float* ln1g = (const float*)d_in[11]; const float* ln1b = (const float*)d_in[12];
    const float* W1 = (const float*)d_in[13]; const float* b1 = (const float*)d_in[14];
    const float* W2 = (const float*)d_in[15]; const float* b2 = (const float*)d_in[16];
    const float* ln2g = (const float*)d_in[17]; const float* ln2b = (const float*)d_in[18];
    float* out = (float*)d_out;

    float *tmp, *h, *btab;
    cudaGetSymbolAddress((void**)&tmp,  g_tmp);
    cudaGetSymbolAddress((void**)&h,    g_h);
    cudaGetSymbolAddress((void**)&btab, g_btab);

    __half *xh,*xl, *qh,*ql, *kh,*kl, *v16, *att16, *h16, *f16;
    __half *wqh,*wql,*wkh,*wkl,*wvh,*wvl,*woh,*wol,*w1h,*w1l,*w2h,*w2l;
    cudaGetSymbolAddress((void**)&xh,   g_xh);   cudaGetSymbolAddress((void**)&xl,   g_xl);
    cudaGetSymbolAddress((void**)&qh,   g_qh);   cudaGetSymbolAddress((void**)&ql,   g_ql);
    cudaGetSymbolAddress((void**)&kh,   g_kh);   cudaGetSymbolAddress((void**)&kl,   g_kl);
    cudaGetSymbolAddress((void**)&v16,  g_v16);
    cudaGetSymbolAddress((void**)&att16,g_att16);
    cudaGetSymbolAddress((void**)&h16,  g_h16);
    cudaGetSymbolAddress((void**)&f16,  g_f16);
    cudaGetSymbolAddress((void**)&wqh,  g_wqh);  cudaGetSymbolAddress((void**)&wql,  g_wql);
    cudaGetSymbolAddress((void**)&wkh,  g_wkh);  cudaGetSymbolAddress((void**)&wkl,  g_wkl);
    cudaGetSymbolAddress((void**)&wvh,  g_wvh);  cudaGetSymbolAddress((void**)&wvl,  g_wvl);
    cudaGetSymbolAddress((void**)&woh,  g_woh);  cudaGetSymbolAddress((void**)&wol,  g_wol);
    cudaGetSymbolAddress((void**)&w1h,  g_w1h);  cudaGetSymbolAddress((void**)&w1l,  g_w1l);
    cudaGetSymbolAddress((void**)&w2h,  g_w2h);  cudaGetSymbolAddress((void**)&w2l,  g_w2l);

    cudaFuncSetAttribute(qkv_gemm, cudaFuncAttributeMaxDynamicSharedMemorySize, GSM3);
    cudaFuncSetAttribute(tcgemm2,  cudaFuncAttributeMaxDynamicSharedMemorySize, GSM2);
    cudaFuncSetAttribute(attn_tc,  cudaFuncAttributeMaxDynamicSharedMemorySize, AT_SMEM);

    bias_table_kernel<<<(2*SS - 1 + 255)/256, 256>>>(rel_bias, btab);
    split_kernel<<<(MR*DD/4 + 255)/256, 256>>>((const float4*)x, xh, xl, MR*DD/4);
    {
        TransArgs ta;
        const float* srcs[6] = {Wq, Wk, Wv, Wo, W1, W2};
        __half* dh[6] = {wqh, wkh, wvh, woh, w1h, w2h};
        __half* dl[6] = {wql, wkl, wvl, wol, w1l, w2l};
        int Ks[6] = {DD, DD, DD, DD, DD, FF};
        int Ns[6] = {DD, DD, DD, DD, FF, DD};
        int bases[6] = {0, 1024, 2048, 3072, 4096, 8192};
        for (int i = 0; i < 6; i++){
            ta.src[i] = srcs[i]; ta.dh[i] = dh[i]; ta.dl[i] = dl[i];
            ta.K[i] = Ks[i]; ta.N[i] = Ns[i]; ta.base[i] = bases[i];
        }
        transpose_all<<<12288, dim3(32, 8)>>>(ta);
    }
    {
        QKVArgs qa;
        qa.Bh[0] = wqh; qa.Bl[0] = wql; qa.bias[0] = bq; qa.Oh[0] = qh;  qa.Ol[0] = ql;
        qa.Bh[1] = wkh; qa.Bl[1] = wkl; qa.bias[1] = bk; qa.Oh[1] = kh;  qa.Ol[1] = kl;
        qa.Bh[2] = wvh; qa.Bl[2] = wvl; qa.bias[2] = bv; qa.Oh[2] = v16; qa.Ol[2] = nullptr;
        qkv_gemm<<<dim3(24, MR/256), 256, GSM3>>>(xh, xl, qa, MR, DD);
    }
    attn_tc<<<dim3(SS/128, NG), 256, AT_SMEM>>>(qh, ql, kh, kl, v16,
                                                mask, btab, att16);
    tcgemm2<<<dim3(DD/128, MR/256), 256, GSM2>>>(att16, woh, wol, bo, tmp,
                                                 nullptr, MR, DD, DD, 0);
    ln_kernel<<<MR, 256>>>((const float4*)tmp, (const float4*)x,
                           (const float4*)ln1g, (const float4*)ln1b,
                           (float4*)h, h16);
    tcgemm2<<<dim3(FF/128, MR/256), 256, GSM2>>>(h16, w1h, w1l, b1, nullptr,
                                                 f16, MR, FF, DD, 1);
    tcgemm2<<<dim3(DD/128, MR/256), 256, GSM2>>>(f16, w2h, w2l, b2, tmp,
                                                 nullptr, MR, DD, FF, 0);
    ln_kernel<<<MR, 256>>>((const float4*)tmp, (const float4*)h,
                           (const float4*)ln2g, (const float4*)ln2b,
                           (float4*)out, nullptr);
}

// round 10
// speedup vs baseline: 3.9348x; 1.0652x over previous
#include <cuda_runtime.h>
#include <cuda_fp16.h>
#include <math.h>
#include <stdint.h>

#define BB 4
#define SS 1024
#define DD 1024
#define HH 16
#define FF 4096
#define DHD 64
#define NG (BB*HH)
#define MR (BB*SS)

// ---------------- scratch (static device globals; no allocation) -------------
__device__ float g_tmp[MR*DD];
__device__ float g_h[MR*DD];
__device__ float g_btab[(2*SS-1)*HH];

__device__ __half g_xh[MR*DD],  g_xl[MR*DD];
__device__ __half g_qh[MR*DD],  g_ql[MR*DD];
__device__ __half g_kh[MR*DD],  g_kl[MR*DD];
__device__ __half g_v16[MR*DD];
__device__ __half g_att16[MR*DD];
__device__ __half g_h16[MR*DD];
__device__ __half g_f16[(size_t)MR*FF];
__device__ __half g_wqh[DD*DD], g_wql[DD*DD];
__device__ __half g_wkh[DD*DD], g_wkl[DD*DD];
__device__ __half g_wvh[DD*DD], g_wvl[DD*DD];
__device__ __half g_woh[DD*DD], g_wol[DD*DD];
__device__ __half g_w1h[(size_t)DD*FF], g_w1l[(size_t)DD*FF];
__device__ __half g_w2h[(size_t)FF*DD], g_w2l[(size_t)FF*DD];

// ---------------- PTX helpers ------------------------------------------------
#define SWZ(o) ((o) ^ (((o) >> 3) & 0x70))

__device__ __forceinline__ uint32_t s2u(const void* p){
    uint32_t a;
    asm("{ .reg .u64 t; cvta.to.shared.u64 t, %1; cvt.u32.u64 %0, t; }"
        : "=r"(a) : "l"(p));
    return a;
}
__device__ __forceinline__ void cp16(uint32_t d, const void* s){
    asm volatile("cp.async.cg.shared.global [%0], [%1], 16;" :: "r"(d), "l"(s));
}
__device__ __forceinline__ void ldm4(uint32_t* r, uint32_t a){
    asm volatile("ldmatrix.sync.aligned.m8n8.x4.shared.b16 {%0,%1,%2,%3}, [%4];"
        : "=r"(r[0]), "=r"(r[1]), "=r"(r[2]), "=r"(r[3]) : "r"(a));
}
__device__ __forceinline__ void ldm4t(uint32_t* r, uint32_t a){
    asm volatile("ldmatrix.sync.aligned.m8n8.x4.trans.shared.b16 {%0,%1,%2,%3}, [%4];"
        : "=r"(r[0]), "=r"(r[1]), "=r"(r[2]), "=r"(r[3]) : "r"(a));
}
__device__ __forceinline__ void mma_hf(float* c, const uint32_t* a,
                                       uint32_t b0, uint32_t b1){
    asm volatile("mma.sync.aligned.m16n8k16.row.col.f32.f16.f16.f32 "
        "{%0,%1,%2,%3}, {%4,%5,%6,%7}, {%8,%9}, {%0,%1,%2,%3};"
        : "+f"(c[0]), "+f"(c[1]), "+f"(c[2]), "+f"(c[3])
        : "r"(a[0]), "r"(a[1]), "r"(a[2]), "r"(a[3]), "r"(b0), "r"(b1));
}
__device__ __forceinline__ uint32_t h2u(__half2 v){ return *(uint32_t*)&v; }

__device__ __forceinline__ __half2 split_h2(float a, float b, __half2* lo){
    __half h0 = __float2half_rn(a), h1 = __float2half_rn(b);
    *lo = __halves2half2(__float2half_rn(a - __half2float(h0)),
                         __float2half_rn(b - __half2float(h1)));
    return __halves2half2(h0, h1);
}

// ---------------- relative-position bias table ------------------------------
__global__ void bias_table_kernel(const float* __restrict__ rel_bias,
                                  float* __restrict__ tab)
{
    int r = blockIdx.x * blockDim.x + threadIdx.x;
    if (r >= 2*SS - 1) return;
    int rel = r - (SS - 1);
    int n = -rel;
    int ret = (n < 0) ? 16 : 0;
    int na = n < 0 ? -n : n;
    int bucket;
    if (na < 8) {
        bucket = ret + na;
    } else {
        double v = log((double)na / 8.0) / log(16.0) * 8.0;
        int vi = 8 + (int)v;
        if (vi > 15) vi = 15;
        bucket = ret + vi;
    }
    #pragma unroll
    for (int h = 0; h < HH; h++) tab[r*HH + h] = rel_bias[bucket*HH + h];
}

// ---------------- fp32 -> fp16 hi/lo split -----------------------------------
__global__ __launch_bounds__(256)
void split_kernel(const float4* __restrict__ in, __half* __restrict__ oh,
                  __half* __restrict__ ol, int n4)
{
    int i = blockIdx.x * 256 + threadIdx.x;
    if (i >= n4) return;
    float4 v = in[i];
    __half2 l0, l1;
    __half2 h0 = split_h2(v.x, v.y, &l0);
    __half2 h1 = split_h2(v.z, v.w, &l1);
    __half2* po = (__half2*)(oh + (size_t)i*4);
    __half2* pl = (__half2*)(ol + (size_t)i*4);
    po[0] = h0; po[1] = h1;
    pl[0] = l0; pl[1] = l1;
}

// ---------------- fused transpose+split of all 6 weights ---------------------
struct TransArgs {
    const float* src[6];
    __half* dh[6];
    __half* dl[6];
    int K[6], N[6], base[6];
};
__global__ __launch_bounds__(256)
void transpose_all(TransArgs a)
{
    __shared__ float t[32][33];
    int bt = blockIdx.x;
    int reg = (bt < 1024) ? 0 : (bt < 2048) ? 1 : (bt < 3072) ? 2 :
              (bt < 4096) ? 3 : (bt < 8192) ? 4 : 5;
    int local = bt - a.base[reg];
    int K = a.K[reg], N = a.N[reg];
    int ntiles = N >> 5;
    int n0 = (local % ntiles) * 32, k0 = (local / ntiles) * 32;

    const float* in = a.src[reg];
    __half* oh = a.dh[reg];
    __half* ol = a.dl[reg];

    int tx = threadIdx.x, ty = threadIdx.y;
    #pragma unroll
    for (int i = 0; i < 32; i += 8)
        t[ty+i][tx] = in[(size_t)(k0+ty+i)*N + n0+tx];
    __syncthreads();
    #pragma unroll
    for (int i = 0; i < 32; i += 8){
        float v = t[tx][ty+i];
        __half h = __float2half_rn(v);
        oh[(size_t)(n0+ty+i)*K + k0+tx] = h;
        ol[(size_t)(n0+ty+i)*K + k0+tx] = __float2half_rn(v - __half2float(h));
    }
}

// ---------------- fused QKV GEMM (fp16 3-term) -------------------------------
// 128 threads, CTA 128x64, warp tile 64x32 (2x2 warps), BK=64, 2-stage.
// Stage: Ah 16K | Al 16K | Bh 8K | Bl 8K = 48K; 2 CTAs/SM.
struct QKVArgs {
    const __half* Bh[3]; const __half* Bl[3];
    const float*  bias[3];
    __half* Oh[3]; __half* Ol[3];
};
#define GSM3 (2*49152)
__global__ __launch_bounds__(128, 2)
void qkv_gemm(const __half* __restrict__ Ah, const __half* __restrict__ Al,
              QKVArgs args, int M, int K)
{
    extern __shared__ __align__(1024) char smraw[];
    uint32_t sb = s2u(smraw);
    const int tid = threadIdx.x, wid = tid >> 5, lane = tid & 31;
    const int reg = blockIdx.x >> 4;
    const int n0 = (blockIdx.x & 15) * 64;
    const int m0 = blockIdx.y * 128;
    const int wm = (wid >> 1) * 64;
    const int wn = (wid & 1) * 32;
    const int N = DD;

    const int KT = K >> 6;
    const __half* pAh = Ah + (size_t)m0*K;
    const __half* pAl = Al + (size_t)m0*K;
    const __half* pBh = args.Bh[reg] + (size_t)n0*K;
    const __half* pBl = args.Bl[reg] + (size_t)n0*K;

    const uint32_t oAh = 0, oAl = 16384, oBh = 32768, oBl = 40960;
    const int arow = tid >> 3, acol = tid & 7;   // 16 rows/pass, 8 chunks/row

    {
        #pragma unroll
        for (int i = 0; i < 8; i++){
            int r = arow + 16*i;
            cp16(sb + oAh + SWZ(r*128 + acol*16), pAh + (size_t)r*K + acol*8);
            cp16(sb + oAl + SWZ(r*128 + acol*16), pAl + (size_t)r*K + acol*8);
        }
        #pragma unroll
        for (int i = 0; i < 4; i++){
            int r = arow + 16*i;
            cp16(sb + oBh + SWZ(r*128 + acol*16), pBh + (size_t)r*K + acol*8);
            cp16(sb + oBl + SWZ(r*128 + acol*16), pBl + (size_t)r*K + acol*8);
        }
        asm volatile("cp.async.commit_group;" ::: "memory");
    }

    float acc[4][4][4];
    #pragma unroll
    for (int a = 0; a < 4; a++)
        #pragma unroll
        for (int b = 0; b < 4; b++)
            #pragma unroll
            for (int c = 0; c < 4; c++) acc[a][b][c] = 0.f;

    const int lrow = (lane & 7) + ((lane >> 3) & 1) * 8;
    const int koff = ((lane >> 4) & 1) * 16;

    for (int kt = 0; kt < KT; kt++){
        asm volatile("cp.async.wait_group 0;" ::: "memory");
        __syncthreads();

        uint32_t bufs = sb + (kt & 1) * 49152;

        if (kt + 1 < KT){
            uint32_t nbb = sb + ((kt + 1) & 1) * 49152;
            int k0 = (kt + 1) << 6;
            #pragma unroll
            for (int i = 0; i < 8; i++){
                int r = arow + 16*i;
                cp16(nbb + oAh + SWZ(r*128 + acol*16), pAh + (size_t)r*K + k0 + acol*8);
                cp16(nbb + oAl + SWZ(r*128 + acol*16), pAl + (size_t)r*K + k0 + acol*8);
            }
            #pragma unroll
            for (int i = 0; i < 4; i++){
                int r = arow + 16*i;
                cp16(nbb + oBh + SWZ(r*128 + acol*16), pBh + (size_t)r*K + k0 + acol*8);
                cp16(nbb + oBl + SWZ(r*128 + acol*16), pBl + (size_t)r*K + k0 + acol*8);
            }
            asm volatile("cp.async.commit_group;" ::: "memory");
        }

        #pragma unroll
        for (int ks = 0; ks < 4; ks++){
            const int kb = ks*32 + koff;
            uint32_t ah[4][4], al[4][4];
            #pragma unroll
            for (int mb = 0; mb < 4; mb++){
                int r = wm + mb*16 + lrow;
                ldm4(ah[mb], bufs + oAh + SWZ(r*128 + kb));
                ldm4(al[mb], bufs + oAl + SWZ(r*128 + kb));
            }
            #pragma unroll
            for (int nb = 0; nb < 2; nb++){
                uint32_t bh4[4], bl4[4];
                int r = wn + nb*16 + lrow;
                ldm4(bh4, bufs + oBh + SWZ(r*128 + kb));
                ldm4(bl4, bufs + oBl + SWZ(r*128 + kb));
                #pragma unroll
                for (int mb = 0; mb < 4; mb++)
                    mma_hf(acc[mb][2*nb+0], ah[mb], bh4[0], bh4[2]);
                #pragma unroll
                for (int mb = 0; mb < 4; mb++)
                    mma_hf(acc[mb][2*nb+1], ah[mb], bh4[1], bh4[3]);
                #pragma unroll
                for (int mb = 0; mb < 4; mb++)
                    mma_hf(acc[mb][2*nb+0], al[mb], bh4[0], bh4[2]);
                #pragma unroll
                for (int mb = 0; mb < 4; mb++)
                    mma_hf(acc[mb][2*nb+1], al[mb], bh4[1], bh4[3]);
                #pragma unroll
                for (int mb = 0; mb < 4; mb++)
                    mma_hf(acc[mb][2*nb+0], ah[mb], bl4[0], bl4[2]);
                #pragma unroll
                for (int mb = 0; mb < 4; mb++)
                    mma_hf(acc[mb][2*nb+1], ah[mb], bl4[1], bl4[3]);
            }
        }
    }

    const float* bias = args.bias[reg];
    __half* Oh = args.Oh[reg];
    __half* Ol = args.Ol[reg];
    const int erow = lane >> 2, ecol = (lane & 3) * 2;
    #pragma unroll
    for (int mb = 0; mb < 4; mb++){
        #pragma unroll
        for (int nf = 0; nf < 4; nf++){
            int r = m0 + wm + mb*16 + erow;
            int cc = n0 + wn + nf*8 + ecol;
            float b0 = bias[cc], b1 = bias[cc+1];
            float2 v0 = make_float2(acc[mb][nf][0] + b0, acc[mb][nf][1] + b1);
            float2 v1 = make_float2(acc[mb][nf][2] + b0, acc[mb][nf][3] + b1);
            if (reg < 2){
                __half2 l0, l1;
                __half2 h0 = split_h2(v0.x, v0.y, &l0);
                __half2 h1 = split_h2(v1.x, v1.y, &l1);
                *(__half2*)(Oh + (size_t)r*N + cc)     = h0;
                *(__half2*)(Ol + (size_t)r*N + cc)     = l0;
                *(__half2*)(Oh + (size_t)(r+8)*N + cc) = h1;
                *(__half2*)(Ol + (size_t)(r+8)*N + cc) = l1;
            } else {
                *(__half2*)(Oh + (size_t)r*N + cc) =
                    __halves2half2(__float2half_rn(v0.x), __float2half_rn(v0.y));
                *(__half2*)(Oh + (size_t)(r+8)*N + cc) =
                    __halves2half2(__float2half_rn(v1.x), __float2half_rn(v1.y));
            }
        }
    }
}

// ---------------- 2-term GEMM: A single fp16, B hi/lo ------------------------
// 128 threads, CTA 128x128, warp tile 64x64 (2x2 warps), BK=64, 2-stage.
// Stage: A 16K | Bh 16K | Bl 16K = 48K; 2 CTAs/SM.
#define GSM2 (2*49152)
__global__ __launch_bounds__(128, 2)
void tcgemm2(const __half* __restrict__ A,
             const __half* __restrict__ Bh, const __half* __restrict__ Bl,
             const float* __restrict__ bias, float* __restrict__ C,
             __half* __restrict__ O16, int M, int N, int K, int relu)
{
    extern __shared__ __align__(1024) char smraw[];
    uint32_t sb = s2u(smraw);
    const int tid = threadIdx.x, wid = tid >> 5, lane = tid & 31;
    const int m0 = blockIdx.y*128, n0 = blockIdx.x*128;
    const int wm = (wid >> 1) * 64;
    const int wn = (wid & 1) * 64;

    const int KT = K >> 6;
    const __half* pA  = A  + (size_t)m0*K;
    const __half* pBh = Bh + (size_t)n0*K;
    const __half* pBl = Bl + (size_t)n0*K;

    const uint32_t oA = 0, oBh = 16384, oBl = 32768;
    const int arow = tid >> 3, acol = tid & 7;

    {
        #pragma unroll
        for (int i = 0; i < 8; i++){
            int r = arow + 16*i;
            cp16(sb + oA  + SWZ(r*128 + acol*16), pA  + (size_t)r*K + acol*8);
            cp16(sb + oBh + SWZ(r*128 + acol*16), pBh + (size_t)r*K + acol*8);
            cp16(sb + oBl + SWZ(r*128 + acol*16), pBl + (size_t)r*K + acol*8);
        }
        asm volatile("cp.async.commit_group;" ::: "memory");
    }

    float acc[4][8][4];
    #pragma unroll
    for (int a = 0; a < 4; a++)
        #pragma unroll
        for (int b = 0; b < 8; b++)
            #pragma unroll
            for (int c = 0; c < 4; c++) acc[a][b][c] = 0.f;

    const int lrow = (lane & 7) + ((lane >> 3) & 1) * 8;
    const int koff = ((lane >> 4) & 1) * 16;

    for (int kt = 0; kt < KT; kt++){
        asm volatile("cp.async.wait_group 0;" ::: "memory");
        __syncthreads();

        uint32_t bufs = sb + (kt & 1) * 49152;

        if (kt + 1 < KT){
            uint32_t nbb = sb + ((kt + 1) & 1) * 49152;
            int k0 = (kt + 1) << 6;
            #pragma unroll
            for (int i = 0; i < 8; i++){
                int r = arow + 16*i;
                cp16(nbb + oA  + SWZ(r*128 + acol*16), pA  + (size_t)r*K + k0 + acol*8);
                cp16(nbb + oBh + SWZ(r*128 + acol*16), pBh + (size_t)r*K + k0 + acol*8);
                cp16(nbb + oBl + SWZ(r*128 + acol*16), pBl + (size_t)r*K + k0 + acol*8);
            }
            asm volatile("cp.async.commit_group;" ::: "memory");
        }

        #pragma unroll
        for (int ks = 0; ks < 4; ks++){
            const int kb = ks*32 + koff;
            uint32_t ah[4][4];
            #pragma unroll
            for (int mb = 0; mb < 4; mb++){
                int r = wm + mb*16 + lrow;
                ldm4(ah[mb], bufs + oA + SWZ(r*128 + kb));
            }
            #pragma unroll
            for (int nb = 0; nb < 4; nb++){
                uint32_t bh4[4], bl4[4];
                int r = wn + nb*16 + lrow;
                ldm4(bh4, bufs + oBh + SWZ(r*128 + kb));
                ldm4(bl4, bufs + oBl + SWZ(r*128 + kb));
                #pragma unroll
                for (int mb = 0; mb < 4; mb++)
                    mma_hf(acc[mb][2*nb+0], ah[mb], bh4[0], bh4[2]);
                #pragma unroll
                for (int mb = 0; mb < 4; mb++)
                    mma_hf(acc[mb][2*nb+1], ah[mb], bh4[1], bh4[3]);
                #pragma unroll
                for (int mb = 0; mb < 4; mb++)
                    mma_hf(acc[mb][2*nb+0], ah[mb], bl4[0], bl4[2]);
                #pragma unroll
                for (int mb = 0; mb < 4; mb++)
                    mma_hf(acc[mb][2*nb+1], ah[mb], bl4[1], bl4[3]);
            }
        }
    }

    const int erow = lane >> 2, ecol = (lane & 3) * 2;
    #pragma unroll
    for (int mb = 0; mb < 4; mb++){
        #pragma unroll
        for (int nf = 0; nf < 8; nf++){
            int r = m0 + wm + mb*16 + erow;
            int cc = n0 + wn + nf*8 + ecol;
            float b0 = bias[cc], b1 = bias[cc+1];
            float2 v0 = make_float2(acc[mb][nf][0] + b0, acc[mb][nf][1] + b1);
            float2 v1 = make_float2(acc[mb][nf][2] + b0, acc[mb][nf][3] + b1);
            if (relu){
                v0.x = fmaxf(v0.x, 0.f); v0.y = fmaxf(v0.y, 0.f);
                v1.x = fmaxf(v1.x, 0.f); v1.y = fmaxf(v1.y, 0.f);
            }
            if (C){
                *(float2*)(C + (size_t)r*N + cc)     = v0;
                *(float2*)(C + (size_t)(r+8)*N + cc) = v1;
            }
            if (O16){
                *(__half2*)(O16 + (size_t)r*N + cc) =
                    __halves2half2(__float2half_rn(v0.x), __float2half_rn(v0.y));
                *(__half2*)(O16 + (size_t)(r+8)*N + cc) =
                    __halves2half2(__float2half_rn(v1.x), __float2half_rn(v1.y));
            }
        }
    }
}

// ---------------- tensor-core flash attention (fp16) -------------------------
#define AT_SMEM 83968
__global__ __launch_bounds__(256, 1)
void attn_tc(const __half* __restrict__ Qh_, const __half* __restrict__ Ql_,
             const __half* __restrict__ Kh_, const __half* __restrict__ Kl_,
             const __half* __restrict__ V_,
             const int* __restrict__ mask, const float* __restrict__ btab,
             __half* __restrict__ O16)
{
    extern __shared__ __align__(1024) char smraw[];
    uint32_t sb = s2u(smraw);
    const int tid = threadIdx.x, wid = tid >> 5, lane = tid & 31;
    const int g = blockIdx.y, q0 = blockIdx.x * 128;
    const int hh_ = g & (HH-1), bb = g >> 4;
    const int wq = wid * 16;
    const int lr = lane >> 2, lq = lane & 3;
    const int lrow = (lane & 7) + ((lane >> 3) & 1) * 8;
    const int koff = ((lane >> 4) & 1) * 16;

    const uint32_t oQh = 0, oQl = 16384, oKV = 32768;
    float* sbias = (float*)(smraw + 81920);
    float* spen  = (float*)(smraw + 82816);

    const size_t gb = (size_t)g * SS * DHD;

    {
        const __half* qh = Qh_ + gb + (size_t)q0 * DHD;
        const __half* ql = Ql_ + gb + (size_t)q0 * DHD;
        #pragma unroll
        for (int i = 0; i < 4; i++){
            int c = tid + 256*i, row = c >> 3, col = c & 7;
            cp16(sb + oQh + SWZ(row*128 + col*16), qh + (size_t)row*64 + col*8);
            cp16(sb + oQl + SWZ(row*128 + col*16), ql + (size_t)row*64 + col*8);
        }
    }
    {
        uint32_t kvb = sb + oKV;
        const __half* srcs[3] = { Kh_ + gb, Kl_ + gb, V_ + gb };
        #pragma unroll
        for (int t = 0; t < 3; t++)
            #pragma unroll
            for (int i = 0; i < 2; i++){
                int c = tid + 256*i, row = c >> 3, col = c & 7;
                cp16(kvb + t*8192 + SWZ(row*128 + col*16), srcs[t] + (size_t)row*64 + col*8);
            }
    }
    asm volatile("cp.async.commit_group;" ::: "memory");

    float m0v = -1e30f, m1v = -1e30f, l0 = 0.f, l1 = 0.f;
    float o[8][4];
    #pragma unroll
    for (int i = 0; i < 8; i++)
        #pragma unroll
        for (int j = 0; j < 4; j++) o[i][j] = 0.f;

    for (int ch = 0; ch < 16; ch++){
        const int k0 = ch * 64;
        if (tid < 192){
            int idx = tid + q0 - k0 - 63 + (SS - 1);
            if (idx < 0) idx = 0;
            if (idx > 2*SS - 2) idx = 2*SS - 2;
            sbias[tid] = btab[idx*HH + hh_];
        }
        if (tid < 64) spen[tid] = (mask[bb*SS + k0 + tid] == 0) ? -1e30f : 0.f;

        if (ch + 1 < 16){
            uint32_t kvb = sb + oKV + ((ch+1)&1)*24576;
            const size_t off = gb + (size_t)(k0 + 64)*64;
            const __half* srcs[3] = { Kh_+off, Kl_+off, V_+off };
            #pragma unroll
            for (int t = 0; t < 3; t++)
                #pragma unroll
                for (int i = 0; i < 2; i++){
                    int c = tid + 256*i, row = c >> 3, col = c & 7;
                    cp16(kvb + t*8192 + SWZ(row*128 + col*16), srcs[t] + (size_t)row*64 + col*8);
                }
            asm volatile("cp.async.commit_group;" ::: "memory");
            asm volatile("cp.async.wait_group 1;" ::: "memory");
        } else {
            asm volatile("cp.async.wait_group 0;" ::: "memory");
        }
        __syncthreads();

        const uint32_t kvb = sb + oKV + (ch&1)*24576;

        float s_[8][4];
        #pragma unroll
        for (int i = 0; i < 8; i++)
            #pragma unroll
            for (int j = 0; j < 4; j++) s_[i][j] = 0.f;

        #pragma unroll
        for (int kb = 0; kb < 4; kb++){
            uint32_t qa[4], qb[4];
            ldm4(qa, sb + oQh + SWZ((wq+lrow)*128 + kb*32 + koff));
            ldm4(qb, sb + oQl + SWZ((wq+lrow)*128 + kb*32 + koff));
            #pragma unroll
            for (int jp = 0; jp < 2; jp++){
                int j0 = 2*jp, j1 = 2*jp + 1;
                uint32_t kh0[4], kl0[4], kh1[4], kl1[4];
                ldm4(kh0, kvb +        SWZ((j0*16+lrow)*128 + kb*32 + koff));
                ldm4(kl0, kvb + 8192 + SWZ((j0*16+lrow)*128 + kb*32 + koff));
                ldm4(kh1, kvb +        SWZ((j1*16+lrow)*128 + kb*32 + koff));
                ldm4(kl1, kvb + 8192 + SWZ((j1*16+lrow)*128 + kb*32 + koff));
                mma_hf(s_[2*j0],   qa, kh0[0], kh0[2]);
                mma_hf(s_[2*j1],   qa, kh1[0], kh1[2]);
                mma_hf(s_[2*j0+1], qa, kh0[1], kh0[3]);
                mma_hf(s_[2*j1+1], qa, kh1[1], kh1[3]);
                mma_hf(s_[2*j0],   qb, kh0[0], kh0[2]);
                mma_hf(s_[2*j1],   qb, kh1[0], kh1[2]);
                mma_hf(s_[2*j0+1], qb, kh0[1], kh0[3]);
                mma_hf(s_[2*j1+1], qb, kh1[1], kh1[3]);
                mma_hf(s_[2*j0],   qa, kl0[0], kl0[2]);
                mma_hf(s_[2*j1],   qa, kl1[0], kl1[2]);
                mma_hf(s_[2*j0+1], qa, kl0[1], kl0[3]);
                mma_hf(s_[2*j1+1], qa, kl1[1], kl1[3]);
            }
        }

        const int r0 = wq + lr, r1 = r0 + 8;
        #pragma unroll
        for (int nf = 0; nf < 8; nf++){
            int c0 = nf*8 + lq*2;
            s_[nf][0] += sbias[r0 - c0 + 63] + spen[c0];
            s_[nf][1] += sbias[r0 - c0 + 62] + spen[c0+1];
            s_[nf][2] += sbias[r1 - c0 + 63] + spen[c0];
            s_[nf][3] += sbias[r1 - c0 + 62] + spen[c0+1];
        }

        float mx0 = -1e30f, mx1 = -1e30f;
        #pragma unroll
        for (int nf = 0; nf < 8; nf++){
            mx0 = fmaxf(mx0, fmaxf(s_[nf][0], s_[nf][1]));
            mx1 = fmaxf(mx1, fmaxf(s_[nf][2], s_[nf][3]));
        }
        #pragma unroll
        for (int off = 1; off < 4; off <<= 1){
            mx0 = fmaxf(mx0, __shfl_xor_sync(0xffffffffu, mx0, off));
            mx1 = fmaxf(mx1, __shfl_xor_sync(0xffffffffu, mx1, off));
        }
        float mn0 = fmaxf(m0v, mx0), mn1 = fmaxf(m1v, mx1);
        float al0 = __expf(m0v - mn0), al1 = __expf(m1v - mn1);
        float sum0 = 0.f, sum1 = 0.f;
        #pragma unroll
        for (int nf = 0; nf < 8; nf++){
            s_[nf][0] = __expf(s_[nf][0] - mn0); sum0 += s_[nf][0];
            s_[nf][1] = __expf(s_[nf][1] - mn0); sum0 += s_[nf][1];
            s_[nf][2] = __expf(s_[nf][2] - mn1); sum1 += s_[nf][2];
            s_[nf][3] = __expf(s_[nf][3] - mn1); sum1 += s_[nf][3];
        }
        #pragma unroll
        for (int off = 1; off < 4; off <<= 1){
            sum0 += __shfl_xor_sync(0xffffffffu, sum0, off);
            sum1 += __shfl_xor_sync(0xffffffffu, sum1, off);
        }
        l0 = l0*al0 + sum0; l1 = l1*al1 + sum1;
        m0v = mn0; m1v = mn1;
        #pragma unroll
        for (int nf = 0; nf < 8; nf++){
            o[nf][0] *= al0; o[nf][1] *= al0;
            o[nf][2] *= al1; o[nf][3] *= al1;
        }

        #pragma unroll
        for (int kb = 0; kb < 4; kb++){
            uint32_t ph[4], pl[4];
            {
                __half2 t0l, t1l, t2l, t3l;
                __half2 t0 = split_h2(s_[2*kb][0],   s_[2*kb][1],   &t0l);
                __half2 t1 = split_h2(s_[2*kb][2],   s_[2*kb][3],   &t1l);
                __half2 t2 = split_h2(s_[2*kb+1][0], s_[2*kb+1][1], &t2l);
                __half2 t3 = split_h2(s_[2*kb+1][2], s_[2*kb+1][3], &t3l);
                ph[0] = h2u(t0);  ph[1] = h2u(t1);  ph[2] = h2u(t2);  ph[3] = h2u(t3);
                pl[0] = h2u(t0l); pl[1] = h2u(t1l); pl[2] = h2u(t2l); pl[3] = h2u(t3l);
            }
            #pragma unroll
            for (int jp = 0; jp < 2; jp++){
                int j0 = 2*jp, j1 = 2*jp + 1;
                uint32_t v0[4], v1[4];
                ldm4t(v0, kvb + 16384 + SWZ((kb*16+lrow)*128 + j0*32 + koff));
                ldm4t(v1, kvb + 16384 + SWZ((kb*16+lrow)*128 + j1*32 + koff));
                mma_hf(o[2*j0],   ph, v0[0], v0[1]);
                mma_hf(o[2*j1],   ph, v1[0], v1[1]);
                mma_hf(o[2*j0+1], ph, v0[2], v0[3]);
                mma_hf(o[2*j1+1], ph, v1[2], v1[3]);
                mma_hf(o[2*j0],   pl, v0[0], v0[1]);
                mma_hf(o[2*j1],   pl, v1[0], v1[1]);
                mma_hf(o[2*j0+1], pl, v0[2], v0[3]);
                mma_hf(o[2*j1+1], pl, v1[2], v1[3]);
            }
        }
        __syncthreads();
    }

    const float inv0 = 1.f / l0, inv1 = 1.f / l1;
    const int tq0 = q0 + wq + lr, tq1 = tq0 + 8;
    const size_t b0 = (size_t)g*65536 + (size_t)tq0*64;
    const size_t b1 = (size_t)g*65536 + (size_t)tq1*64;
    #pragma unroll
    for (int nf = 0; nf < 8; nf++){
        int d0 = nf*8 + lq*2;
        *(__half2*)(O16 + b0 + d0) = __halves2half2(
            __float2half_rn(o[nf][0]*inv0), __float2half_rn(o[nf][1]*inv0));
        *(__half2*)(O16 + b1 + d0) = __halves2half2(
            __float2half_rn(o[nf][2]*inv1), __float2half_rn(o[nf][3]*inv1));
    }
}

// ---------------- LayerNorm with residual (register-resident) ----------------
__global__ __launch_bounds__(256)
void ln_kernel(const float4* __restrict__ A, const float4* __restrict__ R,
               const float4* __restrict__ gamma, const float4* __restrict__ beta,
               float4* __restrict__ Out, __half* __restrict__ O16)
{
    __shared__ float red[8];
    const int row = blockIdx.x, tid = threadIdx.x;
    const size_t base = (size_t)row * (DD/4);

    float4 a = A[base + tid], r4 = R[base + tid];
    float x0 = a.x + r4.x, x1 = a.y + r4.y, x2 = a.z + r4.z, x3 = a.w + r4.w;

    float lsum = x0 + x1 + x2 + x3;
    #pragma unroll
    for (int off = 16; off; off >>= 1) lsum += __shfl_xor_sync(0xffffffffu, lsum, off);
    if ((tid & 31) == 0) red[tid >> 5] = lsum;
    __syncthreads();
    float tot = 0.f;
    #pragma unroll
    for (int w = 0; w < 8; w++) tot += red[w];
    float mu = tot * (1.f / DD);
    __syncthreads();

    float d0 = x0-mu, d1 = x1-mu, d2 = x2-mu, d3 = x3-mu;
    float lsq = d0*d0 + d1*d1 + d2*d2 + d3*d3;
    #pragma unroll
    for (int off = 16; off; off >>= 1) lsq += __shfl_xor_sync(0xffffffffu, lsq, off);
    if ((tid & 31) == 0) red[tid >> 5] = lsq;
    __syncthreads();
    float vt = 0.f;
    #pragma unroll
    for (int w = 0; w < 8; w++) vt += red[w];
    float inv = rsqrtf(vt * (1.f / DD) + 1e-5f);

    float4 g = gamma[tid], b = beta[tid];
    float4 v;
    v.x = g.x * d0 * inv + b.x;
    v.y = g.y * d1 * inv + b.y;
    v.z = g.z * d2 * inv + b.z;
    v.w = g.w * d3 * inv + b.w;
    Out[base + tid] = v;
    if (O16){
        __half2* ph = (__half2*)(O16 + (size_t)row*DD + tid*4);
        ph[0] = __halves2half2(__float2half_rn(v.x), __float2half_rn(v.y));
        ph[1] = __halves2half2(__float2half_rn(v.z), __float2half_rn(v.w));
    }
}

// ---------------- launch ----------------------------------------------------
extern "C" void kernel_launch(void* const* d_in, const int* in_sizes, int n_in,
                              void* d_out, int out_size)
{
    const float* x    = (const float*)d_in[0];
    const int*   mask = (const int*)  d_in[1];
    const float* Wq = (const float*)d_in[2];  const float* bq = (const float*)d_in[3];
    const float* Wk = (const float*)d_in[4];  const float* bk = (const float*)d_in[5];
    const float* Wv = (const float*)d_in[6];  const float* bv = (const float*)d_in[7];
    const float* Wo = (const float*)d_in[8];  const float* bo = (const float*)d_in[9];
    const float* rel_bias = (const float*)d_in[10];
    const float* ln1g = (const float*)d_in[11]; const float* ln1b = (const float*)d_in[12];
    const float* W1 = (const float*)d_in[13]; const float* b1 = (const float*)d_in[14];
    const float* W2 = (const float*)d_in[15]; const float* b2 = (const float*)d_in[16];
    const float* ln2g = (const float*)d_in[17]; const float* ln2b = (const float*)d_in[18];
    float* out = (float*)d_out;

    float *tmp, *h, *btab;
    cudaGetSymbolAddress((void**)&tmp,  g_tmp);
    cudaGetSymbolAddress((void**)&h,    g_h);
    cudaGetSymbolAddress((void**)&btab, g_btab);

    __half *xh,*xl, *qh,*ql, *kh,*kl, *v16, *att16, *h16, *f16;
    __half *wqh,*wql,*wkh,*wkl,*wvh,*wvl,*woh,*wol,*w1h,*w1l,*w2h,*w2l;
    cudaGetSymbolAddress((void**)&xh,   g_xh);   cudaGetSymbolAddress((void**)&xl,   g_xl);
    cudaGetSymbolAddress((void**)&qh,   g_qh);   cudaGetSymbolAddress((void**)&ql,   g_ql);
    cudaGetSymbolAddress((void**)&kh,   g_kh);   cudaGetSymbolAddress((void**)&kl,   g_kl);
    cudaGetSymbolAddress((void**)&v16,  g_v16);
    cudaGetSymbolAddress((void**)&att16,g_att16);
    cudaGetSymbolAddress((void**)&h16,  g_h16);
    cudaGetSymbolAddress((void**)&f16,  g_f16);
    cudaGetSymbolAddress((void**)&wqh,  g_wqh);  cudaGetSymbolAddress((void**)&wql,  g_wql);
    cudaGetSymbolAddress((void**)&wkh,  g_wkh);  cudaGetSymbolAddress((void**)&wkl,  g_wkl);
    cudaGetSymbolAddress((void**)&wvh,  g_wvh);  cudaGetSymbolAddress((void**)&wvl,  g_wvl);
    cudaGetSymbolAddress((void**)&woh,  g_woh);  cudaGetSymbolAddress((void**)&wol,  g_wol);
    cudaGetSymbolAddress((void**)&w1h,  g_w1h);  cudaGetSymbolAddress((void**)&w1l,  g_w1l);
    cudaGetSymbolAddress((void**)&w2h,  g_w2h);  cudaGetSymbolAddress((void**)&w2l,  g_w2l);

    cudaFuncSetAttribute(qkv_gemm, cudaFuncAttributeMaxDynamicSharedMemorySize, GSM3);
    cudaFuncSetAttribute(tcgemm2,  cudaFuncAttributeMaxDynamicSharedMemorySize, GSM2);
    cudaFuncSetAttribute(attn_tc,  cudaFuncAttributeMaxDynamicSharedMemorySize, AT_SMEM);

    bias_table_kernel<<<(2*SS - 1 + 255)/256, 256>>>(rel_bias, btab);
    split_kernel<<<(MR*DD/4 + 255)/256, 256>>>((const float4*)x, xh, xl, MR*DD/4);
    {
        TransArgs ta;
        const float* srcs[6] = {Wq, Wk, Wv, Wo, W1, W2};
        __half* dh[6] = {wqh, wkh, wvh, woh, w1h, w2h};
        __half* dl[6] = {wql, wkl, wvl, wol, w1l, w2l};
        int Ks[6] = {DD, DD, DD, DD, DD, FF};
        int Ns[6] = {DD, DD, DD, DD, FF, DD};
        int bases[6] = {0, 1024, 2048, 3072, 4096, 8192};
        for (int i = 0; i < 6; i++){
            ta.src[i] = srcs[i]; ta.dh[i] = dh[i]; ta.dl[i] = dl[i];
            ta.K[i] = Ks[i]; ta.N[i] = Ns[i]; ta.base[i] = bases[i];
        }
        transpose_all<<<12288, dim3(32, 8)>>>(ta);
    }
    {
        QKVArgs qa;
        qa.Bh[0] = wqh; qa.Bl[0] = wql; qa.bias[0] = bq; qa.Oh[0] = qh;  qa.Ol[0] = ql;
        qa.Bh[1] = wkh; qa.Bl[1] = wkl; qa.bias[1] = bk; qa.Oh[1] = kh;  qa.Ol[1] = kl;
        qa.Bh[2] = wvh; qa.Bl[2] = wvl; qa.bias[2] = bv; qa.Oh[2] = v16; qa.Ol[2] = nullptr;
        qkv_gemm<<<dim3(48, MR/128), 128, GSM3>>>(xh, xl, qa, MR, DD);
    }
    attn_tc<<<dim3(SS/128, NG), 256, AT_SMEM>>>(qh, ql, kh, kl, v16,
                                                mask, btab, att16);
    tcgemm2<<<dim3(DD/128, MR/128), 128, GSM2>>>(att16, woh, wol, bo, tmp,
                                                 nullptr, MR, DD, DD, 0);
    ln_kernel<<<MR, 256>>>((const float4*)tmp, (const float4*)x,
                           (const float4*)ln1g, (const float4*)ln1b,
                           (float4*)h, h16);
    tcgemm2<<<dim3(FF/128, MR/128), 128, GSM2>>>(h16, w1h, w1l, b1, nullptr,
                                                 f16, MR, FF, DD, 1);
    tcgemm2<<<dim3(DD/128, MR/128), 128, GSM2>>>(f16, w2h, w2l, b2, tmp,
                                                 nullptr, MR, DD, FF, 0);
    ln_kernel<<<MR, 256>>>((const float4*)tmp, (const float4*)h,
                           (const float4*)ln2g, (const float4*)ln2b,
                           (float4*)out, nullptr);
}